// round 1
// baseline (speedup 1.0000x reference)
#include <cuda_runtime.h>
#include <math.h>

// Problem dims (fixed)
#define BB   64
#define CC   256
#define C8   32
#define HH   32
#define WW   32
#define NN   1024            // H*W
#define BCN  16777216        // B*C*N
#define BQN  2097152         // B*C8*N
#define BNN  67108864        // B*N*N

// ---------------- scratch (static device arrays; no runtime alloc) -------------
__device__ float g_t1[BCN];     // dw1 output
__device__ float g_t2[BCN];     // pw1+BN+ReLU output
__device__ float g_t3[BCN];     // dw2 output
__device__ float g_xa[BCN];     // pw2+BN + x  (attention input)
__device__ float g_q[BQN];
__device__ float g_k[BQN];
__device__ float g_v[BCN];
__device__ float g_S[BNN];      // attention logits -> softmax in place
__device__ float g_bn[4 * CC];  // scale1, shift1, scale2, shift2

// ---------------- BN affine precompute ----------------------------------------
__global__ void bnprep_kernel(const float* __restrict__ g1, const float* __restrict__ b1,
                              const float* __restrict__ m1, const float* __restrict__ v1,
                              const float* __restrict__ g2, const float* __restrict__ b2,
                              const float* __restrict__ m2, const float* __restrict__ v2,
                              float* __restrict__ bn) {
    int c = threadIdx.x;
    float s1 = g1[c] * rsqrtf(v1[c] + 1e-5f);
    float s2 = g2[c] * rsqrtf(v2[c] + 1e-5f);
    bn[c]          = s1;
    bn[CC + c]     = b1[c] - m1[c] * s1;
    bn[2 * CC + c] = s2;
    bn[3 * CC + c] = b2[c] - m2[c] * s2;
}

// ---------------- depthwise 3x3, SAME, stride 1 --------------------------------
__global__ __launch_bounds__(256) void dwconv_kernel(const float* __restrict__ in,
                                                     const float* __restrict__ w9,
                                                     float* __restrict__ out) {
    __shared__ float s[34 * 34];
    int p = blockIdx.x;           // plane index = b*C + c
    int c = p & (CC - 1);
    const float* ip = in + (long)p * NN;
    float w[9];
#pragma unroll
    for (int j = 0; j < 9; j++) w[j] = w9[c * 9 + j];

    for (int idx = threadIdx.x; idx < 34 * 34; idx += 256) {
        int y = idx / 34 - 1, x = idx % 34 - 1;
        s[idx] = (y >= 0 && y < HH && x >= 0 && x < WW) ? ip[y * WW + x] : 0.0f;
    }
    __syncthreads();

#pragma unroll
    for (int r = 0; r < 4; r++) {
        int pix = threadIdx.x + r * 256;
        int oy = pix >> 5, ox = pix & 31;
        const float* base = s + oy * 34 + ox;  // base[dy*34+dx] = in(oy+dy-1, ox+dx-1)
        float acc = 0.0f;
#pragma unroll
        for (int dy = 0; dy < 3; dy++)
#pragma unroll
            for (int dx = 0; dx < 3; dx++)
                acc = fmaf(base[dy * 34 + dx], w[dy * 3 + dx], acc);
        out[(long)p * NN + pix] = acc;
    }
}

// ---------------- generic tiled fp32 GEMM --------------------------------------
// C[b][m][n] = sum_k A[b][m][k or k][m] * B[b][k][n or n][k]    + epilogue
// ATR=true : A stored [M,K], k contiguous (weights / v / P)
// ATR=false: A stored [K,M], m contiguous (q^T case)
// BTR=true : B stored [N,K], k contiguous (P in the PV GEMM)
// BTR=false: B stored [K,N], n contiguous (activations)
// EPI: 0 = relu(acc*scale[m]+shift[m])
//      1 = acc*scale[m]+shift[m] + res
//      2 = acc + scale[m]   (bias)
//      3 = acc
//      4 = relu(gamma[0]*acc + res)
template <int TM, int TN, int TK, bool ATR, bool BTR, int EPI>
__global__ __launch_bounds__(256) void gemm_kernel(
    const float* __restrict__ A, const float* __restrict__ B, float* __restrict__ Cm,
    int K, int lda, int ldb, int ldc,
    long sA, long sB, long sC,
    const float* __restrict__ scale, const float* __restrict__ shift,
    const float* __restrict__ res, long sRes,
    const float* __restrict__ gammaPtr) {
    constexpr int RM = TM / 16;
    constexpr int RN = TN / 16;
    __shared__ float As[TK][TM + 1];
    __shared__ float Bs[TK][TN + 1];

    int bz = blockIdx.z;
    const float* Ab = A + (long)bz * sA;
    const float* Bb = B + (long)bz * sB;
    int m0 = blockIdx.y * TM;
    int n0 = blockIdx.x * TN;
    int tid = threadIdx.x;
    int ty = tid >> 4, tx = tid & 15;

    float acc[RM][RN];
#pragma unroll
    for (int i = 0; i < RM; i++)
#pragma unroll
        for (int j = 0; j < RN; j++) acc[i][j] = 0.0f;

    for (int k0 = 0; k0 < K; k0 += TK) {
        if (ATR) {
            int k = tid & (TK - 1);
            int mrow = tid / TK;
#pragma unroll
            for (int r = 0; r < (TM * TK) / 256; r++) {
                int m = mrow + r * (256 / TK);
                As[k][m] = Ab[(long)(m0 + m) * lda + (k0 + k)];
            }
        } else {
#pragma unroll
            for (int r = 0; r < (TM * TK) / 256; r++) {
                int idx = tid + r * 256;
                int k = idx / TM, m = idx % TM;
                As[k][m] = Ab[(long)(k0 + k) * lda + (m0 + m)];
            }
        }
        if (BTR) {
            int k = tid & (TK - 1);
            int nrow = tid / TK;
#pragma unroll
            for (int r = 0; r < (TN * TK) / 256; r++) {
                int n = nrow + r * (256 / TK);
                Bs[k][n] = Bb[(long)(n0 + n) * ldb + (k0 + k)];
            }
        } else {
#pragma unroll
            for (int r = 0; r < (TN * TK) / 256; r++) {
                int idx = tid + r * 256;
                int k = idx / TN, n = idx % TN;
                Bs[k][n] = Bb[(long)(k0 + k) * ldb + (n0 + n)];
            }
        }
        __syncthreads();

#pragma unroll
        for (int k = 0; k < TK; k++) {
            float a[RM], bv[RN];
#pragma unroll
            for (int i = 0; i < RM; i++) a[i] = As[k][ty + 16 * i];
#pragma unroll
            for (int j = 0; j < RN; j++) bv[j] = Bs[k][tx + 16 * j];
#pragma unroll
            for (int i = 0; i < RM; i++)
#pragma unroll
                for (int j = 0; j < RN; j++) acc[i][j] = fmaf(a[i], bv[j], acc[i][j]);
        }
        __syncthreads();
    }

    float gm = 0.0f;
    if (EPI == 4) gm = gammaPtr[0];

#pragma unroll
    for (int i = 0; i < RM; i++) {
        int m = m0 + ty + 16 * i;
#pragma unroll
        for (int j = 0; j < RN; j++) {
            int n = n0 + tx + 16 * j;
            float val = acc[i][j];
            if (EPI == 0) {
                val = fmaxf(fmaf(val, scale[m], shift[m]), 0.0f);
            } else if (EPI == 1) {
                val = fmaf(val, scale[m], shift[m]) + res[(long)bz * sRes + (long)m * ldc + n];
            } else if (EPI == 2) {
                val = val + scale[m];
            } else if (EPI == 4) {
                val = fmaxf(fmaf(gm, val, res[(long)bz * sRes + (long)m * ldc + n]), 0.0f);
            }
            Cm[(long)bz * sC + (long)m * ldc + n] = val;
        }
    }
}

// ---------------- row softmax over 1024 elements --------------------------------
__global__ __launch_bounds__(256) void softmax_kernel(float* __restrict__ S) {
    __shared__ float red[256];
    float* p = S + (long)blockIdx.x * NN;
    int t = threadIdx.x;
    float v[4];
#pragma unroll
    for (int i = 0; i < 4; i++) v[i] = p[t + i * 256];
    float m = fmaxf(fmaxf(v[0], v[1]), fmaxf(v[2], v[3]));
    red[t] = m;
    __syncthreads();
    for (int s2 = 128; s2 > 0; s2 >>= 1) {
        if (t < s2) red[t] = fmaxf(red[t], red[t + s2]);
        __syncthreads();
    }
    m = red[0];
    __syncthreads();
    float sum = 0.0f;
#pragma unroll
    for (int i = 0; i < 4; i++) {
        v[i] = __expf(v[i] - m);
        sum += v[i];
    }
    red[t] = sum;
    __syncthreads();
    for (int s2 = 128; s2 > 0; s2 >>= 1) {
        if (t < s2) red[t] += red[t + s2];
        __syncthreads();
    }
    float inv = 1.0f / red[0];
#pragma unroll
    for (int i = 0; i < 4; i++) p[t + i * 256] = v[i] * inv;
}

// ---------------- launch ---------------------------------------------------------
extern "C" void kernel_launch(void* const* d_in, const int* in_sizes, int n_in,
                              void* d_out, int out_size) {
    const float* x     = (const float*)d_in[0];
    const float* dw1   = (const float*)d_in[1];
    const float* pw1   = (const float*)d_in[2];
    const float* bn1_g = (const float*)d_in[3];
    const float* bn1_b = (const float*)d_in[4];
    const float* bn1_m = (const float*)d_in[5];
    const float* bn1_v = (const float*)d_in[6];
    const float* dw2   = (const float*)d_in[7];
    const float* pw2   = (const float*)d_in[8];
    const float* bn2_g = (const float*)d_in[9];
    const float* bn2_b = (const float*)d_in[10];
    const float* bn2_m = (const float*)d_in[11];
    const float* bn2_v = (const float*)d_in[12];
    const float* wq    = (const float*)d_in[13];
    const float* bq    = (const float*)d_in[14];
    const float* wk    = (const float*)d_in[15];
    const float* bk    = (const float*)d_in[16];
    const float* wv    = (const float*)d_in[17];
    const float* bv    = (const float*)d_in[18];
    const float* gamma = (const float*)d_in[19];
    float* out = (float*)d_out;

    float *t1, *t2, *t3, *xa, *q, *k, *v, *S, *bn;
    cudaGetSymbolAddress((void**)&t1, g_t1);
    cudaGetSymbolAddress((void**)&t2, g_t2);
    cudaGetSymbolAddress((void**)&t3, g_t3);
    cudaGetSymbolAddress((void**)&xa, g_xa);
    cudaGetSymbolAddress((void**)&q,  g_q);
    cudaGetSymbolAddress((void**)&k,  g_k);
    cudaGetSymbolAddress((void**)&v,  g_v);
    cudaGetSymbolAddress((void**)&S,  g_S);
    cudaGetSymbolAddress((void**)&bn, g_bn);
    const float* scale1 = bn;
    const float* shift1 = bn + CC;
    const float* scale2 = bn + 2 * CC;
    const float* shift2 = bn + 3 * CC;

    const long sBCN = (long)CC * NN;   // 262144
    const long sBQN = (long)C8 * NN;   // 32768
    const long sBNN = (long)NN * NN;   // 1048576

    // 0) BN affine precompute
    bnprep_kernel<<<1, CC>>>(bn1_g, bn1_b, bn1_m, bn1_v, bn2_g, bn2_b, bn2_m, bn2_v, bn);

    // 1) depthwise 1
    dwconv_kernel<<<BB * CC, 256>>>(x, dw1, t1);

    // 2) pointwise 1 + BN + ReLU : t2 = relu(scale1 * (pw1 @ t1) + shift1)
    gemm_kernel<64, 64, 16, true, false, 0><<<dim3(NN / 64, CC / 64, BB), 256>>>(
        pw1, t1, t2, CC, CC, NN, NN, 0, sBCN, sBCN, scale1, shift1, nullptr, 0, nullptr);

    // 3) depthwise 2
    dwconv_kernel<<<BB * CC, 256>>>(t2, dw2, t3);

    // 4) pointwise 2 + BN + residual x : xa = scale2 * (pw2 @ t3) + shift2 + x
    gemm_kernel<64, 64, 16, true, false, 1><<<dim3(NN / 64, CC / 64, BB), 256>>>(
        pw2, t3, xa, CC, CC, NN, NN, 0, sBCN, sBCN, scale2, shift2, x, sBCN, nullptr);

    // 5) q = wq @ xa + bq   (M=32)
    gemm_kernel<32, 64, 16, true, false, 2><<<dim3(NN / 64, 1, BB), 256>>>(
        wq, xa, q, CC, CC, NN, NN, 0, sBCN, sBQN, bq, nullptr, nullptr, 0, nullptr);

    // 6) k = wk @ xa + bk
    gemm_kernel<32, 64, 16, true, false, 2><<<dim3(NN / 64, 1, BB), 256>>>(
        wk, xa, k, CC, CC, NN, NN, 0, sBCN, sBQN, bk, nullptr, nullptr, 0, nullptr);

    // 7) v = wv @ xa + bv
    gemm_kernel<64, 64, 16, true, false, 2><<<dim3(NN / 64, CC / 64, BB), 256>>>(
        wv, xa, v, CC, CC, NN, NN, 0, sBCN, sBCN, bv, nullptr, nullptr, 0, nullptr);

    // 8) S[m][n] = sum_d q[d][m] k[d][n]   (A = q^T stored [K,M] m-contig)
    gemm_kernel<64, 64, 16, false, false, 3><<<dim3(NN / 64, NN / 64, BB), 256>>>(
        q, k, S, C8, NN, NN, NN, sBQN, sBQN, sBNN, nullptr, nullptr, nullptr, 0, nullptr);

    // 9) softmax over n (rows of S)
    softmax_kernel<<<BB * NN, 256>>>(S);

    // 10) O[c][m] = sum_n v[c][n] P[m][n] ; out = relu(gamma*O + xa)
    gemm_kernel<64, 64, 16, true, true, 4><<<dim3(NN / 64, CC / 64, BB), 256>>>(
        v, S, out, NN, NN, NN, NN, sBCN, sBNN, sBCN, nullptr, nullptr, xa, sBCN, gamma);

    (void)in_sizes; (void)n_in; (void)out_size;
}

// round 4
// speedup vs baseline: 2.2350x; 2.2350x over previous
#include <cuda_runtime.h>
#include <math.h>

// Problem dims (fixed)
#define BB   64
#define CC   256
#define C8   32
#define HH   32
#define WW   32
#define NN   1024            // H*W
#define BCN  16777216        // B*C*N
#define BQN  2097152         // B*C8*N
#define BNN  67108864        // B*N*N

// ---------------- scratch (static device arrays; no runtime alloc) -------------
// NOTE: __align__(256) is load-bearing: these are accessed with float4/float2
// vector ops; default __device__ array alignment is only 4 bytes and a
// misaligned LDG.128 is a hardware trap (err715).
__device__ __align__(256) float g_t1[BCN];     // dw1 output
__device__ __align__(256) float g_t2[BCN];     // pw1+BN+ReLU output
__device__ __align__(256) float g_t3[BCN];     // dw2 output
__device__ __align__(256) float g_xa[BCN];     // pw2+BN + x  (attention input)
__device__ __align__(256) float g_q[BQN];
__device__ __align__(256) float g_k[BQN];
__device__ __align__(256) float g_v[BCN];
__device__ __align__(256) float g_S[BNN];      // attention logits -> softmax in place
__device__ __align__(256) float g_bn[4 * CC];  // scale1, shift1, scale2, shift2

// ---------------- BN affine precompute ----------------------------------------
__global__ void bnprep_kernel(const float* __restrict__ g1, const float* __restrict__ b1,
                              const float* __restrict__ m1, const float* __restrict__ v1,
                              const float* __restrict__ g2, const float* __restrict__ b2,
                              const float* __restrict__ m2, const float* __restrict__ v2,
                              float* __restrict__ bn) {
    int c = threadIdx.x;
    float s1 = g1[c] * rsqrtf(v1[c] + 1e-5f);
    float s2 = g2[c] * rsqrtf(v2[c] + 1e-5f);
    bn[c]          = s1;
    bn[CC + c]     = b1[c] - m1[c] * s1;
    bn[2 * CC + c] = s2;
    bn[3 * CC + c] = b2[c] - m2[c] * s2;
}

// ---------------- depthwise 3x3, SAME, stride 1 --------------------------------
__global__ __launch_bounds__(256) void dwconv_kernel(const float* __restrict__ in,
                                                     const float* __restrict__ w9,
                                                     float* __restrict__ out) {
    __shared__ float s[34 * 34];
    int p = blockIdx.x;           // plane index = b*C + c
    int c = p & (CC - 1);
    const float* ip = in + (long)p * NN;
    float w[9];
#pragma unroll
    for (int j = 0; j < 9; j++) w[j] = w9[c * 9 + j];

    for (int idx = threadIdx.x; idx < 34 * 34; idx += 256) {
        int y = idx / 34 - 1, x = idx % 34 - 1;
        s[idx] = (y >= 0 && y < HH && x >= 0 && x < WW) ? ip[y * WW + x] : 0.0f;
    }
    __syncthreads();

#pragma unroll
    for (int r = 0; r < 4; r++) {
        int pix = threadIdx.x + r * 256;
        int oy = pix >> 5, ox = pix & 31;
        const float* base = s + oy * 34 + ox;
        float acc = 0.0f;
#pragma unroll
        for (int dy = 0; dy < 3; dy++)
#pragma unroll
            for (int dx = 0; dx < 3; dx++)
                acc = fmaf(base[dy * 34 + dx], w[dy * 3 + dx], acc);
        out[(long)p * NN + pix] = acc;
    }
}

// ---------------- fp32 tiled GEMM (kept for precision-sensitive small GEMMs) ----
template <int TM, int TN, int TK, bool ATR, bool BTR, int EPI>
__global__ __launch_bounds__(256) void gemm_kernel(
    const float* __restrict__ A, const float* __restrict__ B, float* __restrict__ Cm,
    int K, int lda, int ldb, int ldc,
    long sA, long sB, long sC,
    const float* __restrict__ scale, const float* __restrict__ shift,
    const float* __restrict__ res, long sRes,
    const float* __restrict__ gammaPtr) {
    constexpr int RM = TM / 16;
    constexpr int RN = TN / 16;
    __shared__ float As[TK][TM + 1];
    __shared__ float Bs[TK][TN + 1];

    int bz = blockIdx.z;
    const float* Ab = A + (long)bz * sA;
    const float* Bb = B + (long)bz * sB;
    int m0 = blockIdx.y * TM;
    int n0 = blockIdx.x * TN;
    int tid = threadIdx.x;
    int ty = tid >> 4, tx = tid & 15;

    float acc[RM][RN];
#pragma unroll
    for (int i = 0; i < RM; i++)
#pragma unroll
        for (int j = 0; j < RN; j++) acc[i][j] = 0.0f;

    for (int k0 = 0; k0 < K; k0 += TK) {
        if (ATR) {
            int k = tid & (TK - 1);
            int mrow = tid / TK;
#pragma unroll
            for (int r = 0; r < (TM * TK) / 256; r++) {
                int m = mrow + r * (256 / TK);
                As[k][m] = Ab[(long)(m0 + m) * lda + (k0 + k)];
            }
        } else {
#pragma unroll
            for (int r = 0; r < (TM * TK) / 256; r++) {
                int idx = tid + r * 256;
                int k = idx / TM, m = idx % TM;
                As[k][m] = Ab[(long)(k0 + k) * lda + (m0 + m)];
            }
        }
        if (BTR) {
            int k = tid & (TK - 1);
            int nrow = tid / TK;
#pragma unroll
            for (int r = 0; r < (TN * TK) / 256; r++) {
                int n = nrow + r * (256 / TK);
                Bs[k][n] = Bb[(long)(n0 + n) * ldb + (k0 + k)];
            }
        } else {
#pragma unroll
            for (int r = 0; r < (TN * TK) / 256; r++) {
                int idx = tid + r * 256;
                int k = idx / TN, n = idx % TN;
                Bs[k][n] = Bb[(long)(k0 + k) * ldb + (n0 + n)];
            }
        }
        __syncthreads();

#pragma unroll
        for (int k = 0; k < TK; k++) {
            float a[RM], bv[RN];
#pragma unroll
            for (int i = 0; i < RM; i++) a[i] = As[k][ty + 16 * i];
#pragma unroll
            for (int j = 0; j < RN; j++) bv[j] = Bs[k][tx + 16 * j];
#pragma unroll
            for (int i = 0; i < RM; i++)
#pragma unroll
                for (int j = 0; j < RN; j++) acc[i][j] = fmaf(a[i], bv[j], acc[i][j]);
        }
        __syncthreads();
    }

    float gm = 0.0f;
    if (EPI == 4) gm = gammaPtr[0];

#pragma unroll
    for (int i = 0; i < RM; i++) {
        int m = m0 + ty + 16 * i;
#pragma unroll
        for (int j = 0; j < RN; j++) {
            int n = n0 + tx + 16 * j;
            float val = acc[i][j];
            if (EPI == 0) {
                val = fmaxf(fmaf(val, scale[m], shift[m]), 0.0f);
            } else if (EPI == 1) {
                val = fmaf(val, scale[m], shift[m]) + res[(long)bz * sRes + (long)m * ldc + n];
            } else if (EPI == 2) {
                val = val + scale[m];
            } else if (EPI == 4) {
                val = fmaxf(fmaf(gm, val, res[(long)bz * sRes + (long)m * ldc + n]), 0.0f);
            }
            Cm[(long)bz * sC + (long)m * ldc + n] = val;
        }
    }
}

// ---------------- TF32 tensor-core GEMM ----------------------------------------
// C[b][m][n] = sum_k A[b][m][k] * B[...]   (A always [M,K] k-contiguous)
// BTR=false: B stored [K,N] n-contiguous.  BTR=true: B stored [N,K] k-contiguous.
// EPI: 0 relu(acc*scale[m]+shift[m]); 1 acc*scale[m]+shift[m]+res; 2 acc+scale[m];
//      4 relu(gamma*acc + res)
__device__ __forceinline__ unsigned f2tf(float x) {
    unsigned r;
    asm("cvt.rna.tf32.f32 %0, %1;" : "=r"(r) : "f"(x));
    return r;
}

template <bool BTR, int EPI>
__global__ __launch_bounds__(256) void gemm_tf32(
    const float* __restrict__ A, const float* __restrict__ B, float* __restrict__ Cm,
    int K, int lda, int ldb, int ldc,
    long sA, long sB, long sC,
    const float* __restrict__ scale, const float* __restrict__ shift,
    const float* __restrict__ res, long sRes,
    const float* __restrict__ gammaPtr) {
    constexpr int BM = 128, BN = 128, BK = 16;
    __shared__ unsigned As[2][BK][BM + 4];
    __shared__ unsigned Bs[2][BK][BN + 4];

    int tid = threadIdx.x;
    int bz = blockIdx.z;
    const float* Ab = A + (long)bz * sA;
    const float* Bb = B + (long)bz * sB;
    int m0 = blockIdx.y * BM, n0 = blockIdx.x * BN;

    // staging index precompute
    int arow = tid >> 2;            // 0..63
    int akq = (tid & 3) * 4;        // k quad base
    int brow, bcq;
    if (BTR) { brow = tid >> 2; bcq = (tid & 3) * 4; }     // per n-row, quad along k
    else     { brow = tid >> 5; bcq = (tid & 31) * 4; }    // per k-row, quad along n

    float4 pa[2], pb[2];

    auto ldgAB = [&](int k0) {
#pragma unroll
        for (int r = 0; r < 2; r++)
            pa[r] = *(const float4*)(Ab + (long)(m0 + arow + r * 64) * lda + k0 + akq);
        if (BTR) {
#pragma unroll
            for (int r = 0; r < 2; r++)
                pb[r] = *(const float4*)(Bb + (long)(n0 + brow + r * 64) * ldb + k0 + bcq);
        } else {
#pragma unroll
            for (int r = 0; r < 2; r++)
                pb[r] = *(const float4*)(Bb + (long)(k0 + brow + r * 8) * ldb + n0 + bcq);
        }
    };
    auto stsAB = [&](int buf) {
#pragma unroll
        for (int r = 0; r < 2; r++) {
            int m = arow + r * 64;
            As[buf][akq + 0][m] = f2tf(pa[r].x);
            As[buf][akq + 1][m] = f2tf(pa[r].y);
            As[buf][akq + 2][m] = f2tf(pa[r].z);
            As[buf][akq + 3][m] = f2tf(pa[r].w);
        }
        if (BTR) {
#pragma unroll
            for (int r = 0; r < 2; r++) {
                int n = brow + r * 64;
                Bs[buf][bcq + 0][n] = f2tf(pb[r].x);
                Bs[buf][bcq + 1][n] = f2tf(pb[r].y);
                Bs[buf][bcq + 2][n] = f2tf(pb[r].z);
                Bs[buf][bcq + 3][n] = f2tf(pb[r].w);
            }
        } else {
#pragma unroll
            for (int r = 0; r < 2; r++) {
                int k = brow + r * 8;
                Bs[buf][k][bcq + 0] = f2tf(pb[r].x);
                Bs[buf][k][bcq + 1] = f2tf(pb[r].y);
                Bs[buf][k][bcq + 2] = f2tf(pb[r].z);
                Bs[buf][k][bcq + 3] = f2tf(pb[r].w);
            }
        }
    };

    int lane = tid & 31, warp = tid >> 5;
    int wm = (warp >> 2) * 64;      // 0 or 64
    int wn = (warp & 3) * 32;       // 0,32,64,96
    int gid = lane >> 2, tig = lane & 3;

    float acc[4][4][4];
#pragma unroll
    for (int i = 0; i < 4; i++)
#pragma unroll
        for (int j = 0; j < 4; j++)
#pragma unroll
            for (int e = 0; e < 4; e++) acc[i][j][e] = 0.0f;

    ldgAB(0);
    stsAB(0);
    __syncthreads();

    int nk = K / BK;
    for (int t = 0; t < nk; t++) {
        int cur = t & 1;
        if (t + 1 < nk) ldgAB((t + 1) * BK);

#pragma unroll
        for (int kk = 0; kk < 2; kk++) {
            int kb = kk * 8;
            unsigned af[4][4], bf[4][2];
#pragma unroll
            for (int mi = 0; mi < 4; mi++) {
                int m = wm + 16 * mi;
                af[mi][0] = As[cur][kb + tig][m + gid];
                af[mi][1] = As[cur][kb + tig][m + 8 + gid];
                af[mi][2] = As[cur][kb + 4 + tig][m + gid];
                af[mi][3] = As[cur][kb + 4 + tig][m + 8 + gid];
            }
#pragma unroll
            for (int nj = 0; nj < 4; nj++) {
                int n = wn + 8 * nj;
                bf[nj][0] = Bs[cur][kb + tig][n + gid];
                bf[nj][1] = Bs[cur][kb + 4 + tig][n + gid];
            }
#pragma unroll
            for (int mi = 0; mi < 4; mi++)
#pragma unroll
                for (int nj = 0; nj < 4; nj++) {
                    asm volatile(
                        "mma.sync.aligned.m16n8k8.row.col.f32.tf32.tf32.f32 "
                        "{%0,%1,%2,%3},{%4,%5,%6,%7},{%8,%9},{%0,%1,%2,%3};\n"
                        : "+f"(acc[mi][nj][0]), "+f"(acc[mi][nj][1]),
                          "+f"(acc[mi][nj][2]), "+f"(acc[mi][nj][3])
                        : "r"(af[mi][0]), "r"(af[mi][1]), "r"(af[mi][2]), "r"(af[mi][3]),
                          "r"(bf[nj][0]), "r"(bf[nj][1]));
                }
        }
        if (t + 1 < nk) {
            // writes go to buffer cur^1, whose last readers were fenced by the
            // previous iteration's post-store barrier -> single barrier needed.
            stsAB(cur ^ 1);
            __syncthreads();
        }
    }

    float gm = (EPI == 4) ? gammaPtr[0] : 0.0f;
    const float* resb = res ? res + (long)bz * sRes : nullptr;
    float* Cb = Cm + (long)bz * sC;

#pragma unroll
    for (int mi = 0; mi < 4; mi++) {
#pragma unroll
        for (int e2 = 0; e2 < 2; e2++) {        // c01 (row gid) / c23 (row gid+8)
            int m = m0 + wm + 16 * mi + gid + 8 * e2;
            float sc = 0.0f, sh = 0.0f;
            if (EPI == 0 || EPI == 1) { sc = scale[m]; sh = shift[m]; }
            else if (EPI == 2) { sc = scale[m]; }
#pragma unroll
            for (int nj = 0; nj < 4; nj++) {
                int n = n0 + wn + 8 * nj + 2 * tig;
                float v0 = acc[mi][nj][2 * e2 + 0];
                float v1 = acc[mi][nj][2 * e2 + 1];
                if (EPI == 0) {
                    v0 = fmaxf(fmaf(v0, sc, sh), 0.0f);
                    v1 = fmaxf(fmaf(v1, sc, sh), 0.0f);
                } else if (EPI == 1) {
                    float2 r2 = *(const float2*)(resb + (long)m * ldc + n);
                    v0 = fmaf(v0, sc, sh) + r2.x;
                    v1 = fmaf(v1, sc, sh) + r2.y;
                } else if (EPI == 2) {
                    v0 += sc; v1 += sc;
                } else if (EPI == 4) {
                    float2 r2 = *(const float2*)(resb + (long)m * ldc + n);
                    v0 = fmaxf(fmaf(gm, v0, r2.x), 0.0f);
                    v1 = fmaxf(fmaf(gm, v1, r2.y), 0.0f);
                }
                float2 o2 = make_float2(v0, v1);
                *(float2*)(Cb + (long)m * ldc + n) = o2;
            }
        }
    }
}

// ---------------- row softmax over 1024 elements --------------------------------
__global__ __launch_bounds__(256) void softmax_kernel(float* __restrict__ S) {
    __shared__ float red[256];
    float* p = S + (long)blockIdx.x * NN;
    int t = threadIdx.x;
    float v[4];
#pragma unroll
    for (int i = 0; i < 4; i++) v[i] = p[t + i * 256];
    float m = fmaxf(fmaxf(v[0], v[1]), fmaxf(v[2], v[3]));
    red[t] = m;
    __syncthreads();
    for (int s2 = 128; s2 > 0; s2 >>= 1) {
        if (t < s2) red[t] = fmaxf(red[t], red[t + s2]);
        __syncthreads();
    }
    m = red[0];
    __syncthreads();
    float sum = 0.0f;
#pragma unroll
    for (int i = 0; i < 4; i++) {
        v[i] = __expf(v[i] - m);
        sum += v[i];
    }
    red[t] = sum;
    __syncthreads();
    for (int s2 = 128; s2 > 0; s2 >>= 1) {
        if (t < s2) red[t] += red[t + s2];
        __syncthreads();
    }
    float inv = 1.0f / red[0];
#pragma unroll
    for (int i = 0; i < 4; i++) p[t + i * 256] = v[i] * inv;
}

// ---------------- launch ---------------------------------------------------------
extern "C" void kernel_launch(void* const* d_in, const int* in_sizes, int n_in,
                              void* d_out, int out_size) {
    const float* x     = (const float*)d_in[0];
    const float* dw1   = (const float*)d_in[1];
    const float* pw1   = (const float*)d_in[2];
    const float* bn1_g = (const float*)d_in[3];
    const float* bn1_b = (const float*)d_in[4];
    const float* bn1_m = (const float*)d_in[5];
    const float* bn1_v = (const float*)d_in[6];
    const float* dw2   = (const float*)d_in[7];
    const float* pw2   = (const float*)d_in[8];
    const float* bn2_g = (const float*)d_in[9];
    const float* bn2_b = (const float*)d_in[10];
    const float* bn2_m = (const float*)d_in[11];
    const float* bn2_v = (const float*)d_in[12];
    const float* wq    = (const float*)d_in[13];
    const float* bq    = (const float*)d_in[14];
    const float* wk    = (const float*)d_in[15];
    const float* bk    = (const float*)d_in[16];
    const float* wv    = (const float*)d_in[17];
    const float* bv    = (const float*)d_in[18];
    const float* gamma = (const float*)d_in[19];
    float* out = (float*)d_out;

    float *t1, *t2, *t3, *xa, *q, *k, *v, *S, *bn;
    cudaGetSymbolAddress((void**)&t1, g_t1);
    cudaGetSymbolAddress((void**)&t2, g_t2);
    cudaGetSymbolAddress((void**)&t3, g_t3);
    cudaGetSymbolAddress((void**)&xa, g_xa);
    cudaGetSymbolAddress((void**)&q,  g_q);
    cudaGetSymbolAddress((void**)&k,  g_k);
    cudaGetSymbolAddress((void**)&v,  g_v);
    cudaGetSymbolAddress((void**)&S,  g_S);
    cudaGetSymbolAddress((void**)&bn, g_bn);
    const float* scale1 = bn;
    const float* shift1 = bn + CC;
    const float* scale2 = bn + 2 * CC;
    const float* shift2 = bn + 3 * CC;

    const long sBCN = (long)CC * NN;   // 262144
    const long sBQN = (long)C8 * NN;   // 32768
    const long sBNN = (long)NN * NN;   // 1048576

    // 0) BN affine precompute
    bnprep_kernel<<<1, CC>>>(bn1_g, bn1_b, bn1_m, bn1_v, bn2_g, bn2_b, bn2_m, bn2_v, bn);

    // 1) depthwise 1
    dwconv_kernel<<<BB * CC, 256>>>(x, dw1, t1);

    // 2) pointwise 1 + BN + ReLU (TF32 TC)
    gemm_tf32<false, 0><<<dim3(NN / 128, CC / 128, BB), 256>>>(
        pw1, t1, t2, CC, CC, NN, NN, 0, sBCN, sBCN, scale1, shift1, nullptr, 0, nullptr);

    // 3) depthwise 2
    dwconv_kernel<<<BB * CC, 256>>>(t2, dw2, t3);

    // 4) pointwise 2 + BN + residual x (TF32 TC)
    gemm_tf32<false, 1><<<dim3(NN / 128, CC / 128, BB), 256>>>(
        pw2, t3, xa, CC, CC, NN, NN, 0, sBCN, sBCN, scale2, shift2, x, sBCN, nullptr);

    // 5) q = wq @ xa + bq  (fp32, precision-sensitive for softmax)
    gemm_kernel<32, 64, 16, true, false, 2><<<dim3(NN / 64, 1, BB), 256>>>(
        wq, xa, q, CC, CC, NN, NN, 0, sBCN, sBQN, bq, nullptr, nullptr, 0, nullptr);

    // 6) k = wk @ xa + bk  (fp32)
    gemm_kernel<32, 64, 16, true, false, 2><<<dim3(NN / 64, 1, BB), 256>>>(
        wk, xa, k, CC, CC, NN, NN, 0, sBCN, sBQN, bk, nullptr, nullptr, 0, nullptr);

    // 7) v = wv @ xa + bv (TF32 TC)
    gemm_tf32<false, 2><<<dim3(NN / 128, CC / 128, BB), 256>>>(
        wv, xa, v, CC, CC, NN, NN, 0, sBCN, sBCN, bv, nullptr, nullptr, 0, nullptr);

    // 8) S[m][n] = sum_d q[d][m] k[d][n]  (fp32, feeds softmax)
    gemm_kernel<64, 64, 16, false, false, 3><<<dim3(NN / 64, NN / 64, BB), 256>>>(
        q, k, S, C8, NN, NN, NN, sBQN, sBQN, sBNN, nullptr, nullptr, nullptr, 0, nullptr);

    // 9) softmax over n (rows of S)
    softmax_kernel<<<BB * NN, 256>>>(S);

    // 10) O[c][m] = sum_n v[c][n] P[m][n] ; out = relu(gamma*O + xa)  (TF32 TC)
    gemm_tf32<true, 4><<<dim3(NN / 128, CC / 128, BB), 256>>>(
        v, S, out, NN, NN, NN, NN, sBCN, sBNN, sBCN, nullptr, nullptr, xa, sBCN, gamma);

    (void)in_sizes; (void)n_in; (void)out_size;
}

// round 6
// speedup vs baseline: 2.3522x; 1.0524x over previous
#include <cuda_runtime.h>
#include <math.h>

// Problem dims (fixed)
#define BB   64
#define CC   256
#define C8   32
#define HH   32
#define WW   32
#define NN   1024            // H*W
#define BCN  16777216        // B*C*N
#define BQN  2097152         // B*C8*N
#define BNN  67108864        // B*N*N

// ---------------- scratch (static device arrays; no runtime alloc) -------------
// __align__(256) is load-bearing: float4/float2 vector access on these.
__device__ __align__(256) float g_t1[BCN];
__device__ __align__(256) float g_t2[BCN];
__device__ __align__(256) float g_t3[BCN];
__device__ __align__(256) float g_xa[BCN];
__device__ __align__(256) float g_q[BQN];
__device__ __align__(256) float g_k[BQN];
__device__ __align__(256) float g_v[BCN];
__device__ __align__(256) float g_S[BNN];
__device__ __align__(256) float g_bn[4 * CC];

// ---------------- BN affine precompute ----------------------------------------
__global__ void bnprep_kernel(const float* __restrict__ g1, const float* __restrict__ b1,
                              const float* __restrict__ m1, const float* __restrict__ v1,
                              const float* __restrict__ g2, const float* __restrict__ b2,
                              const float* __restrict__ m2, const float* __restrict__ v2,
                              float* __restrict__ bn) {
    int c = threadIdx.x;
    float s1 = g1[c] * rsqrtf(v1[c] + 1e-5f);
    float s2 = g2[c] * rsqrtf(v2[c] + 1e-5f);
    bn[c]          = s1;
    bn[CC + c]     = b1[c] - m1[c] * s1;
    bn[2 * CC + c] = s2;
    bn[3 * CC + c] = b2[c] - m2[c] * s2;
}

// ---------------- depthwise 3x3, SAME, stride 1: 4 pixels/thread ---------------
__global__ __launch_bounds__(256) void dwconv_kernel(const float* __restrict__ in,
                                                     const float* __restrict__ w9,
                                                     float* __restrict__ out) {
    __shared__ __align__(16) float s[34 * 34];
    int p = blockIdx.x;           // plane index = b*C + c
    int c = p & (CC - 1);
    const float* ip = in + (long)p * NN;
    float w[9];
#pragma unroll
    for (int j = 0; j < 9; j++) w[j] = w9[c * 9 + j];

    for (int idx = threadIdx.x; idx < 34 * 34; idx += 256) {
        int y = idx / 34 - 1, x = idx % 34 - 1;
        s[idx] = (y >= 0 && y < HH && x >= 0 && x < WW) ? ip[y * WW + x] : 0.0f;
    }
    __syncthreads();

    int oy = threadIdx.x >> 3;            // 0..31
    int ox = (threadIdx.x & 7) * 4;       // 0,4,...,28
    const float* base = s + oy * 34 + ox; // base[dy*34+dx] = in(oy+dy-1, ox+dx-1)
    float acc0 = 0.f, acc1 = 0.f, acc2 = 0.f, acc3 = 0.f;
#pragma unroll
    for (int dy = 0; dy < 3; dy++) {
        float r0 = base[dy * 34 + 0];
        float r1 = base[dy * 34 + 1];
        float r2 = base[dy * 34 + 2];
        float r3 = base[dy * 34 + 3];
        float r4 = base[dy * 34 + 4];
        float r5 = base[dy * 34 + 5];
        float w0 = w[dy * 3 + 0], w1 = w[dy * 3 + 1], w2 = w[dy * 3 + 2];
        acc0 = fmaf(r0, w0, fmaf(r1, w1, fmaf(r2, w2, acc0)));
        acc1 = fmaf(r1, w0, fmaf(r2, w1, fmaf(r3, w2, acc1)));
        acc2 = fmaf(r2, w0, fmaf(r3, w1, fmaf(r4, w2, acc2)));
        acc3 = fmaf(r3, w0, fmaf(r4, w1, fmaf(r5, w2, acc3)));
    }
    *(float4*)(out + (long)p * NN + oy * WW + ox) = make_float4(acc0, acc1, acc2, acc3);
}

// ---------------- fp32 tiled GEMM (precision-sensitive small GEMMs) -------------
template <int TM, int TN, int TK, bool ATR, bool BTR, int EPI>
__global__ __launch_bounds__(256) void gemm_kernel(
    const float* __restrict__ A, const float* __restrict__ B, float* __restrict__ Cm,
    int K, int lda, int ldb, int ldc,
    long sA, long sB, long sC,
    const float* __restrict__ scale, const float* __restrict__ shift,
    const float* __restrict__ res, long sRes,
    const float* __restrict__ gammaPtr) {
    constexpr int RM = TM / 16;
    constexpr int RN = TN / 16;
    __shared__ __align__(16) float As[TK][TM + 1];
    __shared__ __align__(16) float Bs[TK][TN + 1];

    int bz = blockIdx.z;
    const float* Ab = A + (long)bz * sA;
    const float* Bb = B + (long)bz * sB;
    int m0 = blockIdx.y * TM;
    int n0 = blockIdx.x * TN;
    int tid = threadIdx.x;
    int ty = tid >> 4, tx = tid & 15;

    float acc[RM][RN];
#pragma unroll
    for (int i = 0; i < RM; i++)
#pragma unroll
        for (int j = 0; j < RN; j++) acc[i][j] = 0.0f;

    for (int k0 = 0; k0 < K; k0 += TK) {
        if (ATR) {
            int k = tid & (TK - 1);
            int mrow = tid / TK;
#pragma unroll
            for (int r = 0; r < (TM * TK) / 256; r++) {
                int m = mrow + r * (256 / TK);
                As[k][m] = Ab[(long)(m0 + m) * lda + (k0 + k)];
            }
        } else {
#pragma unroll
            for (int r = 0; r < (TM * TK) / 256; r++) {
                int idx = tid + r * 256;
                int k = idx / TM, m = idx % TM;
                As[k][m] = Ab[(long)(k0 + k) * lda + (m0 + m)];
            }
        }
        if (BTR) {
            int k = tid & (TK - 1);
            int nrow = tid / TK;
#pragma unroll
            for (int r = 0; r < (TN * TK) / 256; r++) {
                int n = nrow + r * (256 / TK);
                Bs[k][n] = Bb[(long)(n0 + n) * ldb + (k0 + k)];
            }
        } else {
#pragma unroll
            for (int r = 0; r < (TN * TK) / 256; r++) {
                int idx = tid + r * 256;
                int k = idx / TN, n = idx % TN;
                Bs[k][n] = Bb[(long)(k0 + k) * ldb + (n0 + n)];
            }
        }
        __syncthreads();

#pragma unroll
        for (int k = 0; k < TK; k++) {
            float a[RM], bv[RN];
#pragma unroll
            for (int i = 0; i < RM; i++) a[i] = As[k][ty + 16 * i];
#pragma unroll
            for (int j = 0; j < RN; j++) bv[j] = Bs[k][tx + 16 * j];
#pragma unroll
            for (int i = 0; i < RM; i++)
#pragma unroll
                for (int j = 0; j < RN; j++) acc[i][j] = fmaf(a[i], bv[j], acc[i][j]);
        }
        __syncthreads();
    }

    float gm = 0.0f;
    if (EPI == 4) gm = gammaPtr[0];

#pragma unroll
    for (int i = 0; i < RM; i++) {
        int m = m0 + ty + 16 * i;
#pragma unroll
        for (int j = 0; j < RN; j++) {
            int n = n0 + tx + 16 * j;
            float val = acc[i][j];
            if (EPI == 0) {
                val = fmaxf(fmaf(val, scale[m], shift[m]), 0.0f);
            } else if (EPI == 1) {
                val = fmaf(val, scale[m], shift[m]) + res[(long)bz * sRes + (long)m * ldc + n];
            } else if (EPI == 2) {
                val = val + scale[m];
            } else if (EPI == 4) {
                val = fmaxf(fmaf(gm, val, res[(long)bz * sRes + (long)m * ldc + n]), 0.0f);
            }
            Cm[(long)bz * sC + (long)m * ldc + n] = val;
        }
    }
}

// ---------------- TF32 tensor-core GEMM ----------------------------------------
// C[b][m][n] = sum_k A[b][m][k]*B[...]  (A always [M,K] k-contiguous)
// BTR=false: B stored [K,N] n-contiguous.  BTR=true: B stored [N,K] k-contiguous.
// Smem layout for k-contiguous operands is fragment-interleaved:
//   X[kstep][row][slot], slot pair (2t,2t+1) holds (k=t, k=t+4) within the 8-wide
//   k-step -> every fragment fetch is a conflict-free LDS.64.
// __align__(16) on the shared arrays is load-bearing: LDS.64 from a shared array
// with only the default 4-byte alignment is the same wide-op trap that killed the
// unaligned global LDG.128 earlier.
__device__ __forceinline__ unsigned f2tf(float x) {
    unsigned r;
    asm("cvt.rna.tf32.f32 %0, %1;" : "=r"(r) : "f"(x));
    return r;
}

template <bool BTR, int EPI>
__global__ __launch_bounds__(256) void gemm_tf32(
    const float* __restrict__ A, const float* __restrict__ B, float* __restrict__ Cm,
    int K, int lda, int ldb, int ldc,
    long sA, long sB, long sC,
    const float* __restrict__ scale, const float* __restrict__ shift,
    const float* __restrict__ res, long sRes,
    const float* __restrict__ gammaPtr) {
    constexpr int BM = 128, BN = 128, BK = 16;
    __shared__ __align__(16) unsigned As2[2][2][BM][8];    // 16 KB
    constexpr int BSZ = BTR ? (2 * 2 * BN * 8) : (2 * BK * (BN + 4));
    __shared__ __align__(16) unsigned Bsh[BSZ];            // 16-16.5 KB

    int tid = threadIdx.x;
    int bz = blockIdx.z;
    const float* Ab = A + (long)bz * sA;
    const float* Bb = B + (long)bz * sB;
    int m0 = blockIdx.y * BM, n0 = blockIdx.x * BN;

    int arow = tid >> 2;            // 0..63
    int akq = (tid & 3) * 4;        // k quad base
    int brow, bcq;
    if (BTR) { brow = tid >> 2; bcq = (tid & 3) * 4; }
    else     { brow = tid >> 5; bcq = (tid & 31) * 4; }

    float4 pa[2], pb[2];

    auto ldgAB = [&](int k0) {
#pragma unroll
        for (int r = 0; r < 2; r++)
            pa[r] = *(const float4*)(Ab + (long)(m0 + arow + r * 64) * lda + k0 + akq);
        if (BTR) {
#pragma unroll
            for (int r = 0; r < 2; r++)
                pb[r] = *(const float4*)(Bb + (long)(n0 + brow + r * 64) * ldb + k0 + bcq);
        } else {
#pragma unroll
            for (int r = 0; r < 2; r++)
                pb[r] = *(const float4*)(Bb + (long)(k0 + brow + r * 8) * ldb + n0 + bcq);
        }
    };
    auto stsAB = [&](int buf) {
#pragma unroll
        for (int r = 0; r < 2; r++) {
            int m = arow + r * 64;
            float v[4] = {pa[r].x, pa[r].y, pa[r].z, pa[r].w};
#pragma unroll
            for (int j = 0; j < 4; j++) {
                int k = akq + j, ks = k >> 3, kk = k & 7;
                As2[buf][ks][m][(kk & 3) * 2 + (kk >> 2)] = f2tf(v[j]);
            }
        }
        if (BTR) {
#pragma unroll
            for (int r = 0; r < 2; r++) {
                int n = brow + r * 64;
                float v[4] = {pb[r].x, pb[r].y, pb[r].z, pb[r].w};
#pragma unroll
                for (int j = 0; j < 4; j++) {
                    int k = bcq + j, ks = k >> 3, kk = k & 7;
                    Bsh[(((buf * 2 + ks) * BN) + n) * 8 + (kk & 3) * 2 + (kk >> 2)] = f2tf(v[j]);
                }
            }
        } else {
#pragma unroll
            for (int r = 0; r < 2; r++) {
                int k = brow + r * 8;
                float v[4] = {pb[r].x, pb[r].y, pb[r].z, pb[r].w};
#pragma unroll
                for (int j = 0; j < 4; j++)
                    Bsh[(buf * BK + k) * (BN + 4) + bcq + j] = f2tf(v[j]);
            }
        }
    };

    int lane = tid & 31, warp = tid >> 5;
    int wm = (warp >> 2) * 64;      // 0 or 64
    int wn = (warp & 3) * 32;       // 0,32,64,96
    int gid = lane >> 2, tig = lane & 3;

    float acc[4][4][4];
#pragma unroll
    for (int i = 0; i < 4; i++)
#pragma unroll
        for (int j = 0; j < 4; j++)
#pragma unroll
            for (int e = 0; e < 4; e++) acc[i][j][e] = 0.0f;

    ldgAB(0);
    stsAB(0);
    __syncthreads();

    int nk = K / BK;
    for (int t = 0; t < nk; t++) {
        int cur = t & 1;
        if (t + 1 < nk) ldgAB((t + 1) * BK);

#pragma unroll
        for (int ks = 0; ks < 2; ks++) {
            unsigned af[4][4], bf[4][2];
#pragma unroll
            for (int mi = 0; mi < 4; mi++) {
                int m = wm + 16 * mi + gid;
                uint2 lo = *(const uint2*)&As2[cur][ks][m][2 * tig];
                uint2 hi = *(const uint2*)&As2[cur][ks][m + 8][2 * tig];
                af[mi][0] = lo.x;  // (row gid,   k tig)
                af[mi][1] = hi.x;  // (row gid+8, k tig)
                af[mi][2] = lo.y;  // (row gid,   k tig+4)
                af[mi][3] = hi.y;  // (row gid+8, k tig+4)
            }
#pragma unroll
            for (int nj = 0; nj < 4; nj++) {
                int n = wn + 8 * nj + gid;
                if (BTR) {
                    uint2 t2 = *(const uint2*)&Bsh[(((cur * 2 + ks) * BN) + n) * 8 + 2 * tig];
                    bf[nj][0] = t2.x;   // (k tig,   n)
                    bf[nj][1] = t2.y;   // (k tig+4, n)
                } else {
                    bf[nj][0] = Bsh[(cur * BK + ks * 8 + tig) * (BN + 4) + n];
                    bf[nj][1] = Bsh[(cur * BK + ks * 8 + 4 + tig) * (BN + 4) + n];
                }
            }
#pragma unroll
            for (int mi = 0; mi < 4; mi++)
#pragma unroll
                for (int nj = 0; nj < 4; nj++) {
                    asm volatile(
                        "mma.sync.aligned.m16n8k8.row.col.f32.tf32.tf32.f32 "
                        "{%0,%1,%2,%3},{%4,%5,%6,%7},{%8,%9},{%0,%1,%2,%3};\n"
                        : "+f"(acc[mi][nj][0]), "+f"(acc[mi][nj][1]),
                          "+f"(acc[mi][nj][2]), "+f"(acc[mi][nj][3])
                        : "r"(af[mi][0]), "r"(af[mi][1]), "r"(af[mi][2]), "r"(af[mi][3]),
                          "r"(bf[nj][0]), "r"(bf[nj][1]));
                }
        }
        if (t + 1 < nk) {
            // stores target buffer cur^1 whose last readers were fenced by the
            // previous iteration's barrier -> single barrier per k-tile.
            stsAB(cur ^ 1);
            __syncthreads();
        }
    }

    float gm = (EPI == 4) ? gammaPtr[0] : 0.0f;
    const float* resb = res ? res + (long)bz * sRes : nullptr;
    float* Cb = Cm + (long)bz * sC;

#pragma unroll
    for (int mi = 0; mi < 4; mi++) {
#pragma unroll
        for (int e2 = 0; e2 < 2; e2++) {
            int m = m0 + wm + 16 * mi + gid + 8 * e2;
            float sc = 0.0f, sh = 0.0f;
            if (EPI == 0 || EPI == 1) { sc = scale[m]; sh = shift[m]; }
            else if (EPI == 2) { sc = scale[m]; }
#pragma unroll
            for (int nj = 0; nj < 4; nj++) {
                int n = n0 + wn + 8 * nj + 2 * tig;
                float v0 = acc[mi][nj][2 * e2 + 0];
                float v1 = acc[mi][nj][2 * e2 + 1];
                if (EPI == 0) {
                    v0 = fmaxf(fmaf(v0, sc, sh), 0.0f);
                    v1 = fmaxf(fmaf(v1, sc, sh), 0.0f);
                } else if (EPI == 1) {
                    float2 r2 = *(const float2*)(resb + (long)m * ldc + n);
                    v0 = fmaf(v0, sc, sh) + r2.x;
                    v1 = fmaf(v1, sc, sh) + r2.y;
                } else if (EPI == 2) {
                    v0 += sc; v1 += sc;
                } else if (EPI == 4) {
                    float2 r2 = *(const float2*)(resb + (long)m * ldc + n);
                    v0 = fmaxf(fmaf(gm, v0, r2.x), 0.0f);
                    v1 = fmaxf(fmaf(gm, v1, r2.y), 0.0f);
                }
                *(float2*)(Cb + (long)m * ldc + n) = make_float2(v0, v1);
            }
        }
    }
}

// ---------------- row softmax over 1024 elements --------------------------------
__global__ __launch_bounds__(256) void softmax_kernel(float* __restrict__ S) {
    __shared__ float red[256];
    float* p = S + (long)blockIdx.x * NN;
    int t = threadIdx.x;
    float v[4];
#pragma unroll
    for (int i = 0; i < 4; i++) v[i] = p[t + i * 256];
    float m = fmaxf(fmaxf(v[0], v[1]), fmaxf(v[2], v[3]));
    red[t] = m;
    __syncthreads();
    for (int s2 = 128; s2 > 0; s2 >>= 1) {
        if (t < s2) red[t] = fmaxf(red[t], red[t + s2]);
        __syncthreads();
    }
    m = red[0];
    __syncthreads();
    float sum = 0.0f;
#pragma unroll
    for (int i = 0; i < 4; i++) {
        v[i] = __expf(v[i] - m);
        sum += v[i];
    }
    red[t] = sum;
    __syncthreads();
    for (int s2 = 128; s2 > 0; s2 >>= 1) {
        if (t < s2) red[t] += red[t + s2];
        __syncthreads();
    }
    float inv = 1.0f / red[0];
#pragma unroll
    for (int i = 0; i < 4; i++) p[t + i * 256] = v[i] * inv;
}

// ---------------- launch ---------------------------------------------------------
extern "C" void kernel_launch(void* const* d_in, const int* in_sizes, int n_in,
                              void* d_out, int out_size) {
    const float* x     = (const float*)d_in[0];
    const float* dw1   = (const float*)d_in[1];
    const float* pw1   = (const float*)d_in[2];
    const float* bn1_g = (const float*)d_in[3];
    const float* bn1_b = (const float*)d_in[4];
    const float* bn1_m = (const float*)d_in[5];
    const float* bn1_v = (const float*)d_in[6];
    const float* dw2   = (const float*)d_in[7];
    const float* pw2   = (const float*)d_in[8];
    const float* bn2_g = (const float*)d_in[9];
    const float* bn2_b = (const float*)d_in[10];
    const float* bn2_m = (const float*)d_in[11];
    const float* bn2_v = (const float*)d_in[12];
    const float* wq    = (const float*)d_in[13];
    const float* bq    = (const float*)d_in[14];
    const float* wk    = (const float*)d_in[15];
    const float* bk    = (const float*)d_in[16];
    const float* wv    = (const float*)d_in[17];
    const float* bv    = (const float*)d_in[18];
    const float* gamma = (const float*)d_in[19];
    float* out = (float*)d_out;

    float *t1, *t2, *t3, *xa, *q, *k, *v, *S, *bn;
    cudaGetSymbolAddress((void**)&t1, g_t1);
    cudaGetSymbolAddress((void**)&t2, g_t2);
    cudaGetSymbolAddress((void**)&t3, g_t3);
    cudaGetSymbolAddress((void**)&xa, g_xa);
    cudaGetSymbolAddress((void**)&q,  g_q);
    cudaGetSymbolAddress((void**)&k,  g_k);
    cudaGetSymbolAddress((void**)&v,  g_v);
    cudaGetSymbolAddress((void**)&S,  g_S);
    cudaGetSymbolAddress((void**)&bn, g_bn);
    const float* scale1 = bn;
    const float* shift1 = bn + CC;
    const float* scale2 = bn + 2 * CC;
    const float* shift2 = bn + 3 * CC;

    const long sBCN = (long)CC * NN;   // 262144
    const long sBQN = (long)C8 * NN;   // 32768
    const long sBNN = (long)NN * NN;   // 1048576

    // 0) BN affine precompute
    bnprep_kernel<<<1, CC>>>(bn1_g, bn1_b, bn1_m, bn1_v, bn2_g, bn2_b, bn2_m, bn2_v, bn);

    // 1) depthwise 1
    dwconv_kernel<<<BB * CC, 256>>>(x, dw1, t1);

    // 2) pointwise 1 + BN + ReLU (TF32 TC)
    gemm_tf32<false, 0><<<dim3(NN / 128, CC / 128, BB), 256>>>(
        pw1, t1, t2, CC, CC, NN, NN, 0, sBCN, sBCN, scale1, shift1, nullptr, 0, nullptr);

    // 3) depthwise 2
    dwconv_kernel<<<BB * CC, 256>>>(t2, dw2, t3);

    // 4) pointwise 2 + BN + residual x (TF32 TC)
    gemm_tf32<false, 1><<<dim3(NN / 128, CC / 128, BB), 256>>>(
        pw2, t3, xa, CC, CC, NN, NN, 0, sBCN, sBCN, scale2, shift2, x, sBCN, nullptr);

    // 5) q = wq @ xa + bq  (fp32, precision-sensitive for softmax)
    gemm_kernel<32, 64, 16, true, false, 2><<<dim3(NN / 64, 1, BB), 256>>>(
        wq, xa, q, CC, CC, NN, NN, 0, sBCN, sBQN, bq, nullptr, nullptr, 0, nullptr);

    // 6) k = wk @ xa + bk  (fp32)
    gemm_kernel<32, 64, 16, true, false, 2><<<dim3(NN / 64, 1, BB), 256>>>(
        wk, xa, k, CC, CC, NN, NN, 0, sBCN, sBQN, bk, nullptr, nullptr, 0, nullptr);

    // 7) v = wv @ xa + bv (TF32 TC)
    gemm_tf32<false, 2><<<dim3(NN / 128, CC / 128, BB), 256>>>(
        wv, xa, v, CC, CC, NN, NN, 0, sBCN, sBCN, bv, nullptr, nullptr, 0, nullptr);

    // 8) S[m][n] = sum_d q[d][m] k[d][n]  (fp32, feeds softmax)
    gemm_kernel<64, 64, 16, false, false, 3><<<dim3(NN / 64, NN / 64, BB), 256>>>(
        q, k, S, C8, NN, NN, NN, sBQN, sBQN, sBNN, nullptr, nullptr, nullptr, 0, nullptr);

    // 9) softmax over n (rows of S)
    softmax_kernel<<<BB * NN, 256>>>(S);

    // 10) O[c][m] = sum_n v[c][n] P[m][n] ; out = relu(gamma*O + xa)  (TF32 TC)
    gemm_tf32<true, 4><<<dim3(NN / 128, CC / 128, BB), 256>>>(
        v, S, out, NN, NN, NN, NN, sBCN, sBNN, sBCN, nullptr, nullptr, xa, sBCN, gamma);

    (void)in_sizes; (void)n_in; (void)out_size;
}

// round 8
// speedup vs baseline: 2.3686x; 1.0070x over previous
#include <cuda_runtime.h>
#include <stdint.h>
#include <math.h>

// Problem dims (fixed)
#define BB   64
#define CC   256
#define C8   32
#define HH   32
#define WW   32
#define NN   1024            // H*W
#define BCN  16777216        // B*C*N
#define BQN  2097152         // B*C8*N
#define BNN  67108864        // B*N*N

// ---------------- scratch (static device arrays; no runtime alloc) -------------
// __align__(256) is load-bearing: float4/float2 vector access on these.
__device__ __align__(256) float g_t1[BCN];
__device__ __align__(256) float g_t2[BCN];
__device__ __align__(256) float g_t3[BCN];
__device__ __align__(256) float g_xa[BCN];
__device__ __align__(256) float g_q[BQN];
__device__ __align__(256) float g_k[BQN];
__device__ __align__(256) float g_v[BCN];
__device__ __align__(256) float g_S[BNN];
__device__ __align__(256) float g_bn[4 * CC];

// ---------------- BN affine precompute ----------------------------------------
__global__ void bnprep_kernel(const float* __restrict__ g1, const float* __restrict__ b1,
                              const float* __restrict__ m1, const float* __restrict__ v1,
                              const float* __restrict__ g2, const float* __restrict__ b2,
                              const float* __restrict__ m2, const float* __restrict__ v2,
                              float* __restrict__ bn) {
    int c = threadIdx.x;
    float s1 = g1[c] * rsqrtf(v1[c] + 1e-5f);
    float s2 = g2[c] * rsqrtf(v2[c] + 1e-5f);
    bn[c]          = s1;
    bn[CC + c]     = b1[c] - m1[c] * s1;
    bn[2 * CC + c] = s2;
    bn[3 * CC + c] = b2[c] - m2[c] * s2;
}

// ---------------- depthwise 3x3, SAME, stride 1: 4 pixels/thread ---------------
__global__ __launch_bounds__(256) void dwconv_kernel(const float* __restrict__ in,
                                                     const float* __restrict__ w9,
                                                     float* __restrict__ out) {
    __shared__ __align__(16) float s[34 * 34];
    int p = blockIdx.x;           // plane index = b*C + c
    int c = p & (CC - 1);
    const float* ip = in + (long)p * NN;
    float w[9];
#pragma unroll
    for (int j = 0; j < 9; j++) w[j] = w9[c * 9 + j];

    for (int idx = threadIdx.x; idx < 34 * 34; idx += 256) {
        int y = idx / 34 - 1, x = idx % 34 - 1;
        s[idx] = (y >= 0 && y < HH && x >= 0 && x < WW) ? ip[y * WW + x] : 0.0f;
    }
    __syncthreads();

    int oy = threadIdx.x >> 3;            // 0..31
    int ox = (threadIdx.x & 7) * 4;       // 0,4,...,28
    const float* base = s + oy * 34 + ox;
    float acc0 = 0.f, acc1 = 0.f, acc2 = 0.f, acc3 = 0.f;
#pragma unroll
    for (int dy = 0; dy < 3; dy++) {
        float r0 = base[dy * 34 + 0];
        float r1 = base[dy * 34 + 1];
        float r2 = base[dy * 34 + 2];
        float r3 = base[dy * 34 + 3];
        float r4 = base[dy * 34 + 4];
        float r5 = base[dy * 34 + 5];
        float w0 = w[dy * 3 + 0], w1 = w[dy * 3 + 1], w2 = w[dy * 3 + 2];
        acc0 = fmaf(r0, w0, fmaf(r1, w1, fmaf(r2, w2, acc0)));
        acc1 = fmaf(r1, w0, fmaf(r2, w1, fmaf(r3, w2, acc1)));
        acc2 = fmaf(r2, w0, fmaf(r3, w1, fmaf(r4, w2, acc2)));
        acc3 = fmaf(r3, w0, fmaf(r4, w1, fmaf(r5, w2, acc3)));
    }
    *(float4*)(out + (long)p * NN + oy * WW + ox) = make_float4(acc0, acc1, acc2, acc3);
}

// ---------------- fp32 tiled GEMM (precision-sensitive small GEMMs) -------------
template <int TM, int TN, int TK, bool ATR, bool BTR, int EPI>
__global__ __launch_bounds__(256) void gemm_kernel(
    const float* __restrict__ A, const float* __restrict__ B, float* __restrict__ Cm,
    int K, int lda, int ldb, int ldc,
    long sA, long sB, long sC,
    const float* __restrict__ scale, const float* __restrict__ shift,
    const float* __restrict__ res, long sRes,
    const float* __restrict__ gammaPtr) {
    constexpr int RM = TM / 16;
    constexpr int RN = TN / 16;
    __shared__ __align__(16) float As[TK][TM + 1];
    __shared__ __align__(16) float Bs[TK][TN + 1];

    int bz = blockIdx.z;
    const float* Ab = A + (long)bz * sA;
    const float* Bb = B + (long)bz * sB;
    int m0 = blockIdx.y * TM;
    int n0 = blockIdx.x * TN;
    int tid = threadIdx.x;
    int ty = tid >> 4, tx = tid & 15;

    float acc[RM][RN];
#pragma unroll
    for (int i = 0; i < RM; i++)
#pragma unroll
        for (int j = 0; j < RN; j++) acc[i][j] = 0.0f;

    for (int k0 = 0; k0 < K; k0 += TK) {
        if (ATR) {
            int k = tid & (TK - 1);
            int mrow = tid / TK;
#pragma unroll
            for (int r = 0; r < (TM * TK) / 256; r++) {
                int m = mrow + r * (256 / TK);
                As[k][m] = Ab[(long)(m0 + m) * lda + (k0 + k)];
            }
        } else {
#pragma unroll
            for (int r = 0; r < (TM * TK) / 256; r++) {
                int idx = tid + r * 256;
                int k = idx / TM, m = idx % TM;
                As[k][m] = Ab[(long)(k0 + k) * lda + (m0 + m)];
            }
        }
        if (BTR) {
            int k = tid & (TK - 1);
            int nrow = tid / TK;
#pragma unroll
            for (int r = 0; r < (TN * TK) / 256; r++) {
                int n = nrow + r * (256 / TK);
                Bs[k][n] = Bb[(long)(n0 + n) * ldb + (k0 + k)];
            }
        } else {
#pragma unroll
            for (int r = 0; r < (TN * TK) / 256; r++) {
                int idx = tid + r * 256;
                int k = idx / TN, n = idx % TN;
                Bs[k][n] = Bb[(long)(k0 + k) * ldb + (n0 + n)];
            }
        }
        __syncthreads();

#pragma unroll
        for (int k = 0; k < TK; k++) {
            float a[RM], bv[RN];
#pragma unroll
            for (int i = 0; i < RM; i++) a[i] = As[k][ty + 16 * i];
#pragma unroll
            for (int j = 0; j < RN; j++) bv[j] = Bs[k][tx + 16 * j];
#pragma unroll
            for (int i = 0; i < RM; i++)
#pragma unroll
                for (int j = 0; j < RN; j++) acc[i][j] = fmaf(a[i], bv[j], acc[i][j]);
        }
        __syncthreads();
    }

    float gm = 0.0f;
    if (EPI == 4) gm = gammaPtr[0];

#pragma unroll
    for (int i = 0; i < RM; i++) {
        int m = m0 + ty + 16 * i;
#pragma unroll
        for (int j = 0; j < RN; j++) {
            int n = n0 + tx + 16 * j;
            float val = acc[i][j];
            if (EPI == 0) {
                val = fmaxf(fmaf(val, scale[m], shift[m]), 0.0f);
            } else if (EPI == 1) {
                val = fmaf(val, scale[m], shift[m]) + res[(long)bz * sRes + (long)m * ldc + n];
            } else if (EPI == 2) {
                val = val + scale[m];
            } else if (EPI == 4) {
                val = fmaxf(fmaf(gm, val, res[(long)bz * sRes + (long)m * ldc + n]), 0.0f);
            }
            Cm[(long)bz * sC + (long)m * ldc + n] = val;
        }
    }
}

// ---------------- cp.async helpers ----------------------------------------------
__device__ __forceinline__ void cp16(uint32_t dst, const float* src) {
    asm volatile("cp.async.ca.shared.global [%0], [%1], 16;" :: "r"(dst), "l"(src));
}
__device__ __forceinline__ void cp_commit() {
    asm volatile("cp.async.commit_group;" ::: "memory");
}
template <int N>
__device__ __forceinline__ void cp_wait() {
    asm volatile("cp.async.wait_group %0;" :: "n"(N) : "memory");
}

// ---------------- TF32 tensor-core GEMM, cp.async 2-stage pipeline --------------
// C[b][m][n] = sum_k A[b][m][k]*B[...]  (A always [M,K] k-contiguous)
// BTR=false: B stored [K,N] n-contiguous.  BTR=true: B stored [N,K] k-contiguous.
// Smem: A / k-contiguous B as [row][16 (+4 pad)] (stride 20 floats: 16B-aligned
// cp.async dst, fragment banks 20*gid+tig all distinct). n-contiguous B as
// [k][128 (+8 pad)] (stride 136: banks 8*tig+gid all distinct).
// mma consumes raw fp32 bits as tf32 (hardware truncates low mantissa bits).
template <bool BTR, int EPI>
__global__ __launch_bounds__(256) void gemm_tf32(
    const float* __restrict__ A, const float* __restrict__ B, float* __restrict__ Cm,
    int K, int lda, int ldb, int ldc,
    long sA, long sB, long sC,
    const float* __restrict__ scale, const float* __restrict__ shift,
    const float* __restrict__ res, long sRes,
    const float* __restrict__ gammaPtr) {
    constexpr int BM = 128, BN = 128, BK = 16;
    constexpr int APAD = 20;
    constexpr int BROWS = BTR ? BN : BK;
    constexpr int BPAD  = BTR ? 20 : (BN + 8);
    __shared__ __align__(16) float As[2][BM][APAD];       // 20.0 KB
    __shared__ __align__(16) float Bs[2][BROWS][BPAD];    // 17.0-20.0 KB

    int tid = threadIdx.x;
    int bz = blockIdx.z;
    const float* Ab = A + (long)bz * sA;
    const float* Bb = B + (long)bz * sB;
    int m0 = blockIdx.y * BM, n0 = blockIdx.x * BN;

    // loader indices: 512 16B-chunks per operand tile, 2 per thread
    int a_row = tid >> 1;
    int a_q   = (tid & 1) * 2;
    int b_row, b_q;
    if (BTR) { b_row = tid >> 1; b_q = (tid & 1) * 2; }
    else     { b_row = tid >> 4; b_q = (tid & 15) * 2; }

    uint32_t asBase = (uint32_t)__cvta_generic_to_shared(&As[0][0][0]);
    uint32_t bsBase = (uint32_t)__cvta_generic_to_shared(&Bs[0][0][0]);

    auto prefetch = [&](int buf, int k0) {
#pragma unroll
        for (int j = 0; j < 2; j++) {
            int q = a_q + j;
            cp16(asBase + (((buf * BM + a_row) * APAD) + q * 4) * 4,
                 Ab + (long)(m0 + a_row) * lda + k0 + q * 4);
        }
        if (BTR) {
#pragma unroll
            for (int j = 0; j < 2; j++) {
                int q = b_q + j;
                cp16(bsBase + (((buf * BROWS + b_row) * BPAD) + q * 4) * 4,
                     Bb + (long)(n0 + b_row) * ldb + k0 + q * 4);
            }
        } else {
#pragma unroll
            for (int j = 0; j < 2; j++) {
                int q = b_q + j;
                cp16(bsBase + (((buf * BROWS + b_row) * BPAD) + q * 4) * 4,
                     Bb + (long)(k0 + b_row) * ldb + n0 + q * 4);
            }
        }
        cp_commit();
    };

    int lane = tid & 31, warp = tid >> 5;
    int wm = (warp >> 2) * 64;      // 0 or 64
    int wn = (warp & 3) * 32;       // 0,32,64,96
    int gid = lane >> 2, tig = lane & 3;

    float acc[4][4][4];
#pragma unroll
    for (int i = 0; i < 4; i++)
#pragma unroll
        for (int j = 0; j < 4; j++)
#pragma unroll
            for (int e = 0; e < 4; e++) acc[i][j][e] = 0.0f;

    prefetch(0, 0);

    int nk = K / BK;
    for (int t = 0; t < nk; t++) {
        int cur = t & 1;
        if (t + 1 < nk) {
            prefetch(cur ^ 1, (t + 1) * BK);
            cp_wait<1>();
        } else {
            cp_wait<0>();
        }
        __syncthreads();

#pragma unroll
        for (int ks = 0; ks < 2; ks++) {
            int kb = ks * 8;
            unsigned af[4][4], bf[4][2];
#pragma unroll
            for (int mi = 0; mi < 4; mi++) {
                const float* ap = &As[cur][wm + 16 * mi + gid][kb + tig];
                af[mi][0] = __float_as_uint(ap[0]);              // (row gid,   k tig)
                af[mi][1] = __float_as_uint(ap[8 * APAD]);       // (row gid+8, k tig)
                af[mi][2] = __float_as_uint(ap[4]);              // (row gid,   k tig+4)
                af[mi][3] = __float_as_uint(ap[8 * APAD + 4]);   // (row gid+8, k tig+4)
            }
#pragma unroll
            for (int nj = 0; nj < 4; nj++) {
                if (BTR) {
                    const float* bp = &Bs[cur][wn + 8 * nj + gid][kb + tig];
                    bf[nj][0] = __float_as_uint(bp[0]);          // (k tig,   n)
                    bf[nj][1] = __float_as_uint(bp[4]);          // (k tig+4, n)
                } else {
                    int n = wn + 8 * nj + gid;
                    bf[nj][0] = __float_as_uint(Bs[cur][kb + tig][n]);
                    bf[nj][1] = __float_as_uint(Bs[cur][kb + 4 + tig][n]);
                }
            }
#pragma unroll
            for (int mi = 0; mi < 4; mi++)
#pragma unroll
                for (int nj = 0; nj < 4; nj++) {
                    asm volatile(
                        "mma.sync.aligned.m16n8k8.row.col.f32.tf32.tf32.f32 "
                        "{%0,%1,%2,%3},{%4,%5,%6,%7},{%8,%9},{%0,%1,%2,%3};\n"
                        : "+f"(acc[mi][nj][0]), "+f"(acc[mi][nj][1]),
                          "+f"(acc[mi][nj][2]), "+f"(acc[mi][nj][3])
                        : "r"(af[mi][0]), "r"(af[mi][1]), "r"(af[mi][2]), "r"(af[mi][3]),
                          "r"(bf[nj][0]), "r"(bf[nj][1]));
                }
        }
        __syncthreads();   // all warps done reading stage `cur` before t+1's prefetch reuses it
    }

    float gm = (EPI == 4) ? gammaPtr[0] : 0.0f;
    const float* resb = res ? res + (long)bz * sRes : nullptr;
    float* Cb = Cm + (long)bz * sC;

#pragma unroll
    for (int mi = 0; mi < 4; mi++) {
#pragma unroll
        for (int e2 = 0; e2 < 2; e2++) {
            int m = m0 + wm + 16 * mi + gid + 8 * e2;
            float sc = 0.0f, sh = 0.0f;
            if (EPI == 0 || EPI == 1) { sc = scale[m]; sh = shift[m]; }
            else if (EPI == 2) { sc = scale[m]; }
#pragma unroll
            for (int nj = 0; nj < 4; nj++) {
                int n = n0 + wn + 8 * nj + 2 * tig;
                float v0 = acc[mi][nj][2 * e2 + 0];
                float v1 = acc[mi][nj][2 * e2 + 1];
                if (EPI == 0) {
                    v0 = fmaxf(fmaf(v0, sc, sh), 0.0f);
                    v1 = fmaxf(fmaf(v1, sc, sh), 0.0f);
                } else if (EPI == 1) {
                    float2 r2 = *(const float2*)(resb + (long)m * ldc + n);
                    v0 = fmaf(v0, sc, sh) + r2.x;
                    v1 = fmaf(v1, sc, sh) + r2.y;
                } else if (EPI == 2) {
                    v0 += sc; v1 += sc;
                } else if (EPI == 4) {
                    float2 r2 = *(const float2*)(resb + (long)m * ldc + n);
                    v0 = fmaxf(fmaf(gm, v0, r2.x), 0.0f);
                    v1 = fmaxf(fmaf(gm, v1, r2.y), 0.0f);
                }
                *(float2*)(Cb + (long)m * ldc + n) = make_float2(v0, v1);
            }
        }
    }
}

// ---------------- row softmax over 1024 elements --------------------------------
__global__ __launch_bounds__(256) void softmax_kernel(float* __restrict__ S) {
    __shared__ float red[256];
    float* p = S + (long)blockIdx.x * NN;
    int t = threadIdx.x;
    float v[4];
#pragma unroll
    for (int i = 0; i < 4; i++) v[i] = p[t + i * 256];
    float m = fmaxf(fmaxf(v[0], v[1]), fmaxf(v[2], v[3]));
    red[t] = m;
    __syncthreads();
    for (int s2 = 128; s2 > 0; s2 >>= 1) {
        if (t < s2) red[t] = fmaxf(red[t], red[t + s2]);
        __syncthreads();
    }
    m = red[0];
    __syncthreads();
    float sum = 0.0f;
#pragma unroll
    for (int i = 0; i < 4; i++) {
        v[i] = __expf(v[i] - m);
        sum += v[i];
    }
    red[t] = sum;
    __syncthreads();
    for (int s2 = 128; s2 > 0; s2 >>= 1) {
        if (t < s2) red[t] += red[t + s2];
        __syncthreads();
    }
    float inv = 1.0f / red[0];
#pragma unroll
    for (int i = 0; i < 4; i++) p[t + i * 256] = v[i] * inv;
}

// ---------------- launch ---------------------------------------------------------
extern "C" void kernel_launch(void* const* d_in, const int* in_sizes, int n_in,
                              void* d_out, int out_size) {
    const float* x     = (const float*)d_in[0];
    const float* dw1   = (const float*)d_in[1];
    const float* pw1   = (const float*)d_in[2];
    const float* bn1_g = (const float*)d_in[3];
    const float* bn1_b = (const float*)d_in[4];
    const float* bn1_m = (const float*)d_in[5];
    const float* bn1_v = (const float*)d_in[6];
    const float* dw2   = (const float*)d_in[7];
    const float* pw2   = (const float*)d_in[8];
    const float* bn2_g = (const float*)d_in[9];
    const float* bn2_b = (const float*)d_in[10];
    const float* bn2_m = (const float*)d_in[11];
    const float* bn2_v = (const float*)d_in[12];
    const float* wq    = (const float*)d_in[13];
    const float* bq    = (const float*)d_in[14];
    const float* wk    = (const float*)d_in[15];
    const float* bk    = (const float*)d_in[16];
    const float* wv    = (const float*)d_in[17];
    const float* bv    = (const float*)d_in[18];
    const float* gamma = (const float*)d_in[19];
    float* out = (float*)d_out;

    float *t1, *t2, *t3, *xa, *q, *k, *v, *S, *bn;
    cudaGetSymbolAddress((void**)&t1, g_t1);
    cudaGetSymbolAddress((void**)&t2, g_t2);
    cudaGetSymbolAddress((void**)&t3, g_t3);
    cudaGetSymbolAddress((void**)&xa, g_xa);
    cudaGetSymbolAddress((void**)&q,  g_q);
    cudaGetSymbolAddress((void**)&k,  g_k);
    cudaGetSymbolAddress((void**)&v,  g_v);
    cudaGetSymbolAddress((void**)&S,  g_S);
    cudaGetSymbolAddress((void**)&bn, g_bn);
    const float* scale1 = bn;
    const float* shift1 = bn + CC;
    const float* scale2 = bn + 2 * CC;
    const float* shift2 = bn + 3 * CC;

    const long sBCN = (long)CC * NN;   // 262144
    const long sBQN = (long)C8 * NN;   // 32768
    const long sBNN = (long)NN * NN;   // 1048576

    // 0) BN affine precompute
    bnprep_kernel<<<1, CC>>>(bn1_g, bn1_b, bn1_m, bn1_v, bn2_g, bn2_b, bn2_m, bn2_v, bn);

    // 1) depthwise 1
    dwconv_kernel<<<BB * CC, 256>>>(x, dw1, t1);

    // 2) pointwise 1 + BN + ReLU (TF32 TC)
    gemm_tf32<false, 0><<<dim3(NN / 128, CC / 128, BB), 256>>>(
        pw1, t1, t2, CC, CC, NN, NN, 0, sBCN, sBCN, scale1, shift1, nullptr, 0, nullptr);

    // 3) depthwise 2
    dwconv_kernel<<<BB * CC, 256>>>(t2, dw2, t3);

    // 4) pointwise 2 + BN + residual x (TF32 TC)
    gemm_tf32<false, 1><<<dim3(NN / 128, CC / 128, BB), 256>>>(
        pw2, t3, xa, CC, CC, NN, NN, 0, sBCN, sBCN, scale2, shift2, x, sBCN, nullptr);

    // 5) q = wq @ xa + bq  (fp32, precision-sensitive for softmax)
    gemm_kernel<32, 64, 16, true, false, 2><<<dim3(NN / 64, 1, BB), 256>>>(
        wq, xa, q, CC, CC, NN, NN, 0, sBCN, sBQN, bq, nullptr, nullptr, 0, nullptr);

    // 6) k = wk @ xa + bk  (fp32)
    gemm_kernel<32, 64, 16, true, false, 2><<<dim3(NN / 64, 1, BB), 256>>>(
        wk, xa, k, CC, CC, NN, NN, 0, sBCN, sBQN, bk, nullptr, nullptr, 0, nullptr);

    // 7) v = wv @ xa + bv (TF32 TC)
    gemm_tf32<false, 2><<<dim3(NN / 128, CC / 128, BB), 256>>>(
        wv, xa, v, CC, CC, NN, NN, 0, sBCN, sBCN, bv, nullptr, nullptr, 0, nullptr);

    // 8) S[m][n] = sum_d q[d][m] k[d][n]  (fp32, feeds softmax)
    gemm_kernel<64, 64, 16, false, false, 3><<<dim3(NN / 64, NN / 64, BB), 256>>>(
        q, k, S, C8, NN, NN, NN, sBQN, sBQN, sBNN, nullptr, nullptr, nullptr, 0, nullptr);

    // 9) softmax over n (rows of S)
    softmax_kernel<<<BB * NN, 256>>>(S);

    // 10) O[c][m] = sum_n v[c][n] P[m][n] ; out = relu(gamma*O + xa)  (TF32 TC)
    gemm_tf32<true, 4><<<dim3(NN / 128, CC / 128, BB), 256>>>(
        v, S, out, NN, NN, NN, NN, sBCN, sBNN, sBCN, nullptr, nullptr, xa, sBCN, gamma);

    (void)in_sizes; (void)n_in; (void)out_size;
}

// round 9
// speedup vs baseline: 2.5446x; 1.0743x over previous
#include <cuda_runtime.h>
#include <stdint.h>
#include <math.h>

// Problem dims (fixed)
#define BB   64
#define CC   256
#define C8   32
#define HH   32
#define WW   32
#define NN   1024            // H*W
#define BCN  16777216        // B*C*N
#define BQN  2097152         // B*C8*N
#define BNN  67108864        // B*N*N

// ---------------- scratch (static device arrays; no runtime alloc) -------------
// __align__(256) is load-bearing: float4/float2 vector access on these.
__device__ __align__(256) float g_t1[BCN];
__device__ __align__(256) float g_t2[BCN];
__device__ __align__(256) float g_t3[BCN];
__device__ __align__(256) float g_xa[BCN];
__device__ __align__(256) float g_q[BQN];
__device__ __align__(256) float g_k[BQN];
__device__ __align__(256) float g_v[BCN];
__device__ __align__(256) float g_S[BNN];
__device__ __align__(256) float g_M[BB * NN];
__device__ __align__(256) float g_iL[BB * NN];
__device__ __align__(256) float g_bn[4 * CC];

// ---------------- BN affine precompute ----------------------------------------
__global__ void bnprep_kernel(const float* __restrict__ g1, const float* __restrict__ b1,
                              const float* __restrict__ m1, const float* __restrict__ v1,
                              const float* __restrict__ g2, const float* __restrict__ b2,
                              const float* __restrict__ m2, const float* __restrict__ v2,
                              float* __restrict__ bn) {
    int c = threadIdx.x;
    float s1 = g1[c] * rsqrtf(v1[c] + 1e-5f);
    float s2 = g2[c] * rsqrtf(v2[c] + 1e-5f);
    bn[c]          = s1;
    bn[CC + c]     = b1[c] - m1[c] * s1;
    bn[2 * CC + c] = s2;
    bn[3 * CC + c] = b2[c] - m2[c] * s2;
}

// ---------------- depthwise 3x3, SAME, stride 1: 4 pixels/thread ---------------
__global__ __launch_bounds__(256) void dwconv_kernel(const float* __restrict__ in,
                                                     const float* __restrict__ w9,
                                                     float* __restrict__ out) {
    __shared__ __align__(16) float s[34 * 34];
    int p = blockIdx.x;           // plane index = b*C + c
    int c = p & (CC - 1);
    const float* ip = in + (long)p * NN;
    float w[9];
#pragma unroll
    for (int j = 0; j < 9; j++) w[j] = w9[c * 9 + j];

    for (int idx = threadIdx.x; idx < 34 * 34; idx += 256) {
        int y = idx / 34 - 1, x = idx % 34 - 1;
        s[idx] = (y >= 0 && y < HH && x >= 0 && x < WW) ? ip[y * WW + x] : 0.0f;
    }
    __syncthreads();

    int oy = threadIdx.x >> 3;            // 0..31
    int ox = (threadIdx.x & 7) * 4;       // 0,4,...,28
    const float* base = s + oy * 34 + ox;
    float acc0 = 0.f, acc1 = 0.f, acc2 = 0.f, acc3 = 0.f;
#pragma unroll
    for (int dy = 0; dy < 3; dy++) {
        float r0 = base[dy * 34 + 0];
        float r1 = base[dy * 34 + 1];
        float r2 = base[dy * 34 + 2];
        float r3 = base[dy * 34 + 3];
        float r4 = base[dy * 34 + 4];
        float r5 = base[dy * 34 + 5];
        float w0 = w[dy * 3 + 0], w1 = w[dy * 3 + 1], w2 = w[dy * 3 + 2];
        acc0 = fmaf(r0, w0, fmaf(r1, w1, fmaf(r2, w2, acc0)));
        acc1 = fmaf(r1, w0, fmaf(r2, w1, fmaf(r3, w2, acc1)));
        acc2 = fmaf(r2, w0, fmaf(r3, w1, fmaf(r4, w2, acc2)));
        acc3 = fmaf(r3, w0, fmaf(r4, w1, fmaf(r5, w2, acc3)));
    }
    *(float4*)(out + (long)p * NN + oy * WW + ox) = make_float4(acc0, acc1, acc2, acc3);
}

// ---------------- fp32 tiled GEMM (precision-sensitive small GEMMs) -------------
template <int TM, int TN, int TK, bool ATR, bool BTR, int EPI>
__global__ __launch_bounds__(256) void gemm_kernel(
    const float* __restrict__ A, const float* __restrict__ B, float* __restrict__ Cm,
    int K, int lda, int ldb, int ldc,
    long sA, long sB, long sC,
    const float* __restrict__ scale, const float* __restrict__ shift,
    const float* __restrict__ res, long sRes,
    const float* __restrict__ gammaPtr) {
    constexpr int RM = TM / 16;
    constexpr int RN = TN / 16;
    __shared__ __align__(16) float As[TK][TM + 1];
    __shared__ __align__(16) float Bs[TK][TN + 1];

    int bz = blockIdx.z;
    const float* Ab = A + (long)bz * sA;
    const float* Bb = B + (long)bz * sB;
    int m0 = blockIdx.y * TM;
    int n0 = blockIdx.x * TN;
    int tid = threadIdx.x;
    int ty = tid >> 4, tx = tid & 15;

    float acc[RM][RN];
#pragma unroll
    for (int i = 0; i < RM; i++)
#pragma unroll
        for (int j = 0; j < RN; j++) acc[i][j] = 0.0f;

    for (int k0 = 0; k0 < K; k0 += TK) {
        if (ATR) {
            int k = tid & (TK - 1);
            int mrow = tid / TK;
#pragma unroll
            for (int r = 0; r < (TM * TK) / 256; r++) {
                int m = mrow + r * (256 / TK);
                As[k][m] = Ab[(long)(m0 + m) * lda + (k0 + k)];
            }
        } else {
#pragma unroll
            for (int r = 0; r < (TM * TK) / 256; r++) {
                int idx = tid + r * 256;
                int k = idx / TM, m = idx % TM;
                As[k][m] = Ab[(long)(k0 + k) * lda + (m0 + m)];
            }
        }
        if (BTR) {
            int k = tid & (TK - 1);
            int nrow = tid / TK;
#pragma unroll
            for (int r = 0; r < (TN * TK) / 256; r++) {
                int n = nrow + r * (256 / TK);
                Bs[k][n] = Bb[(long)(n0 + n) * ldb + (k0 + k)];
            }
        } else {
#pragma unroll
            for (int r = 0; r < (TN * TK) / 256; r++) {
                int idx = tid + r * 256;
                int k = idx / TN, n = idx % TN;
                Bs[k][n] = Bb[(long)(k0 + k) * ldb + (n0 + n)];
            }
        }
        __syncthreads();

#pragma unroll
        for (int k = 0; k < TK; k++) {
            float a[RM], bv[RN];
#pragma unroll
            for (int i = 0; i < RM; i++) a[i] = As[k][ty + 16 * i];
#pragma unroll
            for (int j = 0; j < RN; j++) bv[j] = Bs[k][tx + 16 * j];
#pragma unroll
            for (int i = 0; i < RM; i++)
#pragma unroll
                for (int j = 0; j < RN; j++) acc[i][j] = fmaf(a[i], bv[j], acc[i][j]);
        }
        __syncthreads();
    }

    float gm = 0.0f;
    if (EPI == 4) gm = gammaPtr[0];

#pragma unroll
    for (int i = 0; i < RM; i++) {
        int m = m0 + ty + 16 * i;
#pragma unroll
        for (int j = 0; j < RN; j++) {
            int n = n0 + tx + 16 * j;
            float val = acc[i][j];
            if (EPI == 0) {
                val = fmaxf(fmaf(val, scale[m], shift[m]), 0.0f);
            } else if (EPI == 1) {
                val = fmaf(val, scale[m], shift[m]) + res[(long)bz * sRes + (long)m * ldc + n];
            } else if (EPI == 2) {
                val = val + scale[m];
            } else if (EPI == 4) {
                val = fmaxf(fmaf(gm, val, res[(long)bz * sRes + (long)m * ldc + n]), 0.0f);
            }
            Cm[(long)bz * sC + (long)m * ldc + n] = val;
        }
    }
}

// ---------------- cp.async helpers ----------------------------------------------
__device__ __forceinline__ void cp16(uint32_t dst, const float* src) {
    asm volatile("cp.async.ca.shared.global [%0], [%1], 16;" :: "r"(dst), "l"(src));
}
__device__ __forceinline__ void cp_commit() {
    asm volatile("cp.async.commit_group;" ::: "memory");
}
template <int N>
__device__ __forceinline__ void cp_wait() {
    asm volatile("cp.async.wait_group %0;" :: "n"(N) : "memory");
}

// ---------------- TF32 tensor-core GEMM, cp.async 2-stage pipeline --------------
// C[b][m][n] = sum_k A[b][m][k]*B[k][n]  (A [M,K] k-contiguous, B [K,N] n-contig)
// EPI: 0 relu(acc*scale[m]+shift[m]); 1 acc*scale[m]+shift[m]+res; 2 acc+scale[m]
template <int EPI>
__global__ __launch_bounds__(256) void gemm_tf32(
    const float* __restrict__ A, const float* __restrict__ B, float* __restrict__ Cm,
    int K, int lda, int ldb, int ldc,
    long sA, long sB, long sC,
    const float* __restrict__ scale, const float* __restrict__ shift,
    const float* __restrict__ res, long sRes) {
    constexpr int BM = 128, BN = 128, BK = 16;
    constexpr int APAD = 20;
    __shared__ __align__(16) float As[2][BM][APAD];
    __shared__ __align__(16) float Bs[2][BK][BN + 8];

    int tid = threadIdx.x;
    int bz = blockIdx.z;
    const float* Ab = A + (long)bz * sA;
    const float* Bb = B + (long)bz * sB;
    int m0 = blockIdx.y * BM, n0 = blockIdx.x * BN;

    int a_row = tid >> 1, a_q = (tid & 1) * 2;
    int b_row = tid >> 4, b_q = (tid & 15) * 2;

    uint32_t asBase = (uint32_t)__cvta_generic_to_shared(&As[0][0][0]);
    uint32_t bsBase = (uint32_t)__cvta_generic_to_shared(&Bs[0][0][0]);

    auto prefetch = [&](int buf, int k0) {
#pragma unroll
        for (int j = 0; j < 2; j++) {
            int q = a_q + j;
            cp16(asBase + (((buf * BM + a_row) * APAD) + q * 4) * 4,
                 Ab + (long)(m0 + a_row) * lda + k0 + q * 4);
        }
#pragma unroll
        for (int j = 0; j < 2; j++) {
            int q = b_q + j;
            cp16(bsBase + (((buf * BK + b_row) * (BN + 8)) + q * 4) * 4,
                 Bb + (long)(k0 + b_row) * ldb + n0 + q * 4);
        }
        cp_commit();
    };

    int lane = tid & 31, warp = tid >> 5;
    int wm = (warp >> 2) * 64;
    int wn = (warp & 3) * 32;
    int gid = lane >> 2, tig = lane & 3;

    float acc[4][4][4];
#pragma unroll
    for (int i = 0; i < 4; i++)
#pragma unroll
        for (int j = 0; j < 4; j++)
#pragma unroll
            for (int e = 0; e < 4; e++) acc[i][j][e] = 0.0f;

    prefetch(0, 0);

    int nk = K / BK;
    for (int t = 0; t < nk; t++) {
        int cur = t & 1;
        if (t + 1 < nk) {
            prefetch(cur ^ 1, (t + 1) * BK);
            cp_wait<1>();
        } else {
            cp_wait<0>();
        }
        __syncthreads();

#pragma unroll
        for (int ks = 0; ks < 2; ks++) {
            int kb = ks * 8;
            unsigned af[4][4], bf[4][2];
#pragma unroll
            for (int mi = 0; mi < 4; mi++) {
                const float* ap = &As[cur][wm + 16 * mi + gid][kb + tig];
                af[mi][0] = __float_as_uint(ap[0]);
                af[mi][1] = __float_as_uint(ap[8 * APAD]);
                af[mi][2] = __float_as_uint(ap[4]);
                af[mi][3] = __float_as_uint(ap[8 * APAD + 4]);
            }
#pragma unroll
            for (int nj = 0; nj < 4; nj++) {
                int n = wn + 8 * nj + gid;
                bf[nj][0] = __float_as_uint(Bs[cur][kb + tig][n]);
                bf[nj][1] = __float_as_uint(Bs[cur][kb + 4 + tig][n]);
            }
#pragma unroll
            for (int mi = 0; mi < 4; mi++)
#pragma unroll
                for (int nj = 0; nj < 4; nj++) {
                    asm volatile(
                        "mma.sync.aligned.m16n8k8.row.col.f32.tf32.tf32.f32 "
                        "{%0,%1,%2,%3},{%4,%5,%6,%7},{%8,%9},{%0,%1,%2,%3};\n"
                        : "+f"(acc[mi][nj][0]), "+f"(acc[mi][nj][1]),
                          "+f"(acc[mi][nj][2]), "+f"(acc[mi][nj][3])
                        : "r"(af[mi][0]), "r"(af[mi][1]), "r"(af[mi][2]), "r"(af[mi][3]),
                          "r"(bf[nj][0]), "r"(bf[nj][1]));
                }
        }
        __syncthreads();
    }

    const float* resb = res ? res + (long)bz * sRes : nullptr;
    float* Cb = Cm + (long)bz * sC;

#pragma unroll
    for (int mi = 0; mi < 4; mi++) {
#pragma unroll
        for (int e2 = 0; e2 < 2; e2++) {
            int m = m0 + wm + 16 * mi + gid + 8 * e2;
            float sc = 0.0f, sh = 0.0f;
            if (EPI == 0 || EPI == 1) { sc = scale[m]; sh = shift[m]; }
            else if (EPI == 2) { sc = scale[m]; }
#pragma unroll
            for (int nj = 0; nj < 4; nj++) {
                int n = n0 + wn + 8 * nj + 2 * tig;
                float v0 = acc[mi][nj][2 * e2 + 0];
                float v1 = acc[mi][nj][2 * e2 + 1];
                if (EPI == 0) {
                    v0 = fmaxf(fmaf(v0, sc, sh), 0.0f);
                    v1 = fmaxf(fmaf(v1, sc, sh), 0.0f);
                } else if (EPI == 1) {
                    float2 r2 = *(const float2*)(resb + (long)m * ldc + n);
                    v0 = fmaf(v0, sc, sh) + r2.x;
                    v1 = fmaf(v1, sc, sh) + r2.y;
                } else if (EPI == 2) {
                    v0 += sc; v1 += sc;
                }
                *(float2*)(Cb + (long)m * ldc + n) = make_float2(v0, v1);
            }
        }
    }
}

// ---------------- row stats: M = rowmax(S), iL = 1/sum(exp(S-M)) ----------------
// one warp per row of S (1024 floats)
__global__ __launch_bounds__(256) void rowstat_kernel(const float* __restrict__ S,
                                                      float* __restrict__ M,
                                                      float* __restrict__ iL) {
    int row = blockIdx.x * 8 + (threadIdx.x >> 5);
    int lane = threadIdx.x & 31;
    const float4* p = (const float4*)(S + (long)row * NN);
    float4 v[8];
    float mx = -3.4e38f;
#pragma unroll
    for (int i = 0; i < 8; i++) {
        v[i] = p[lane + 32 * i];
        mx = fmaxf(mx, fmaxf(fmaxf(v[i].x, v[i].y), fmaxf(v[i].z, v[i].w)));
    }
#pragma unroll
    for (int o = 16; o > 0; o >>= 1)
        mx = fmaxf(mx, __shfl_xor_sync(0xffffffffu, mx, o));
    float sum = 0.0f;
#pragma unroll
    for (int i = 0; i < 8; i++) {
        sum += __expf(v[i].x - mx) + __expf(v[i].y - mx)
             + __expf(v[i].z - mx) + __expf(v[i].w - mx);
    }
#pragma unroll
    for (int o = 16; o > 0; o >>= 1)
        sum += __shfl_xor_sync(0xffffffffu, sum, o);
    if (lane == 0) {
        M[row]  = mx;
        iL[row] = 1.0f / sum;
    }
}

// ---------------- PV with fused softmax -----------------------------------------
// out[c,m] = relu( gamma * (sum_n v[c,n] * exp(S[m,n]-M[m])) * iL[m] + xa[c,m] )
// A = v [C,N] via cp.async; B = S rows (k-contiguous) via LDG + exp + STS.
__global__ __launch_bounds__(256) void gemm_pv(
    const float* __restrict__ V, const float* __restrict__ S,
    float* __restrict__ Cm,
    const float* __restrict__ Mrow, const float* __restrict__ iLrow,
    const float* __restrict__ res, const float* __restrict__ gammaPtr) {
    constexpr int BM = 128, BN = 128, BK = 16;
    constexpr int APAD = 20, BPAD = 20;
    __shared__ __align__(16) float As[2][BM][APAD];
    __shared__ __align__(16) float Bs[2][BN][BPAD];

    int tid = threadIdx.x;
    int bz = blockIdx.z;
    const float* Ab = V + (long)bz * ((long)CC * NN);
    const float* Sb = S + (long)bz * ((long)NN * NN);
    int m0 = blockIdx.y * BM, n0 = blockIdx.x * BN;

    int a_row = tid >> 1, a_q = (tid & 1) * 2;
    int b_row = tid >> 1, b_q = (tid & 1) * 2;   // thread's S row fixed: n0+b_row

    float mrow = Mrow[bz * NN + n0 + b_row];

    uint32_t asBase = (uint32_t)__cvta_generic_to_shared(&As[0][0][0]);

    auto prefetchA = [&](int buf, int k0) {
#pragma unroll
        for (int j = 0; j < 2; j++) {
            int q = a_q + j;
            cp16(asBase + (((buf * BM + a_row) * APAD) + q * 4) * 4,
                 Ab + (long)(m0 + a_row) * NN + k0 + q * 4);
        }
        cp_commit();
    };
    float4 braw[2];
    auto ldgB = [&](int k0) {
#pragma unroll
        for (int j = 0; j < 2; j++)
            braw[j] = *(const float4*)(Sb + (long)(n0 + b_row) * NN + k0 + (b_q + j) * 4);
    };
    auto stsB = [&](int buf) {
#pragma unroll
        for (int j = 0; j < 2; j++) {
            float4 e;
            e.x = __expf(braw[j].x - mrow);
            e.y = __expf(braw[j].y - mrow);
            e.z = __expf(braw[j].z - mrow);
            e.w = __expf(braw[j].w - mrow);
            *(float4*)&Bs[buf][b_row][(b_q + j) * 4] = e;
        }
    };

    int lane = tid & 31, warp = tid >> 5;
    int wm = (warp >> 2) * 64;
    int wn = (warp & 3) * 32;
    int gid = lane >> 2, tig = lane & 3;

    float acc[4][4][4];
#pragma unroll
    for (int i = 0; i < 4; i++)
#pragma unroll
        for (int j = 0; j < 4; j++)
#pragma unroll
            for (int e = 0; e < 4; e++) acc[i][j][e] = 0.0f;

    prefetchA(0, 0);
    ldgB(0);
    stsB(0);
    cp_wait<0>();
    __syncthreads();

    const int nk = NN / BK;   // 64
    for (int t = 0; t < nk; t++) {
        int cur = t & 1;
        bool more = (t + 1 < nk);
        if (more) {
            prefetchA(cur ^ 1, (t + 1) * BK);   // buf^1 readers finished at t-1 barrier
            ldgB((t + 1) * BK);
        }

#pragma unroll
        for (int ks = 0; ks < 2; ks++) {
            int kb = ks * 8;
            unsigned af[4][4], bf[4][2];
#pragma unroll
            for (int mi = 0; mi < 4; mi++) {
                const float* ap = &As[cur][wm + 16 * mi + gid][kb + tig];
                af[mi][0] = __float_as_uint(ap[0]);
                af[mi][1] = __float_as_uint(ap[8 * APAD]);
                af[mi][2] = __float_as_uint(ap[4]);
                af[mi][3] = __float_as_uint(ap[8 * APAD + 4]);
            }
#pragma unroll
            for (int nj = 0; nj < 4; nj++) {
                const float* bp = &Bs[cur][wn + 8 * nj + gid][kb + tig];
                bf[nj][0] = __float_as_uint(bp[0]);
                bf[nj][1] = __float_as_uint(bp[4]);
            }
#pragma unroll
            for (int mi = 0; mi < 4; mi++)
#pragma unroll
                for (int nj = 0; nj < 4; nj++) {
                    asm volatile(
                        "mma.sync.aligned.m16n8k8.row.col.f32.tf32.tf32.f32 "
                        "{%0,%1,%2,%3},{%4,%5,%6,%7},{%8,%9},{%0,%1,%2,%3};\n"
                        : "+f"(acc[mi][nj][0]), "+f"(acc[mi][nj][1]),
                          "+f"(acc[mi][nj][2]), "+f"(acc[mi][nj][3])
                        : "r"(af[mi][0]), "r"(af[mi][1]), "r"(af[mi][2]), "r"(af[mi][3]),
                          "r"(bf[nj][0]), "r"(bf[nj][1]));
                }
        }
        if (more) {
            stsB(cur ^ 1);   // buf^1 last read at iter t-1, fenced by t-1's barrier
            cp_wait<1>();
        } else {
            cp_wait<0>();
        }
        __syncthreads();     // stsB + A cp.async of t+1 visible; readers of cur done
    }

    float gm = gammaPtr[0];
    const float* resb = res + (long)bz * ((long)CC * NN);
    const float* ilb = iLrow + bz * NN;
    float* Cb = Cm + (long)bz * ((long)CC * NN);

#pragma unroll
    for (int mi = 0; mi < 4; mi++) {
#pragma unroll
        for (int e2 = 0; e2 < 2; e2++) {
            int m = m0 + wm + 16 * mi + gid + 8 * e2;
#pragma unroll
            for (int nj = 0; nj < 4; nj++) {
                int n = n0 + wn + 8 * nj + 2 * tig;
                float2 il = *(const float2*)(ilb + n);
                float2 r2 = *(const float2*)(resb + (long)m * NN + n);
                float v0 = fmaxf(fmaf(gm * il.x, acc[mi][nj][2 * e2 + 0], r2.x), 0.0f);
                float v1 = fmaxf(fmaf(gm * il.y, acc[mi][nj][2 * e2 + 1], r2.y), 0.0f);
                *(float2*)(Cb + (long)m * NN + n) = make_float2(v0, v1);
            }
        }
    }
}

// ---------------- launch ---------------------------------------------------------
extern "C" void kernel_launch(void* const* d_in, const int* in_sizes, int n_in,
                              void* d_out, int out_size) {
    const float* x     = (const float*)d_in[0];
    const float* dw1   = (const float*)d_in[1];
    const float* pw1   = (const float*)d_in[2];
    const float* bn1_g = (const float*)d_in[3];
    const float* bn1_b = (const float*)d_in[4];
    const float* bn1_m = (const float*)d_in[5];
    const float* bn1_v = (const float*)d_in[6];
    const float* dw2   = (const float*)d_in[7];
    const float* pw2   = (const float*)d_in[8];
    const float* bn2_g = (const float*)d_in[9];
    const float* bn2_b = (const float*)d_in[10];
    const float* bn2_m = (const float*)d_in[11];
    const float* bn2_v = (const float*)d_in[12];
    const float* wq    = (const float*)d_in[13];
    const float* bq    = (const float*)d_in[14];
    const float* wk    = (const float*)d_in[15];
    const float* bk    = (const float*)d_in[16];
    const float* wv    = (const float*)d_in[17];
    const float* bv    = (const float*)d_in[18];
    const float* gamma = (const float*)d_in[19];
    float* out = (float*)d_out;

    float *t1, *t2, *t3, *xa, *q, *k, *v, *S, *Mv, *iL, *bn;
    cudaGetSymbolAddress((void**)&t1, g_t1);
    cudaGetSymbolAddress((void**)&t2, g_t2);
    cudaGetSymbolAddress((void**)&t3, g_t3);
    cudaGetSymbolAddress((void**)&xa, g_xa);
    cudaGetSymbolAddress((void**)&q,  g_q);
    cudaGetSymbolAddress((void**)&k,  g_k);
    cudaGetSymbolAddress((void**)&v,  g_v);
    cudaGetSymbolAddress((void**)&S,  g_S);
    cudaGetSymbolAddress((void**)&Mv, g_M);
    cudaGetSymbolAddress((void**)&iL, g_iL);
    cudaGetSymbolAddress((void**)&bn, g_bn);
    const float* scale1 = bn;
    const float* shift1 = bn + CC;
    const float* scale2 = bn + 2 * CC;
    const float* shift2 = bn + 3 * CC;

    const long sBCN = (long)CC * NN;   // 262144
    const long sBQN = (long)C8 * NN;   // 32768
    const long sBNN = (long)NN * NN;   // 1048576

    // 0) BN affine precompute
    bnprep_kernel<<<1, CC>>>(bn1_g, bn1_b, bn1_m, bn1_v, bn2_g, bn2_b, bn2_m, bn2_v, bn);

    // 1) depthwise 1
    dwconv_kernel<<<BB * CC, 256>>>(x, dw1, t1);

    // 2) pointwise 1 + BN + ReLU (TF32 TC)
    gemm_tf32<0><<<dim3(NN / 128, CC / 128, BB), 256>>>(
        pw1, t1, t2, CC, CC, NN, NN, 0, sBCN, sBCN, scale1, shift1, nullptr, 0);

    // 3) depthwise 2
    dwconv_kernel<<<BB * CC, 256>>>(t2, dw2, t3);

    // 4) pointwise 2 + BN + residual x (TF32 TC)
    gemm_tf32<1><<<dim3(NN / 128, CC / 128, BB), 256>>>(
        pw2, t3, xa, CC, CC, NN, NN, 0, sBCN, sBCN, scale2, shift2, x, sBCN);

    // 5) q = wq @ xa + bq  (fp32, precision-sensitive for softmax)
    gemm_kernel<32, 64, 16, true, false, 2><<<dim3(NN / 64, 1, BB), 256>>>(
        wq, xa, q, CC, CC, NN, NN, 0, sBCN, sBQN, bq, nullptr, nullptr, 0, nullptr);

    // 6) k = wk @ xa + bk  (fp32)
    gemm_kernel<32, 64, 16, true, false, 2><<<dim3(NN / 64, 1, BB), 256>>>(
        wk, xa, k, CC, CC, NN, NN, 0, sBCN, sBQN, bk, nullptr, nullptr, 0, nullptr);

    // 7) v = wv @ xa + bv (TF32 TC)
    gemm_tf32<2><<<dim3(NN / 128, CC / 128, BB), 256>>>(
        wv, xa, v, CC, CC, NN, NN, 0, sBCN, sBCN, bv, nullptr, nullptr, 0);

    // 8) S[m][n] = sum_d q[d][m] k[d][n]  (fp32 logits, feeds softmax)
    gemm_kernel<64, 64, 16, false, false, 3><<<dim3(NN / 64, NN / 64, BB), 256>>>(
        q, k, S, C8, NN, NN, NN, sBQN, sBQN, sBNN, nullptr, nullptr, nullptr, 0, nullptr);

    // 9) row stats (replaces softmax pass)
    rowstat_kernel<<<BB * NN / 8, 256>>>(S, Mv, iL);

    // 10) PV with fused softmax: out = relu(gamma * (v @ exp(S-M)) * iL + xa)
    gemm_pv<<<dim3(NN / 128, CC / 128, BB), 256>>>(v, S, out, Mv, iL, xa, gamma);

    (void)in_sizes; (void)n_in; (void)out_size;
}

// round 12
// speedup vs baseline: 2.6971x; 1.0599x over previous
#include <cuda_runtime.h>
#include <stdint.h>
#include <math.h>

// Problem dims (fixed)
#define BB   64
#define CC   256
#define C8   32
#define HH   32
#define WW   32
#define NN   1024            // H*W
#define BCN  16777216        // B*C*N
#define BQN  2097152         // B*C8*N
#define BNN  67108864        // B*N*N (WHOLE S array; per-batch stride is NN*NN)
#define SM_SHIFT 32.0f       // global logit shift (cancels in softmax; overflow guard)

// ---------------- scratch (static device arrays; no runtime alloc) -------------
// __align__(256) is load-bearing: float4/float2 vector access on these.
__device__ __align__(256) float g_t1[BCN];
__device__ __align__(256) float g_t2[BCN];
__device__ __align__(256) float g_t3[BCN];
__device__ __align__(256) float g_xa[BCN];
__device__ __align__(256) float g_q[BQN];
__device__ __align__(256) float g_k[BQN];
__device__ __align__(256) float g_v[BCN];
__device__ __align__(256) float g_S[BNN];
__device__ __align__(256) float g_L[BB * NN];          // row sums of exp(S - SHIFT)
__device__ __align__(256) float g_wr[3 * CC * CC];     // RNA-rounded pw1|pw2|wv
__device__ __align__(256) float g_bn[4 * CC];

// round-to-nearest tf32 (value stays in fp32 layout, low 13 mantissa bits zero)
__device__ __forceinline__ float rnatf(float x) {
    unsigned r;
    asm("cvt.rna.tf32.f32 %0, %1;" : "=r"(r) : "f"(x));
    return __uint_as_float(r);
}

// ---------------- BN affine precompute ----------------------------------------
__global__ void bnprep_kernel(const float* __restrict__ g1, const float* __restrict__ b1,
                              const float* __restrict__ m1, const float* __restrict__ v1,
                              const float* __restrict__ g2, const float* __restrict__ b2,
                              const float* __restrict__ m2, const float* __restrict__ v2,
                              float* __restrict__ bn) {
    int c = threadIdx.x;
    float s1 = g1[c] * rsqrtf(v1[c] + 1e-5f);
    float s2 = g2[c] * rsqrtf(v2[c] + 1e-5f);
    bn[c]          = s1;
    bn[CC + c]     = b1[c] - m1[c] * s1;
    bn[2 * CC + c] = s2;
    bn[3 * CC + c] = b2[c] - m2[c] * s2;
}

// ---------------- round weights to tf32-rna once --------------------------------
__global__ void roundw_kernel(const float* __restrict__ pw1, const float* __restrict__ pw2,
                              const float* __restrict__ wv, float* __restrict__ wr) {
    int i = blockIdx.x * 256 + threadIdx.x;   // 0 .. 3*CC*CC-1
    const int W = CC * CC;
    float v;
    if (i < W)          v = pw1[i];
    else if (i < 2 * W) v = pw2[i - W];
    else                v = wv[i - 2 * W];
    wr[i] = rnatf(v);
}

// ---------------- zero L ---------------------------------------------------------
__global__ void zerol_kernel(float* __restrict__ L) {
    L[blockIdx.x * 256 + threadIdx.x] = 0.0f;
}

// ---------------- depthwise 3x3, SAME, stride 1: 4 pixels/thread ----------------
// Output rounded to tf32-rna: t1/t3 are consumed only as tf32 GEMM operands.
__global__ __launch_bounds__(256) void dwconv_kernel(const float* __restrict__ in,
                                                     const float* __restrict__ w9,
                                                     float* __restrict__ out) {
    __shared__ __align__(16) float s[34 * 34];
    int p = blockIdx.x;           // plane index = b*C + c
    int c = p & (CC - 1);
    const float* ip = in + (long)p * NN;
    float w[9];
#pragma unroll
    for (int j = 0; j < 9; j++) w[j] = w9[c * 9 + j];

    for (int idx = threadIdx.x; idx < 34 * 34; idx += 256) {
        int y = idx / 34 - 1, x = idx % 34 - 1;
        s[idx] = (y >= 0 && y < HH && x >= 0 && x < WW) ? ip[y * WW + x] : 0.0f;
    }
    __syncthreads();

    int oy = threadIdx.x >> 3;            // 0..31
    int ox = (threadIdx.x & 7) * 4;       // 0,4,...,28
    const float* base = s + oy * 34 + ox;
    float acc0 = 0.f, acc1 = 0.f, acc2 = 0.f, acc3 = 0.f;
#pragma unroll
    for (int dy = 0; dy < 3; dy++) {
        float r0 = base[dy * 34 + 0];
        float r1 = base[dy * 34 + 1];
        float r2 = base[dy * 34 + 2];
        float r3 = base[dy * 34 + 3];
        float r4 = base[dy * 34 + 4];
        float r5 = base[dy * 34 + 5];
        float w0 = w[dy * 3 + 0], w1 = w[dy * 3 + 1], w2 = w[dy * 3 + 2];
        acc0 = fmaf(r0, w0, fmaf(r1, w1, fmaf(r2, w2, acc0)));
        acc1 = fmaf(r1, w0, fmaf(r2, w1, fmaf(r3, w2, acc1)));
        acc2 = fmaf(r2, w0, fmaf(r3, w1, fmaf(r4, w2, acc2)));
        acc3 = fmaf(r3, w0, fmaf(r4, w1, fmaf(r5, w2, acc3)));
    }
    *(float4*)(out + (long)p * NN + oy * WW + ox) =
        make_float4(rnatf(acc0), rnatf(acc1), rnatf(acc2), rnatf(acc3));
}

// ---------------- fp32 tiled GEMM (q/k projections) ------------------------------
template <int TM, int TN, int TK, bool ATR, int EPI>
__global__ __launch_bounds__(256) void gemm_kernel(
    const float* __restrict__ A, const float* __restrict__ B, float* __restrict__ Cm,
    int K, int lda, int ldb, int ldc,
    long sA, long sB, long sC,
    const float* __restrict__ scale) {
    constexpr int RM = TM / 16;
    constexpr int RN = TN / 16;
    __shared__ __align__(16) float As[TK][TM + 1];
    __shared__ __align__(16) float Bs[TK][TN + 1];

    int bz = blockIdx.z;
    const float* Ab = A + (long)bz * sA;
    const float* Bb = B + (long)bz * sB;
    int m0 = blockIdx.y * TM;
    int n0 = blockIdx.x * TN;
    int tid = threadIdx.x;
    int ty = tid >> 4, tx = tid & 15;

    float acc[RM][RN];
#pragma unroll
    for (int i = 0; i < RM; i++)
#pragma unroll
        for (int j = 0; j < RN; j++) acc[i][j] = 0.0f;

    for (int k0 = 0; k0 < K; k0 += TK) {
        if (ATR) {
            int k = tid & (TK - 1);
            int mrow = tid / TK;
#pragma unroll
            for (int r = 0; r < (TM * TK) / 256; r++) {
                int m = mrow + r * (256 / TK);
                As[k][m] = Ab[(long)(m0 + m) * lda + (k0 + k)];
            }
        } else {
#pragma unroll
            for (int r = 0; r < (TM * TK) / 256; r++) {
                int idx = tid + r * 256;
                int k = idx / TM, m = idx % TM;
                As[k][m] = Ab[(long)(k0 + k) * lda + (m0 + m)];
            }
        }
#pragma unroll
        for (int r = 0; r < (TN * TK) / 256; r++) {
            int idx = tid + r * 256;
            int k = idx / TN, n = idx % TN;
            Bs[k][n] = Bb[(long)(k0 + k) * ldb + (n0 + n)];
        }
        __syncthreads();

#pragma unroll
        for (int k = 0; k < TK; k++) {
            float a[RM], bv[RN];
#pragma unroll
            for (int i = 0; i < RM; i++) a[i] = As[k][ty + 16 * i];
#pragma unroll
            for (int j = 0; j < RN; j++) bv[j] = Bs[k][tx + 16 * j];
#pragma unroll
            for (int i = 0; i < RM; i++)
#pragma unroll
                for (int j = 0; j < RN; j++) acc[i][j] = fmaf(a[i], bv[j], acc[i][j]);
        }
        __syncthreads();
    }

#pragma unroll
    for (int i = 0; i < RM; i++) {
        int m = m0 + ty + 16 * i;
#pragma unroll
        for (int j = 0; j < RN; j++) {
            int n = n0 + tx + 16 * j;
            float val = acc[i][j];
            if (EPI == 2) val = val + scale[m];    // bias
            Cm[(long)bz * sC + (long)m * ldc + n] = val;
        }
    }
}

// ---------------- cp.async helpers ----------------------------------------------
__device__ __forceinline__ void cp16(uint32_t dst, const float* src) {
    asm volatile("cp.async.ca.shared.global [%0], [%1], 16;" :: "r"(dst), "l"(src));
}
__device__ __forceinline__ void cp_commit() {
    asm volatile("cp.async.commit_group;" ::: "memory");
}
template <int N>
__device__ __forceinline__ void cp_wait() {
    asm volatile("cp.async.wait_group %0;" :: "n"(N) : "memory");
}

// ---------------- TF32 tensor-core GEMM, cp.async 2-stage pipeline --------------
// C[b][m][n] = sum_k A[b][m][k]*B[k][n]  (A [M,K] k-contiguous, B [K,N] n-contig)
// A is pre-rounded to tf32-rna; B (dwconv outputs) pre-rounded at producer.
// EPI: 0 relu(acc*scale[m]+shift[m]); 1 acc*scale[m]+shift[m]+res;
//      2 rnatf(acc+scale[m])   (v production — consumed only by PV tf32)
template <int EPI>
__global__ __launch_bounds__(256) void gemm_tf32(
    const float* __restrict__ A, const float* __restrict__ B, float* __restrict__ Cm,
    int K, int lda, int ldb, int ldc,
    long sA, long sB, long sC,
    const float* __restrict__ scale, const float* __restrict__ shift,
    const float* __restrict__ res, long sRes) {
    constexpr int BM = 128, BN = 128, BK = 16;
    constexpr int APAD = 20;
    __shared__ __align__(16) float As[2][BM][APAD];
    __shared__ __align__(16) float Bs[2][BK][BN + 8];

    int tid = threadIdx.x;
    int bz = blockIdx.z;
    const float* Ab = A + (long)bz * sA;
    const float* Bb = B + (long)bz * sB;
    int m0 = blockIdx.y * BM, n0 = blockIdx.x * BN;

    int a_row = tid >> 1, a_q = (tid & 1) * 2;
    int b_row = tid >> 4, b_q = (tid & 15) * 2;

    uint32_t asBase = (uint32_t)__cvta_generic_to_shared(&As[0][0][0]);
    uint32_t bsBase = (uint32_t)__cvta_generic_to_shared(&Bs[0][0][0]);

    auto prefetch = [&](int buf, int k0) {
#pragma unroll
        for (int j = 0; j < 2; j++) {
            int q = a_q + j;
            cp16(asBase + (((buf * BM + a_row) * APAD) + q * 4) * 4,
                 Ab + (long)(m0 + a_row) * lda + k0 + q * 4);
        }
#pragma unroll
        for (int j = 0; j < 2; j++) {
            int q = b_q + j;
            cp16(bsBase + (((buf * BK + b_row) * (BN + 8)) + q * 4) * 4,
                 Bb + (long)(k0 + b_row) * ldb + n0 + q * 4);
        }
        cp_commit();
    };

    int lane = tid & 31, warp = tid >> 5;
    int wm = (warp >> 2) * 64;
    int wn = (warp & 3) * 32;
    int gid = lane >> 2, tig = lane & 3;

    float acc[4][4][4];
#pragma unroll
    for (int i = 0; i < 4; i++)
#pragma unroll
        for (int j = 0; j < 4; j++)
#pragma unroll
            for (int e = 0; e < 4; e++) acc[i][j][e] = 0.0f;

    prefetch(0, 0);

    int nk = K / BK;
    for (int t = 0; t < nk; t++) {
        int cur = t & 1;
        if (t + 1 < nk) {
            prefetch(cur ^ 1, (t + 1) * BK);
            cp_wait<1>();     // guarantees group for tile t complete
        } else {
            cp_wait<0>();
        }
        __syncthreads();

#pragma unroll
        for (int ks = 0; ks < 2; ks++) {
            int kb = ks * 8;
            unsigned af[4][4], bf[4][2];
#pragma unroll
            for (int mi = 0; mi < 4; mi++) {
                const float* ap = &As[cur][wm + 16 * mi + gid][kb + tig];
                af[mi][0] = __float_as_uint(ap[0]);
                af[mi][1] = __float_as_uint(ap[8 * APAD]);
                af[mi][2] = __float_as_uint(ap[4]);
                af[mi][3] = __float_as_uint(ap[8 * APAD + 4]);
            }
#pragma unroll
            for (int nj = 0; nj < 4; nj++) {
                int n = wn + 8 * nj + gid;
                bf[nj][0] = __float_as_uint(Bs[cur][kb + tig][n]);
                bf[nj][1] = __float_as_uint(Bs[cur][kb + 4 + tig][n]);
            }
#pragma unroll
            for (int mi = 0; mi < 4; mi++)
#pragma unroll
                for (int nj = 0; nj < 4; nj++) {
                    asm volatile(
                        "mma.sync.aligned.m16n8k8.row.col.f32.tf32.tf32.f32 "
                        "{%0,%1,%2,%3},{%4,%5,%6,%7},{%8,%9},{%0,%1,%2,%3};\n"
                        : "+f"(acc[mi][nj][0]), "+f"(acc[mi][nj][1]),
                          "+f"(acc[mi][nj][2]), "+f"(acc[mi][nj][3])
                        : "r"(af[mi][0]), "r"(af[mi][1]), "r"(af[mi][2]), "r"(af[mi][3]),
                          "r"(bf[nj][0]), "r"(bf[nj][1]));
                }
        }
        __syncthreads();
    }

    const float* resb = res ? res + (long)bz * sRes : nullptr;
    float* Cb = Cm + (long)bz * sC;

#pragma unroll
    for (int mi = 0; mi < 4; mi++) {
#pragma unroll
        for (int e2 = 0; e2 < 2; e2++) {
            int m = m0 + wm + 16 * mi + gid + 8 * e2;
            float sc = 0.0f, sh = 0.0f;
            if (EPI == 0 || EPI == 1) { sc = scale[m]; sh = shift[m]; }
            else if (EPI == 2) { sc = scale[m]; }
#pragma unroll
            for (int nj = 0; nj < 4; nj++) {
                int n = n0 + wn + 8 * nj + 2 * tig;
                float v0 = acc[mi][nj][2 * e2 + 0];
                float v1 = acc[mi][nj][2 * e2 + 1];
                if (EPI == 0) {
                    v0 = fmaxf(fmaf(v0, sc, sh), 0.0f);
                    v1 = fmaxf(fmaf(v1, sc, sh), 0.0f);
                } else if (EPI == 1) {
                    float2 r2 = *(const float2*)(resb + (long)m * ldc + n);
                    v0 = fmaf(v0, sc, sh) + r2.x;
                    v1 = fmaf(v1, sc, sh) + r2.y;
                } else if (EPI == 2) {
                    v0 = rnatf(v0 + sc);
                    v1 = rnatf(v1 + sc);
                }
                *(float2*)(Cb + (long)m * ldc + n) = make_float2(v0, v1);
            }
        }
    }
}

// ---------------- QK: S = q^T k (fp32) + fused exp-rowsum into L ----------------
// q,k stored [C8=32, NN] per batch; S[m][n] = sum_d q[d][m] k[d][n].
// Epilogue: L[m] += sum_n rnatf(exp(S[m][n]-SHIFT)) (atomic over n-tiles).
// Global SHIFT cancels exactly in softmax; rna-rounded exp matches what PV feeds
// the tensor cores, so numerator/denominator are consistent.
__global__ __launch_bounds__(256, 2) void qk_kernel(
    const float* __restrict__ q, const float* __restrict__ k,
    float* __restrict__ S, float* __restrict__ L) {
    __shared__ float Qs[32][129];
    __shared__ float Ks[32][129];
    int tid = threadIdx.x;
    int bz = blockIdx.z;
    const float* qb = q + (long)bz * (C8 * NN);
    const float* kb = k + (long)bz * (C8 * NN);
    int m0 = blockIdx.y * 128, n0 = blockIdx.x * 128;

#pragma unroll
    for (int r = 0; r < 16; r++) {
        int idx = tid + r * 256;
        int kk = idx >> 7, mm = idx & 127;
        Qs[kk][mm] = qb[kk * NN + m0 + mm];
        Ks[kk][mm] = kb[kk * NN + n0 + mm];
    }
    __syncthreads();

    int ty = tid >> 4, tx = tid & 15;
    float acc[8][8];
#pragma unroll
    for (int i = 0; i < 8; i++)
#pragma unroll
        for (int j = 0; j < 8; j++) acc[i][j] = 0.0f;

#pragma unroll
    for (int kk = 0; kk < 32; kk++) {
        float a[8], b[8];
#pragma unroll
        for (int i = 0; i < 8; i++) a[i] = Qs[kk][ty + 16 * i];
#pragma unroll
        for (int j = 0; j < 8; j++) b[j] = Ks[kk][tx + 16 * j];
#pragma unroll
        for (int i = 0; i < 8; i++)
#pragma unroll
            for (int j = 0; j < 8; j++) acc[i][j] = fmaf(a[i], b[j], acc[i][j]);
    }

    float* Sb = S + (long)bz * ((long)NN * NN);   // per-batch stride NN*NN (NOT BNN!)
    float* Lb = L + bz * NN;
#pragma unroll
    for (int i = 0; i < 8; i++) {
        int m = m0 + ty + 16 * i;
        float rp = 0.0f;
#pragma unroll
        for (int j = 0; j < 8; j++) {
            int n = n0 + tx + 16 * j;
            float val = acc[i][j];
            Sb[(long)m * NN + n] = val;
            rp += rnatf(__expf(val - SM_SHIFT));
        }
        // reduce over tx (16 lanes per m within each half-warp)
#pragma unroll
        for (int o = 8; o > 0; o >>= 1)
            rp += __shfl_xor_sync(0xffffffffu, rp, o);
        if (tx == 0) atomicAdd(&Lb[m], rp);
    }
}

// ---------------- PV with fused softmax -----------------------------------------
// out[c,m] = relu( gamma * (sum_n v[c,n] * exp(S[m,n]-SHIFT)) / L[m] + xa[c,m] )
// A = v (tf32-rounded) via cp.async; B = exp(S-SHIFT) via LDG + exp + rna + STS.
__global__ __launch_bounds__(256) void gemm_pv(
    const float* __restrict__ V, const float* __restrict__ S,
    float* __restrict__ Cm,
    const float* __restrict__ Lrow,
    const float* __restrict__ res, const float* __restrict__ gammaPtr) {
    constexpr int BM = 128, BN = 128, BK = 16;
    constexpr int APAD = 20, BPAD = 20;
    __shared__ __align__(16) float As[2][BM][APAD];
    __shared__ __align__(16) float Bs[2][BN][BPAD];

    int tid = threadIdx.x;
    int bz = blockIdx.z;
    const float* Ab = V + (long)bz * ((long)CC * NN);
    const float* Sb = S + (long)bz * ((long)NN * NN);
    int m0 = blockIdx.y * BM, n0 = blockIdx.x * BN;

    int a_row = tid >> 1, a_q = (tid & 1) * 2;
    int b_row = tid >> 1, b_q = (tid & 1) * 2;   // thread's S row fixed: n0+b_row

    uint32_t asBase = (uint32_t)__cvta_generic_to_shared(&As[0][0][0]);

    auto prefetchA = [&](int buf, int k0) {
#pragma unroll
        for (int j = 0; j < 2; j++) {
            int q = a_q + j;
            cp16(asBase + (((buf * BM + a_row) * APAD) + q * 4) * 4,
                 Ab + (long)(m0 + a_row) * NN + k0 + q * 4);
        }
        cp_commit();
    };
    float4 braw[2];
    auto ldgB = [&](int k0) {
#pragma unroll
        for (int j = 0; j < 2; j++)
            braw[j] = *(const float4*)(Sb + (long)(n0 + b_row) * NN + k0 + (b_q + j) * 4);
    };
    auto stsB = [&](int buf) {
#pragma unroll
        for (int j = 0; j < 2; j++) {
            float4 e;
            e.x = rnatf(__expf(braw[j].x - SM_SHIFT));
            e.y = rnatf(__expf(braw[j].y - SM_SHIFT));
            e.z = rnatf(__expf(braw[j].z - SM_SHIFT));
            e.w = rnatf(__expf(braw[j].w - SM_SHIFT));
            *(float4*)&Bs[buf][b_row][(b_q + j) * 4] = e;
        }
    };

    int lane = tid & 31, warp = tid >> 5;
    int wm = (warp >> 2) * 64;
    int wn = (warp & 3) * 32;
    int gid = lane >> 2, tig = lane & 3;

    float acc[4][4][4];
#pragma unroll
    for (int i = 0; i < 4; i++)
#pragma unroll
        for (int j = 0; j < 4; j++)
#pragma unroll
            for (int e = 0; e < 4; e++) acc[i][j][e] = 0.0f;

    prefetchA(0, 0);
    ldgB(0);
    stsB(0);
    cp_wait<0>();
    __syncthreads();

    const int nk = NN / BK;   // 64
    for (int t = 0; t < nk; t++) {
        int cur = t & 1;
        bool more = (t + 1 < nk);
        if (more) {
            prefetchA(cur ^ 1, (t + 1) * BK);   // buf^1 readers finished at t-1 barrier
            ldgB((t + 1) * BK);
            cp_wait<1>();    // tile t's A group complete before mma reads it
        } else {
            cp_wait<0>();
        }

#pragma unroll
        for (int ks = 0; ks < 2; ks++) {
            int kb = ks * 8;
            unsigned af[4][4], bf[4][2];
#pragma unroll
            for (int mi = 0; mi < 4; mi++) {
                const float* ap = &As[cur][wm + 16 * mi + gid][kb + tig];
                af[mi][0] = __float_as_uint(ap[0]);
                af[mi][1] = __float_as_uint(ap[8 * APAD]);
                af[mi][2] = __float_as_uint(ap[4]);
                af[mi][3] = __float_as_uint(ap[8 * APAD + 4]);
            }
#pragma unroll
            for (int nj = 0; nj < 4; nj++) {
                const float* bp = &Bs[cur][wn + 8 * nj + gid][kb + tig];
                bf[nj][0] = __float_as_uint(bp[0]);
                bf[nj][1] = __float_as_uint(bp[4]);
            }
#pragma unroll
            for (int mi = 0; mi < 4; mi++)
#pragma unroll
                for (int nj = 0; nj < 4; nj++) {
                    asm volatile(
                        "mma.sync.aligned.m16n8k8.row.col.f32.tf32.tf32.f32 "
                        "{%0,%1,%2,%3},{%4,%5,%6,%7},{%8,%9},{%0,%1,%2,%3};\n"
                        : "+f"(acc[mi][nj][0]), "+f"(acc[mi][nj][1]),
                          "+f"(acc[mi][nj][2]), "+f"(acc[mi][nj][3])
                        : "r"(af[mi][0]), "r"(af[mi][1]), "r"(af[mi][2]), "r"(af[mi][3]),
                          "r"(bf[nj][0]), "r"(bf[nj][1]));
                }
        }
        if (more) stsB(cur ^ 1);   // buf^1 last read at iter t-1, fenced by t-1's barrier
        __syncthreads();           // stsB visible; readers of cur done before reuse
    }

    float gm = gammaPtr[0];
    const float* resb = res + (long)bz * ((long)CC * NN);
    const float* lb = Lrow + bz * NN;
    float* Cb = Cm + (long)bz * ((long)CC * NN);

#pragma unroll
    for (int mi = 0; mi < 4; mi++) {
#pragma unroll
        for (int e2 = 0; e2 < 2; e2++) {
            int m = m0 + wm + 16 * mi + gid + 8 * e2;
#pragma unroll
            for (int nj = 0; nj < 4; nj++) {
                int n = n0 + wn + 8 * nj + 2 * tig;
                float2 l2 = *(const float2*)(lb + n);
                float2 r2 = *(const float2*)(resb + (long)m * NN + n);
                float v0 = fmaxf(fmaf(gm / l2.x, acc[mi][nj][2 * e2 + 0], r2.x), 0.0f);
                float v1 = fmaxf(fmaf(gm / l2.y, acc[mi][nj][2 * e2 + 1], r2.y), 0.0f);
                *(float2*)(Cb + (long)m * NN + n) = make_float2(v0, v1);
            }
        }
    }
}

// ---------------- launch ---------------------------------------------------------
extern "C" void kernel_launch(void* const* d_in, const int* in_sizes, int n_in,
                              void* d_out, int out_size) {
    const float* x     = (const float*)d_in[0];
    const float* dw1   = (const float*)d_in[1];
    const float* pw1   = (const float*)d_in[2];
    const float* bn1_g = (const float*)d_in[3];
    const float* bn1_b = (const float*)d_in[4];
    const float* bn1_m = (const float*)d_in[5];
    const float* bn1_v = (const float*)d_in[6];
    const float* dw2   = (const float*)d_in[7];
    const float* pw2   = (const float*)d_in[8];
    const float* bn2_g = (const float*)d_in[9];
    const float* bn2_b = (const float*)d_in[10];
    const float* bn2_m = (const float*)d_in[11];
    const float* bn2_v = (const float*)d_in[12];
    const float* wq    = (const float*)d_in[13];
    const float* bq    = (const float*)d_in[14];
    const float* wk    = (const float*)d_in[15];
    const float* bk    = (const float*)d_in[16];
    const float* wv    = (const float*)d_in[17];
    const float* bv    = (const float*)d_in[18];
    const float* gamma = (const float*)d_in[19];
    float* out = (float*)d_out;

    float *t1, *t2, *t3, *xa, *q, *k, *v, *S, *L, *wr, *bn;
    cudaGetSymbolAddress((void**)&t1, g_t1);
    cudaGetSymbolAddress((void**)&t2, g_t2);
    cudaGetSymbolAddress((void**)&t3, g_t3);
    cudaGetSymbolAddress((void**)&xa, g_xa);
    cudaGetSymbolAddress((void**)&q,  g_q);
    cudaGetSymbolAddress((void**)&k,  g_k);
    cudaGetSymbolAddress((void**)&v,  g_v);
    cudaGetSymbolAddress((void**)&S,  g_S);
    cudaGetSymbolAddress((void**)&L,  g_L);
    cudaGetSymbolAddress((void**)&wr, g_wr);
    cudaGetSymbolAddress((void**)&bn, g_bn);
    const float* scale1 = bn;
    const float* shift1 = bn + CC;
    const float* scale2 = bn + 2 * CC;
    const float* shift2 = bn + 3 * CC;
    const float* pw1r = wr;
    const float* pw2r = wr + CC * CC;
    const float* wvr  = wr + 2 * CC * CC;

    const long sBCN = (long)CC * NN;   // 262144
    const long sBQN = (long)C8 * NN;   // 32768

    // 0) BN affine precompute + weight rounding + L zeroing
    bnprep_kernel<<<1, CC>>>(bn1_g, bn1_b, bn1_m, bn1_v, bn2_g, bn2_b, bn2_m, bn2_v, bn);
    roundw_kernel<<<3 * CC * CC / 256, 256>>>(pw1, pw2, wv, wr);
    zerol_kernel<<<BB * NN / 256, 256>>>(L);

    // 1) depthwise 1 (output tf32-rna rounded)
    dwconv_kernel<<<BB * CC, 256>>>(x, dw1, t1);

    // 2) pointwise 1 + BN + ReLU (TF32 TC, both operands rna)
    gemm_tf32<0><<<dim3(NN / 128, CC / 128, BB), 256>>>(
        pw1r, t1, t2, CC, CC, NN, NN, 0, sBCN, sBCN, scale1, shift1, nullptr, 0);

    // 3) depthwise 2 (output tf32-rna rounded)
    dwconv_kernel<<<BB * CC, 256>>>(t2, dw2, t3);

    // 4) pointwise 2 + BN + residual x (TF32 TC)
    gemm_tf32<1><<<dim3(NN / 128, CC / 128, BB), 256>>>(
        pw2r, t3, xa, CC, CC, NN, NN, 0, sBCN, sBCN, scale2, shift2, x, sBCN);

    // 5) q = wq @ xa + bq  (fp32)
    gemm_kernel<32, 64, 16, true, 2><<<dim3(NN / 64, 1, BB), 256>>>(
        wq, xa, q, CC, CC, NN, NN, 0, sBCN, sBQN, bq);

    // 6) k = wk @ xa + bk  (fp32)
    gemm_kernel<32, 64, 16, true, 2><<<dim3(NN / 64, 1, BB), 256>>>(
        wk, xa, k, CC, CC, NN, NN, 0, sBCN, sBQN, bk);

    // 7) v = wv @ xa + bv (TF32 TC, output rna-rounded for PV)
    gemm_tf32<2><<<dim3(NN / 128, CC / 128, BB), 256>>>(
        wvr, xa, v, CC, CC, NN, NN, 0, sBCN, sBCN, bv, nullptr, nullptr, 0);

    // 8) S = q^T k (fp32) + fused exp-rowsum -> L
    qk_kernel<<<dim3(NN / 128, NN / 128, BB), 256>>>(q, k, S, L);

    // 9) PV with fused softmax: out = relu(gamma * (v @ exp(S-SHIFT)) / L + xa)
    gemm_pv<<<dim3(NN / 128, CC / 128, BB), 256>>>(v, S, out, L, xa, gamma);

    (void)in_sizes; (void)n_in; (void)out_size;
}

// round 13
// speedup vs baseline: 2.9557x; 1.0959x over previous
#include <cuda_runtime.h>
#include <stdint.h>
#include <math.h>

// Problem dims (fixed)
#define BB   64
#define CC   256
#define C8   32
#define HH   32
#define WW   32
#define NN   1024            // H*W
#define BCN  16777216        // B*C*N
#define BQN  2097152         // B*C8*N
#define BNN  67108864        // B*N*N (WHOLE S array; per-batch stride is NN*NN)
#define SM_SHIFT 32.0f       // global logit shift (cancels in softmax; overflow guard)

// ---------------- scratch (static device arrays; no runtime alloc) -------------
// __align__(256) is load-bearing: float4/float2 vector access on these.
__device__ __align__(256) float g_t1[BCN];
__device__ __align__(256) float g_t2[BCN];
__device__ __align__(256) float g_t3[BCN];
__device__ __align__(256) float g_xa[BCN];
__device__ __align__(256) float g_q[BQN];
__device__ __align__(256) float g_k[BQN];
__device__ __align__(256) float g_v[BCN];
__device__ __align__(256) float g_S[BNN];
__device__ __align__(256) float g_L[BB * NN];          // row sums of exp(S - SHIFT)
__device__ __align__(256) float g_wr[3 * CC * CC];     // RNA-rounded pw1|pw2|wv
__device__ __align__(256) float g_bn[4 * CC];

// round-to-nearest tf32 (value stays in fp32 layout, low 13 mantissa bits zero)
__device__ __forceinline__ float rnatf(float x) {
    unsigned r;
    asm("cvt.rna.tf32.f32 %0, %1;" : "=r"(r) : "f"(x));
    return __uint_as_float(r);
}

// ---------------- BN affine precompute ----------------------------------------
__global__ void bnprep_kernel(const float* __restrict__ g1, const float* __restrict__ b1,
                              const float* __restrict__ m1, const float* __restrict__ v1,
                              const float* __restrict__ g2, const float* __restrict__ b2,
                              const float* __restrict__ m2, const float* __restrict__ v2,
                              float* __restrict__ bn) {
    int c = threadIdx.x;
    float s1 = g1[c] * rsqrtf(v1[c] + 1e-5f);
    float s2 = g2[c] * rsqrtf(v2[c] + 1e-5f);
    bn[c]          = s1;
    bn[CC + c]     = b1[c] - m1[c] * s1;
    bn[2 * CC + c] = s2;
    bn[3 * CC + c] = b2[c] - m2[c] * s2;
}

// ---------------- round weights to tf32-rna once --------------------------------
__global__ void roundw_kernel(const float* __restrict__ pw1, const float* __restrict__ pw2,
                              const float* __restrict__ wv, float* __restrict__ wr) {
    int i = blockIdx.x * 256 + threadIdx.x;   // 0 .. 3*CC*CC-1
    const int W = CC * CC;
    float v;
    if (i < W)          v = pw1[i];
    else if (i < 2 * W) v = pw2[i - W];
    else                v = wv[i - 2 * W];
    wr[i] = rnatf(v);
}

// ---------------- zero L ---------------------------------------------------------
__global__ void zerol_kernel(float* __restrict__ L) {
    L[blockIdx.x * 256 + threadIdx.x] = 0.0f;
}

// ---------------- depthwise 3x3, SAME, stride 1: 4 pixels/thread ----------------
__global__ __launch_bounds__(256) void dwconv_kernel(const float* __restrict__ in,
                                                     const float* __restrict__ w9,
                                                     float* __restrict__ out) {
    __shared__ __align__(16) float s[34 * 34];
    int p = blockIdx.x;           // plane index = b*C + c
    int c = p & (CC - 1);
    const float* ip = in + (long)p * NN;
    float w[9];
#pragma unroll
    for (int j = 0; j < 9; j++) w[j] = w9[c * 9 + j];

    for (int idx = threadIdx.x; idx < 34 * 34; idx += 256) {
        int y = idx / 34 - 1, x = idx % 34 - 1;
        s[idx] = (y >= 0 && y < HH && x >= 0 && x < WW) ? ip[y * WW + x] : 0.0f;
    }
    __syncthreads();

    int oy = threadIdx.x >> 3;            // 0..31
    int ox = (threadIdx.x & 7) * 4;       // 0,4,...,28
    const float* base = s + oy * 34 + ox;
    float acc0 = 0.f, acc1 = 0.f, acc2 = 0.f, acc3 = 0.f;
#pragma unroll
    for (int dy = 0; dy < 3; dy++) {
        float r0 = base[dy * 34 + 0];
        float r1 = base[dy * 34 + 1];
        float r2 = base[dy * 34 + 2];
        float r3 = base[dy * 34 + 3];
        float r4 = base[dy * 34 + 4];
        float r5 = base[dy * 34 + 5];
        float w0 = w[dy * 3 + 0], w1 = w[dy * 3 + 1], w2 = w[dy * 3 + 2];
        acc0 = fmaf(r0, w0, fmaf(r1, w1, fmaf(r2, w2, acc0)));
        acc1 = fmaf(r1, w0, fmaf(r2, w1, fmaf(r3, w2, acc1)));
        acc2 = fmaf(r2, w0, fmaf(r3, w1, fmaf(r4, w2, acc2)));
        acc3 = fmaf(r3, w0, fmaf(r4, w1, fmaf(r5, w2, acc3)));
    }
    *(float4*)(out + (long)p * NN + oy * WW + ox) =
        make_float4(rnatf(acc0), rnatf(acc1), rnatf(acc2), rnatf(acc3));
}

// ---------------- fused q/k projection (fp32 math, rna-rounded output) ----------
// rows 0-31 of the 64-row A tile are wq, rows 32-63 are wk. Reads xa ONCE.
__global__ __launch_bounds__(256) void qkproj_kernel(
    const float* __restrict__ wq, const float* __restrict__ bq,
    const float* __restrict__ wk, const float* __restrict__ bk,
    const float* __restrict__ xa, float* __restrict__ q, float* __restrict__ k) {
    __shared__ __align__(16) float As[16][65];
    __shared__ __align__(16) float Bs[16][65];

    int bz = blockIdx.z;
    const float* xab = xa + (long)bz * ((long)CC * NN);
    int n0 = blockIdx.x * 64;
    int tid = threadIdx.x;
    int ty = tid >> 4, tx = tid & 15;

    float acc[4][4];
#pragma unroll
    for (int i = 0; i < 4; i++)
#pragma unroll
        for (int j = 0; j < 4; j++) acc[i][j] = 0.0f;

    int kk = tid & 15, mrow = tid >> 4;
    for (int k0 = 0; k0 < CC; k0 += 16) {
#pragma unroll
        for (int r = 0; r < 4; r++) {
            int m = mrow + r * 16;
            const float* wrow = (m < 32) ? (wq + m * CC) : (wk + (m - 32) * CC);
            As[kk][m] = wrow[k0 + kk];
        }
#pragma unroll
        for (int r = 0; r < 4; r++) {
            int idx = tid + r * 256;
            int kb2 = idx >> 6, nn = idx & 63;
            Bs[kb2][nn] = xab[(long)(k0 + kb2) * NN + n0 + nn];
        }
        __syncthreads();

#pragma unroll
        for (int kc = 0; kc < 16; kc++) {
            float a[4], b[4];
#pragma unroll
            for (int i = 0; i < 4; i++) a[i] = As[kc][ty + 16 * i];
#pragma unroll
            for (int j = 0; j < 4; j++) b[j] = Bs[kc][tx + 16 * j];
#pragma unroll
            for (int i = 0; i < 4; i++)
#pragma unroll
                for (int j = 0; j < 4; j++) acc[i][j] = fmaf(a[i], b[j], acc[i][j]);
        }
        __syncthreads();
    }

    float* qb = q + (long)bz * (C8 * NN);
    float* kb = k + (long)bz * (C8 * NN);
#pragma unroll
    for (int i = 0; i < 4; i++) {
        int m = ty + 16 * i;
        float bias = (m < 32) ? bq[m] : bk[m - 32];
        float* dst = (m < 32) ? (qb + (long)m * NN) : (kb + (long)(m - 32) * NN);
#pragma unroll
        for (int j = 0; j < 4; j++) {
            int n = n0 + tx + 16 * j;
            dst[n] = rnatf(acc[i][j] + bias);
        }
    }
}

// ---------------- cp.async helpers ----------------------------------------------
__device__ __forceinline__ void cp16(uint32_t dst, const float* src) {
    asm volatile("cp.async.ca.shared.global [%0], [%1], 16;" :: "r"(dst), "l"(src));
}
__device__ __forceinline__ void cp_commit() {
    asm volatile("cp.async.commit_group;" ::: "memory");
}
template <int N>
__device__ __forceinline__ void cp_wait() {
    asm volatile("cp.async.wait_group %0;" :: "n"(N) : "memory");
}

// ---------------- TF32 tensor-core GEMM, cp.async 2-stage pipeline --------------
// C[b][m][n] = sum_k A[b][m][k]*B[k][n]  (A [M,K] k-contiguous, B [K,N] n-contig)
// EPI: 0 relu(acc*scale[m]+shift[m]); 1 acc*scale[m]+shift[m]+res;
//      2 rnatf(acc+scale[m])   (v production — consumed only by PV tf32)
template <int EPI>
__global__ __launch_bounds__(256) void gemm_tf32(
    const float* __restrict__ A, const float* __restrict__ B, float* __restrict__ Cm,
    int K, int lda, int ldb, int ldc,
    long sA, long sB, long sC,
    const float* __restrict__ scale, const float* __restrict__ shift,
    const float* __restrict__ res, long sRes) {
    constexpr int BM = 128, BN = 128, BK = 16;
    constexpr int APAD = 20;
    __shared__ __align__(16) float As[2][BM][APAD];
    __shared__ __align__(16) float Bs[2][BK][BN + 8];

    int tid = threadIdx.x;
    int bz = blockIdx.z;
    const float* Ab = A + (long)bz * sA;
    const float* Bb = B + (long)bz * sB;
    int m0 = blockIdx.y * BM, n0 = blockIdx.x * BN;

    int a_row = tid >> 1, a_q = (tid & 1) * 2;
    int b_row = tid >> 4, b_q = (tid & 15) * 2;

    uint32_t asBase = (uint32_t)__cvta_generic_to_shared(&As[0][0][0]);
    uint32_t bsBase = (uint32_t)__cvta_generic_to_shared(&Bs[0][0][0]);

    auto prefetch = [&](int buf, int k0) {
#pragma unroll
        for (int j = 0; j < 2; j++) {
            int q = a_q + j;
            cp16(asBase + (((buf * BM + a_row) * APAD) + q * 4) * 4,
                 Ab + (long)(m0 + a_row) * lda + k0 + q * 4);
        }
#pragma unroll
        for (int j = 0; j < 2; j++) {
            int q = b_q + j;
            cp16(bsBase + (((buf * BK + b_row) * (BN + 8)) + q * 4) * 4,
                 Bb + (long)(k0 + b_row) * ldb + n0 + q * 4);
        }
        cp_commit();
    };

    int lane = tid & 31, warp = tid >> 5;
    int wm = (warp >> 2) * 64;
    int wn = (warp & 3) * 32;
    int gid = lane >> 2, tig = lane & 3;

    float acc[4][4][4];
#pragma unroll
    for (int i = 0; i < 4; i++)
#pragma unroll
        for (int j = 0; j < 4; j++)
#pragma unroll
            for (int e = 0; e < 4; e++) acc[i][j][e] = 0.0f;

    prefetch(0, 0);

    int nk = K / BK;
    for (int t = 0; t < nk; t++) {
        int cur = t & 1;
        if (t + 1 < nk) {
            prefetch(cur ^ 1, (t + 1) * BK);
            cp_wait<1>();     // guarantees group for tile t complete
        } else {
            cp_wait<0>();
        }
        __syncthreads();

#pragma unroll
        for (int ks = 0; ks < 2; ks++) {
            int kb = ks * 8;
            unsigned af[4][4], bf[4][2];
#pragma unroll
            for (int mi = 0; mi < 4; mi++) {
                const float* ap = &As[cur][wm + 16 * mi + gid][kb + tig];
                af[mi][0] = __float_as_uint(ap[0]);
                af[mi][1] = __float_as_uint(ap[8 * APAD]);
                af[mi][2] = __float_as_uint(ap[4]);
                af[mi][3] = __float_as_uint(ap[8 * APAD + 4]);
            }
#pragma unroll
            for (int nj = 0; nj < 4; nj++) {
                int n = wn + 8 * nj + gid;
                bf[nj][0] = __float_as_uint(Bs[cur][kb + tig][n]);
                bf[nj][1] = __float_as_uint(Bs[cur][kb + 4 + tig][n]);
            }
#pragma unroll
            for (int mi = 0; mi < 4; mi++)
#pragma unroll
                for (int nj = 0; nj < 4; nj++) {
                    asm volatile(
                        "mma.sync.aligned.m16n8k8.row.col.f32.tf32.tf32.f32 "
                        "{%0,%1,%2,%3},{%4,%5,%6,%7},{%8,%9},{%0,%1,%2,%3};\n"
                        : "+f"(acc[mi][nj][0]), "+f"(acc[mi][nj][1]),
                          "+f"(acc[mi][nj][2]), "+f"(acc[mi][nj][3])
                        : "r"(af[mi][0]), "r"(af[mi][1]), "r"(af[mi][2]), "r"(af[mi][3]),
                          "r"(bf[nj][0]), "r"(bf[nj][1]));
                }
        }
        __syncthreads();
    }

    const float* resb = res ? res + (long)bz * sRes : nullptr;
    float* Cb = Cm + (long)bz * sC;

#pragma unroll
    for (int mi = 0; mi < 4; mi++) {
#pragma unroll
        for (int e2 = 0; e2 < 2; e2++) {
            int m = m0 + wm + 16 * mi + gid + 8 * e2;
            float sc = 0.0f, sh = 0.0f;
            if (EPI == 0 || EPI == 1) { sc = scale[m]; sh = shift[m]; }
            else if (EPI == 2) { sc = scale[m]; }
#pragma unroll
            for (int nj = 0; nj < 4; nj++) {
                int n = n0 + wn + 8 * nj + 2 * tig;
                float v0 = acc[mi][nj][2 * e2 + 0];
                float v1 = acc[mi][nj][2 * e2 + 1];
                if (EPI == 0) {
                    v0 = fmaxf(fmaf(v0, sc, sh), 0.0f);
                    v1 = fmaxf(fmaf(v1, sc, sh), 0.0f);
                } else if (EPI == 1) {
                    float2 r2 = *(const float2*)(resb + (long)m * ldc + n);
                    v0 = fmaf(v0, sc, sh) + r2.x;
                    v1 = fmaf(v1, sc, sh) + r2.y;
                } else if (EPI == 2) {
                    v0 = rnatf(v0 + sc);
                    v1 = rnatf(v1 + sc);
                }
                *(float2*)(Cb + (long)m * ldc + n) = make_float2(v0, v1);
            }
        }
    }
}

// ---------------- TF32 QK: S = q^T k + fused exp-rowsum into L ------------------
// q,k stored [C8=32][NN] per batch, rna-rounded at producer. K=32 -> single smem
// load, 4 mma k-steps. Epilogue: store S (fp32 acc), L[m] += sum_n rna(exp(S-SHIFT)).
__global__ __launch_bounds__(256) void qk_tf32_kernel(
    const float* __restrict__ q, const float* __restrict__ k,
    float* __restrict__ S, float* __restrict__ L) {
    __shared__ __align__(16) float Qs[128][33];   // [m][d]
    __shared__ __align__(16) float Ks[128][33];   // [n][d]
    int tid = threadIdx.x;
    int bz = blockIdx.z;
    const float* qb = q + (long)bz * (C8 * NN);
    const float* kb = k + (long)bz * (C8 * NN);
    int m0 = blockIdx.y * 128, n0 = blockIdx.x * 128;

#pragma unroll
    for (int r = 0; r < 16; r++) {
        int idx = tid + r * 256;      // 0..4095
        int d = idx >> 7, mm = idx & 127;
        Qs[mm][d] = qb[(long)d * NN + m0 + mm];
        Ks[mm][d] = kb[(long)d * NN + n0 + mm];
    }
    __syncthreads();

    int lane = tid & 31, warp = tid >> 5;
    int wm = (warp >> 2) * 64;
    int wn = (warp & 3) * 32;
    int gid = lane >> 2, tig = lane & 3;

    float acc[4][4][4];
#pragma unroll
    for (int i = 0; i < 4; i++)
#pragma unroll
        for (int j = 0; j < 4; j++)
#pragma unroll
            for (int e = 0; e < 4; e++) acc[i][j][e] = 0.0f;

#pragma unroll
    for (int ks = 0; ks < 4; ks++) {
        int kb2 = ks * 8;
        unsigned af[4][4], bf[4][2];
#pragma unroll
        for (int mi = 0; mi < 4; mi++) {
            const float* ap = &Qs[wm + 16 * mi + gid][kb2 + tig];
            af[mi][0] = __float_as_uint(ap[0]);
            af[mi][1] = __float_as_uint(ap[8 * 33]);
            af[mi][2] = __float_as_uint(ap[4]);
            af[mi][3] = __float_as_uint(ap[8 * 33 + 4]);
        }
#pragma unroll
        for (int nj = 0; nj < 4; nj++) {
            const float* bp = &Ks[wn + 8 * nj + gid][kb2 + tig];
            bf[nj][0] = __float_as_uint(bp[0]);
            bf[nj][1] = __float_as_uint(bp[4]);
        }
#pragma unroll
        for (int mi = 0; mi < 4; mi++)
#pragma unroll
            for (int nj = 0; nj < 4; nj++) {
                asm volatile(
                    "mma.sync.aligned.m16n8k8.row.col.f32.tf32.tf32.f32 "
                    "{%0,%1,%2,%3},{%4,%5,%6,%7},{%8,%9},{%0,%1,%2,%3};\n"
                    : "+f"(acc[mi][nj][0]), "+f"(acc[mi][nj][1]),
                      "+f"(acc[mi][nj][2]), "+f"(acc[mi][nj][3])
                    : "r"(af[mi][0]), "r"(af[mi][1]), "r"(af[mi][2]), "r"(af[mi][3]),
                      "r"(bf[nj][0]), "r"(bf[nj][1]));
            }
    }

    float* Sb = S + (long)bz * ((long)NN * NN);
    float* Lb = L + bz * NN;
#pragma unroll
    for (int mi = 0; mi < 4; mi++) {
#pragma unroll
        for (int e2 = 0; e2 < 2; e2++) {
            int m = m0 + wm + 16 * mi + gid + 8 * e2;
            float rp = 0.0f;
#pragma unroll
            for (int nj = 0; nj < 4; nj++) {
                int n = n0 + wn + 8 * nj + 2 * tig;
                float v0 = acc[mi][nj][2 * e2 + 0];
                float v1 = acc[mi][nj][2 * e2 + 1];
                *(float2*)(Sb + (long)m * NN + n) = make_float2(v0, v1);
                rp += rnatf(__expf(v0 - SM_SHIFT)) + rnatf(__expf(v1 - SM_SHIFT));
            }
            // reduce over tig (4 lanes cover this warp's 32 columns for row m)
            rp += __shfl_xor_sync(0xffffffffu, rp, 1);
            rp += __shfl_xor_sync(0xffffffffu, rp, 2);
            if (tig == 0) atomicAdd(&Lb[m], rp);
        }
    }
}

// ---------------- PV with fused softmax -----------------------------------------
// out[c,m] = relu( gamma * (sum_n v[c,n] * exp(S[m,n]-SHIFT)) / L[m] + xa[c,m] )
__global__ __launch_bounds__(256) void gemm_pv(
    const float* __restrict__ V, const float* __restrict__ S,
    float* __restrict__ Cm,
    const float* __restrict__ Lrow,
    const float* __restrict__ res, const float* __restrict__ gammaPtr) {
    constexpr int BM = 128, BN = 128, BK = 16;
    constexpr int APAD = 20, BPAD = 20;
    __shared__ __align__(16) float As[2][BM][APAD];
    __shared__ __align__(16) float Bs[2][BN][BPAD];

    int tid = threadIdx.x;
    int bz = blockIdx.z;
    const float* Ab = V + (long)bz * ((long)CC * NN);
    const float* Sb = S + (long)bz * ((long)NN * NN);
    int m0 = blockIdx.y * BM, n0 = blockIdx.x * BN;

    int a_row = tid >> 1, a_q = (tid & 1) * 2;
    int b_row = tid >> 1, b_q = (tid & 1) * 2;   // thread's S row fixed: n0+b_row

    uint32_t asBase = (uint32_t)__cvta_generic_to_shared(&As[0][0][0]);

    auto prefetchA = [&](int buf, int k0) {
#pragma unroll
        for (int j = 0; j < 2; j++) {
            int q = a_q + j;
            cp16(asBase + (((buf * BM + a_row) * APAD) + q * 4) * 4,
                 Ab + (long)(m0 + a_row) * NN + k0 + q * 4);
        }
        cp_commit();
    };
    float4 braw[2];
    auto ldgB = [&](int k0) {
#pragma unroll
        for (int j = 0; j < 2; j++)
            braw[j] = *(const float4*)(Sb + (long)(n0 + b_row) * NN + k0 + (b_q + j) * 4);
    };
    auto stsB = [&](int buf) {
#pragma unroll
        for (int j = 0; j < 2; j++) {
            float4 e;
            e.x = rnatf(__expf(braw[j].x - SM_SHIFT));
            e.y = rnatf(__expf(braw[j].y - SM_SHIFT));
            e.z = rnatf(__expf(braw[j].z - SM_SHIFT));
            e.w = rnatf(__expf(braw[j].w - SM_SHIFT));
            *(float4*)&Bs[buf][b_row][(b_q + j) * 4] = e;
        }
    };

    int lane = tid & 31, warp = tid >> 5;
    int wm = (warp >> 2) * 64;
    int wn = (warp & 3) * 32;
    int gid = lane >> 2, tig = lane & 3;

    float acc[4][4][4];
#pragma unroll
    for (int i = 0; i < 4; i++)
#pragma unroll
        for (int j = 0; j < 4; j++)
#pragma unroll
            for (int e = 0; e < 4; e++) acc[i][j][e] = 0.0f;

    prefetchA(0, 0);
    ldgB(0);
    stsB(0);
    cp_wait<0>();
    __syncthreads();

    const int nk = NN / BK;   // 64
    for (int t = 0; t < nk; t++) {
        int cur = t & 1;
        bool more = (t + 1 < nk);
        if (more) {
            prefetchA(cur ^ 1, (t + 1) * BK);   // buf^1 readers finished at t-1 barrier
            ldgB((t + 1) * BK);
            cp_wait<1>();    // tile t's A group complete before mma reads it
        } else {
            cp_wait<0>();
        }

#pragma unroll
        for (int ks = 0; ks < 2; ks++) {
            int kb = ks * 8;
            unsigned af[4][4], bf[4][2];
#pragma unroll
            for (int mi = 0; mi < 4; mi++) {
                const float* ap = &As[cur][wm + 16 * mi + gid][kb + tig];
                af[mi][0] = __float_as_uint(ap[0]);
                af[mi][1] = __float_as_uint(ap[8 * APAD]);
                af[mi][2] = __float_as_uint(ap[4]);
                af[mi][3] = __float_as_uint(ap[8 * APAD + 4]);
            }
#pragma unroll
            for (int nj = 0; nj < 4; nj++) {
                const float* bp = &Bs[cur][wn + 8 * nj + gid][kb + tig];
                bf[nj][0] = __float_as_uint(bp[0]);
                bf[nj][1] = __float_as_uint(bp[4]);
            }
#pragma unroll
            for (int mi = 0; mi < 4; mi++)
#pragma unroll
                for (int nj = 0; nj < 4; nj++) {
                    asm volatile(
                        "mma.sync.aligned.m16n8k8.row.col.f32.tf32.tf32.f32 "
                        "{%0,%1,%2,%3},{%4,%5,%6,%7},{%8,%9},{%0,%1,%2,%3};\n"
                        : "+f"(acc[mi][nj][0]), "+f"(acc[mi][nj][1]),
                          "+f"(acc[mi][nj][2]), "+f"(acc[mi][nj][3])
                        : "r"(af[mi][0]), "r"(af[mi][1]), "r"(af[mi][2]), "r"(af[mi][3]),
                          "r"(bf[nj][0]), "r"(bf[nj][1]));
                }
        }
        if (more) stsB(cur ^ 1);   // buf^1 last read at iter t-1, fenced by t-1's barrier
        __syncthreads();           // stsB visible; readers of cur done before reuse
    }

    float gm = gammaPtr[0];
    const float* resb = res + (long)bz * ((long)CC * NN);
    const float* lb = Lrow + bz * NN;
    float* Cb = Cm + (long)bz * ((long)CC * NN);

#pragma unroll
    for (int mi = 0; mi < 4; mi++) {
#pragma unroll
        for (int e2 = 0; e2 < 2; e2++) {
            int m = m0 + wm + 16 * mi + gid + 8 * e2;
#pragma unroll
            for (int nj = 0; nj < 4; nj++) {
                int n = n0 + wn + 8 * nj + 2 * tig;
                float2 l2 = *(const float2*)(lb + n);
                float2 r2 = *(const float2*)(resb + (long)m * NN + n);
                float v0 = fmaxf(fmaf(gm / l2.x, acc[mi][nj][2 * e2 + 0], r2.x), 0.0f);
                float v1 = fmaxf(fmaf(gm / l2.y, acc[mi][nj][2 * e2 + 1], r2.y), 0.0f);
                *(float2*)(Cb + (long)m * NN + n) = make_float2(v0, v1);
            }
        }
    }
}

// ---------------- launch ---------------------------------------------------------
extern "C" void kernel_launch(void* const* d_in, const int* in_sizes, int n_in,
                              void* d_out, int out_size) {
    const float* x     = (const float*)d_in[0];
    const float* dw1   = (const float*)d_in[1];
    const float* pw1   = (const float*)d_in[2];
    const float* bn1_g = (const float*)d_in[3];
    const float* bn1_b = (const float*)d_in[4];
    const float* bn1_m = (const float*)d_in[5];
    const float* bn1_v = (const float*)d_in[6];
    const float* dw2   = (const float*)d_in[7];
    const float* pw2   = (const float*)d_in[8];
    const float* bn2_g = (const float*)d_in[9];
    const float* bn2_b = (const float*)d_in[10];
    const float* bn2_m = (const float*)d_in[11];
    const float* bn2_v = (const float*)d_in[12];
    const float* wq    = (const float*)d_in[13];
    const float* bq    = (const float*)d_in[14];
    const float* wk    = (const float*)d_in[15];
    const float* bk    = (const float*)d_in[16];
    const float* wv    = (const float*)d_in[17];
    const float* bv    = (const float*)d_in[18];
    const float* gamma = (const float*)d_in[19];
    float* out = (float*)d_out;

    float *t1, *t2, *t3, *xa, *q, *k, *v, *S, *L, *wr, *bn;
    cudaGetSymbolAddress((void**)&t1, g_t1);
    cudaGetSymbolAddress((void**)&t2, g_t2);
    cudaGetSymbolAddress((void**)&t3, g_t3);
    cudaGetSymbolAddress((void**)&xa, g_xa);
    cudaGetSymbolAddress((void**)&q,  g_q);
    cudaGetSymbolAddress((void**)&k,  g_k);
    cudaGetSymbolAddress((void**)&v,  g_v);
    cudaGetSymbolAddress((void**)&S,  g_S);
    cudaGetSymbolAddress((void**)&L,  g_L);
    cudaGetSymbolAddress((void**)&wr, g_wr);
    cudaGetSymbolAddress((void**)&bn, g_bn);
    const float* scale1 = bn;
    const float* shift1 = bn + CC;
    const float* scale2 = bn + 2 * CC;
    const float* shift2 = bn + 3 * CC;
    const float* pw1r = wr;
    const float* pw2r = wr + CC * CC;
    const float* wvr  = wr + 2 * CC * CC;

    const long sBCN = (long)CC * NN;   // 262144

    // 0) BN affine precompute + weight rounding + L zeroing
    bnprep_kernel<<<1, CC>>>(bn1_g, bn1_b, bn1_m, bn1_v, bn2_g, bn2_b, bn2_m, bn2_v, bn);
    roundw_kernel<<<3 * CC * CC / 256, 256>>>(pw1, pw2, wv, wr);
    zerol_kernel<<<BB * NN / 256, 256>>>(L);

    // 1) depthwise 1 (output tf32-rna rounded)
    dwconv_kernel<<<BB * CC, 256>>>(x, dw1, t1);

    // 2) pointwise 1 + BN + ReLU (TF32 TC)
    gemm_tf32<0><<<dim3(NN / 128, CC / 128, BB), 256>>>(
        pw1r, t1, t2, CC, CC, NN, NN, 0, sBCN, sBCN, scale1, shift1, nullptr, 0);

    // 3) depthwise 2 (output tf32-rna rounded)
    dwconv_kernel<<<BB * CC, 256>>>(t2, dw2, t3);

    // 4) pointwise 2 + BN + residual x (TF32 TC)
    gemm_tf32<1><<<dim3(NN / 128, CC / 128, BB), 256>>>(
        pw2r, t3, xa, CC, CC, NN, NN, 0, sBCN, sBCN, scale2, shift2, x, sBCN);

    // 5) fused q & k projections (fp32 math, rna-rounded outputs; reads xa once)
    qkproj_kernel<<<dim3(NN / 64, 1, BB), 256>>>(wq, bq, wk, bk, xa, q, k);

    // 6) v = wv @ xa + bv (TF32 TC, output rna-rounded for PV)
    gemm_tf32<2><<<dim3(NN / 128, CC / 128, BB), 256>>>(
        wvr, xa, v, CC, CC, NN, NN, 0, sBCN, sBCN, bv, nullptr, nullptr, 0);

    // 7) S = q^T k (TF32 TC) + fused exp-rowsum -> L
    qk_tf32_kernel<<<dim3(NN / 128, NN / 128, BB), 256>>>(q, k, S, L);

    // 8) PV with fused softmax: out = relu(gamma * (v @ exp(S-SHIFT)) / L + xa)
    gemm_pv<<<dim3(NN / 128, CC / 128, BB), 256>>>(v, S, out, L, xa, gamma);

    (void)in_sizes; (void)n_in; (void)out_size;
}

// round 14
// speedup vs baseline: 3.2425x; 1.0970x over previous
#include <cuda_runtime.h>
#include <stdint.h>
#include <math.h>

// Problem dims (fixed)
#define BB   64
#define CC   256
#define C8   32
#define HH   32
#define WW   32
#define NN   1024            // H*W
#define BCN  16777216        // B*C*N
#define BQN  2097152         // B*C8*N
#define BNN  67108864        // B*N*N (WHOLE S array; per-batch stride is NN*NN)
#define SM_SHIFT 32.0f       // global logit shift (cancels in softmax; overflow guard)

// ---------------- scratch (static device arrays; no runtime alloc) -------------
// __align__(256) is load-bearing: float4/float2 vector access on these.
__device__ __align__(256) float g_t1[BCN];
__device__ __align__(256) float g_t2[BCN];
__device__ __align__(256) float g_t3[BCN];
__device__ __align__(256) float g_xa[BCN];
__device__ __align__(256) float g_q[BQN];
__device__ __align__(256) float g_k[BQN];
__device__ __align__(256) float g_v[BCN];
__device__ __align__(256) float g_S[BNN];              // holds rna(exp(S - SHIFT))
__device__ __align__(256) float g_L[BB * NN];          // row sums of exp(S - SHIFT)
__device__ __align__(256) float g_wr[3 * CC * CC];     // RNA-rounded pw1|pw2|wv
__device__ __align__(256) float g_bn[4 * CC];

// round-to-nearest tf32 (value stays in fp32 layout, low 13 mantissa bits zero)
__device__ __forceinline__ float rnatf(float x) {
    unsigned r;
    asm("cvt.rna.tf32.f32 %0, %1;" : "=r"(r) : "f"(x));
    return __uint_as_float(r);
}

// ---------------- BN affine precompute ----------------------------------------
__global__ void bnprep_kernel(const float* __restrict__ g1, const float* __restrict__ b1,
                              const float* __restrict__ m1, const float* __restrict__ v1,
                              const float* __restrict__ g2, const float* __restrict__ b2,
                              const float* __restrict__ m2, const float* __restrict__ v2,
                              float* __restrict__ bn) {
    int c = threadIdx.x;
    float s1 = g1[c] * rsqrtf(v1[c] + 1e-5f);
    float s2 = g2[c] * rsqrtf(v2[c] + 1e-5f);
    bn[c]          = s1;
    bn[CC + c]     = b1[c] - m1[c] * s1;
    bn[2 * CC + c] = s2;
    bn[3 * CC + c] = b2[c] - m2[c] * s2;
}

// ---------------- round weights to tf32-rna once --------------------------------
__global__ void roundw_kernel(const float* __restrict__ pw1, const float* __restrict__ pw2,
                              const float* __restrict__ wv, float* __restrict__ wr) {
    int i = blockIdx.x * 256 + threadIdx.x;   // 0 .. 3*CC*CC-1
    const int W = CC * CC;
    float v;
    if (i < W)          v = pw1[i];
    else if (i < 2 * W) v = pw2[i - W];
    else                v = wv[i - 2 * W];
    wr[i] = rnatf(v);
}

// ---------------- zero L ---------------------------------------------------------
__global__ void zerol_kernel(float* __restrict__ L) {
    L[blockIdx.x * 256 + threadIdx.x] = 0.0f;
}

// ---------------- depthwise 3x3 v3: padded tile, column mapping -----------------
// s layout: [34 rows][40 floats]; input (y,x) at s[(y+1)*40 + 4 + x].
// Halo (x=-1 -> col 3, x=32 -> col 36, rows 0/33) provided by the zero-fill.
// Compute: lane = ox (32 cols), warp covers 4 output rows -> all LDS are
// 32-consecutive-float (conflict-free), zero index math in the loader.
#define DWST 40
__global__ __launch_bounds__(256) void dwconv_kernel(const float* __restrict__ in,
                                                     const float* __restrict__ w9,
                                                     float* __restrict__ out) {
    __shared__ __align__(16) float s[34 * DWST];
    int p = blockIdx.x;           // plane index = b*C + c
    int c = p & (CC - 1);
    const float* ip = in + (long)p * NN;
    int tid = threadIdx.x;
    float w[9];
#pragma unroll
    for (int j = 0; j < 9; j++) w[j] = w9[c * 9 + j];

    // zero everything (covers all halo), then fill interior with aligned float4
#pragma unroll
    for (int i = tid; i < 34 * DWST / 4; i += 256)
        ((float4*)s)[i] = make_float4(0.f, 0.f, 0.f, 0.f);
    __syncthreads();
    {
        int y = tid >> 3;                 // 0..31
        int xq = (tid & 7) * 4;           // 0,4,...,28
        *(float4*)&s[(y + 1) * DWST + 4 + xq] = *(const float4*)(ip + y * WW + xq);
    }
    __syncthreads();

    int ox = tid & 31;                    // lane -> column
    int oy0 = (tid >> 5) * 4;             // warp -> 4 rows
    const float* col = s + (oy0 * DWST) + 4 + ox;   // padded row oy0 = input row oy0-1
    float r[6][3];
#pragma unroll
    for (int rr = 0; rr < 6; rr++) {
        r[rr][0] = col[rr * DWST - 1];
        r[rr][1] = col[rr * DWST];
        r[rr][2] = col[rr * DWST + 1];
    }
    float* op = out + (long)p * NN + oy0 * WW + ox;
#pragma unroll
    for (int rr = 0; rr < 4; rr++) {
        float acc = 0.0f;
#pragma unroll
        for (int dy = 0; dy < 3; dy++)
#pragma unroll
            for (int dx = 0; dx < 3; dx++)
                acc = fmaf(r[rr + dy][dx], w[dy * 3 + dx], acc);
        op[rr * WW] = rnatf(acc);
    }
}

// ---------------- fused q/k projection (fp32 math, rna-rounded output) ----------
// rows 0-31 of the 64-row A tile are wq, rows 32-63 are wk. Reads xa ONCE.
__global__ __launch_bounds__(256) void qkproj_kernel(
    const float* __restrict__ wq, const float* __restrict__ bq,
    const float* __restrict__ wk, const float* __restrict__ bk,
    const float* __restrict__ xa, float* __restrict__ q, float* __restrict__ k) {
    __shared__ __align__(16) float As[16][65];
    __shared__ __align__(16) float Bs[16][65];

    int bz = blockIdx.z;
    const float* xab = xa + (long)bz * ((long)CC * NN);
    int n0 = blockIdx.x * 64;
    int tid = threadIdx.x;
    int ty = tid >> 4, tx = tid & 15;

    float acc[4][4];
#pragma unroll
    for (int i = 0; i < 4; i++)
#pragma unroll
        for (int j = 0; j < 4; j++) acc[i][j] = 0.0f;

    int kk = tid & 15, mrow = tid >> 4;
    for (int k0 = 0; k0 < CC; k0 += 16) {
#pragma unroll
        for (int r = 0; r < 4; r++) {
            int m = mrow + r * 16;
            const float* wrow = (m < 32) ? (wq + m * CC) : (wk + (m - 32) * CC);
            As[kk][m] = wrow[k0 + kk];
        }
#pragma unroll
        for (int r = 0; r < 4; r++) {
            int idx = tid + r * 256;
            int kb2 = idx >> 6, nn = idx & 63;
            Bs[kb2][nn] = xab[(long)(k0 + kb2) * NN + n0 + nn];
        }
        __syncthreads();

#pragma unroll
        for (int kc = 0; kc < 16; kc++) {
            float a[4], b[4];
#pragma unroll
            for (int i = 0; i < 4; i++) a[i] = As[kc][ty + 16 * i];
#pragma unroll
            for (int j = 0; j < 4; j++) b[j] = Bs[kc][tx + 16 * j];
#pragma unroll
            for (int i = 0; i < 4; i++)
#pragma unroll
                for (int j = 0; j < 4; j++) acc[i][j] = fmaf(a[i], b[j], acc[i][j]);
        }
        __syncthreads();
    }

    float* qb = q + (long)bz * (C8 * NN);
    float* kb = k + (long)bz * (C8 * NN);
#pragma unroll
    for (int i = 0; i < 4; i++) {
        int m = ty + 16 * i;
        float bias = (m < 32) ? bq[m] : bk[m - 32];
        float* dst = (m < 32) ? (qb + (long)m * NN) : (kb + (long)(m - 32) * NN);
#pragma unroll
        for (int j = 0; j < 4; j++) {
            int n = n0 + tx + 16 * j;
            dst[n] = rnatf(acc[i][j] + bias);
        }
    }
}

// ---------------- cp.async helpers ----------------------------------------------
__device__ __forceinline__ void cp16(uint32_t dst, const float* src) {
    asm volatile("cp.async.ca.shared.global [%0], [%1], 16;" :: "r"(dst), "l"(src));
}
__device__ __forceinline__ void cp_commit() {
    asm volatile("cp.async.commit_group;" ::: "memory");
}
template <int N>
__device__ __forceinline__ void cp_wait() {
    asm volatile("cp.async.wait_group %0;" :: "n"(N) : "memory");
}

// ---------------- TF32 tensor-core GEMM, cp.async 2-stage pipeline --------------
// C[b][m][n] = sum_k A[b][m][k]*B[k][n]  (A [M,K] k-contiguous, B [K,N] n-contig)
// EPI: 0 relu(acc*scale[m]+shift[m]); 1 acc*scale[m]+shift[m]+res;
//      2 rnatf(acc+scale[m])   (v production — consumed only by PV tf32)
template <int EPI>
__global__ __launch_bounds__(256) void gemm_tf32(
    const float* __restrict__ A, const float* __restrict__ B, float* __restrict__ Cm,
    int K, int lda, int ldb, int ldc,
    long sA, long sB, long sC,
    const float* __restrict__ scale, const float* __restrict__ shift,
    const float* __restrict__ res, long sRes) {
    constexpr int BM = 128, BN = 128, BK = 16;
    constexpr int APAD = 20;
    __shared__ __align__(16) float As[2][BM][APAD];
    __shared__ __align__(16) float Bs[2][BK][BN + 8];

    int tid = threadIdx.x;
    int bz = blockIdx.z;
    const float* Ab = A + (long)bz * sA;
    const float* Bb = B + (long)bz * sB;
    int m0 = blockIdx.y * BM, n0 = blockIdx.x * BN;

    int a_row = tid >> 1, a_q = (tid & 1) * 2;
    int b_row = tid >> 4, b_q = (tid & 15) * 2;

    uint32_t asBase = (uint32_t)__cvta_generic_to_shared(&As[0][0][0]);
    uint32_t bsBase = (uint32_t)__cvta_generic_to_shared(&Bs[0][0][0]);

    auto prefetch = [&](int buf, int k0) {
#pragma unroll
        for (int j = 0; j < 2; j++) {
            int q = a_q + j;
            cp16(asBase + (((buf * BM + a_row) * APAD) + q * 4) * 4,
                 Ab + (long)(m0 + a_row) * lda + k0 + q * 4);
        }
#pragma unroll
        for (int j = 0; j < 2; j++) {
            int q = b_q + j;
            cp16(bsBase + (((buf * BK + b_row) * (BN + 8)) + q * 4) * 4,
                 Bb + (long)(k0 + b_row) * ldb + n0 + q * 4);
        }
        cp_commit();
    };

    int lane = tid & 31, warp = tid >> 5;
    int wm = (warp >> 2) * 64;
    int wn = (warp & 3) * 32;
    int gid = lane >> 2, tig = lane & 3;

    float acc[4][4][4];
#pragma unroll
    for (int i = 0; i < 4; i++)
#pragma unroll
        for (int j = 0; j < 4; j++)
#pragma unroll
            for (int e = 0; e < 4; e++) acc[i][j][e] = 0.0f;

    prefetch(0, 0);

    int nk = K / BK;
    for (int t = 0; t < nk; t++) {
        int cur = t & 1;
        if (t + 1 < nk) {
            prefetch(cur ^ 1, (t + 1) * BK);
            cp_wait<1>();     // guarantees group for tile t complete
        } else {
            cp_wait<0>();
        }
        __syncthreads();

#pragma unroll
        for (int ks = 0; ks < 2; ks++) {
            int kb = ks * 8;
            unsigned af[4][4], bf[4][2];
#pragma unroll
            for (int mi = 0; mi < 4; mi++) {
                const float* ap = &As[cur][wm + 16 * mi + gid][kb + tig];
                af[mi][0] = __float_as_uint(ap[0]);
                af[mi][1] = __float_as_uint(ap[8 * APAD]);
                af[mi][2] = __float_as_uint(ap[4]);
                af[mi][3] = __float_as_uint(ap[8 * APAD + 4]);
            }
#pragma unroll
            for (int nj = 0; nj < 4; nj++) {
                int n = wn + 8 * nj + gid;
                bf[nj][0] = __float_as_uint(Bs[cur][kb + tig][n]);
                bf[nj][1] = __float_as_uint(Bs[cur][kb + 4 + tig][n]);
            }
#pragma unroll
            for (int mi = 0; mi < 4; mi++)
#pragma unroll
                for (int nj = 0; nj < 4; nj++) {
                    asm volatile(
                        "mma.sync.aligned.m16n8k8.row.col.f32.tf32.tf32.f32 "
                        "{%0,%1,%2,%3},{%4,%5,%6,%7},{%8,%9},{%0,%1,%2,%3};\n"
                        : "+f"(acc[mi][nj][0]), "+f"(acc[mi][nj][1]),
                          "+f"(acc[mi][nj][2]), "+f"(acc[mi][nj][3])
                        : "r"(af[mi][0]), "r"(af[mi][1]), "r"(af[mi][2]), "r"(af[mi][3]),
                          "r"(bf[nj][0]), "r"(bf[nj][1]));
                }
        }
        __syncthreads();
    }

    const float* resb = res ? res + (long)bz * sRes : nullptr;
    float* Cb = Cm + (long)bz * sC;

#pragma unroll
    for (int mi = 0; mi < 4; mi++) {
#pragma unroll
        for (int e2 = 0; e2 < 2; e2++) {
            int m = m0 + wm + 16 * mi + gid + 8 * e2;
            float sc = 0.0f, sh = 0.0f;
            if (EPI == 0 || EPI == 1) { sc = scale[m]; sh = shift[m]; }
            else if (EPI == 2) { sc = scale[m]; }
#pragma unroll
            for (int nj = 0; nj < 4; nj++) {
                int n = n0 + wn + 8 * nj + 2 * tig;
                float v0 = acc[mi][nj][2 * e2 + 0];
                float v1 = acc[mi][nj][2 * e2 + 1];
                if (EPI == 0) {
                    v0 = fmaxf(fmaf(v0, sc, sh), 0.0f);
                    v1 = fmaxf(fmaf(v1, sc, sh), 0.0f);
                } else if (EPI == 1) {
                    float2 r2 = *(const float2*)(resb + (long)m * ldc + n);
                    v0 = fmaf(v0, sc, sh) + r2.x;
                    v1 = fmaf(v1, sc, sh) + r2.y;
                } else if (EPI == 2) {
                    v0 = rnatf(v0 + sc);
                    v1 = rnatf(v1 + sc);
                }
                *(float2*)(Cb + (long)m * ldc + n) = make_float2(v0, v1);
            }
        }
    }
}

// ---------------- TF32 QK: P = rna(exp(q^T k - SHIFT)) + rowsum into L ----------
// q,k stored [C8=32][NN] per batch, rna-rounded at producer. K=32 -> single smem
// load, 4 mma k-steps. Stores the rounded EXP (not the raw logit): PV consumes it
// directly, and L is summed from the same values -> consistent softmax.
__global__ __launch_bounds__(256) void qk_tf32_kernel(
    const float* __restrict__ q, const float* __restrict__ k,
    float* __restrict__ S, float* __restrict__ L) {
    __shared__ __align__(16) float Qs[128][33];   // [m][d]
    __shared__ __align__(16) float Ks[128][33];   // [n][d]
    int tid = threadIdx.x;
    int bz = blockIdx.z;
    const float* qb = q + (long)bz * (C8 * NN);
    const float* kb = k + (long)bz * (C8 * NN);
    int m0 = blockIdx.y * 128, n0 = blockIdx.x * 128;

#pragma unroll
    for (int r = 0; r < 16; r++) {
        int idx = tid + r * 256;      // 0..4095
        int d = idx >> 7, mm = idx & 127;
        Qs[mm][d] = qb[(long)d * NN + m0 + mm];
        Ks[mm][d] = kb[(long)d * NN + n0 + mm];
    }
    __syncthreads();

    int lane = tid & 31, warp = tid >> 5;
    int wm = (warp >> 2) * 64;
    int wn = (warp & 3) * 32;
    int gid = lane >> 2, tig = lane & 3;

    float acc[4][4][4];
#pragma unroll
    for (int i = 0; i < 4; i++)
#pragma unroll
        for (int j = 0; j < 4; j++)
#pragma unroll
            for (int e = 0; e < 4; e++) acc[i][j][e] = 0.0f;

#pragma unroll
    for (int ks = 0; ks < 4; ks++) {
        int kb2 = ks * 8;
        unsigned af[4][4], bf[4][2];
#pragma unroll
        for (int mi = 0; mi < 4; mi++) {
            const float* ap = &Qs[wm + 16 * mi + gid][kb2 + tig];
            af[mi][0] = __float_as_uint(ap[0]);
            af[mi][1] = __float_as_uint(ap[8 * 33]);
            af[mi][2] = __float_as_uint(ap[4]);
            af[mi][3] = __float_as_uint(ap[8 * 33 + 4]);
        }
#pragma unroll
        for (int nj = 0; nj < 4; nj++) {
            const float* bp = &Ks[wn + 8 * nj + gid][kb2 + tig];
            bf[nj][0] = __float_as_uint(bp[0]);
            bf[nj][1] = __float_as_uint(bp[4]);
        }
#pragma unroll
        for (int mi = 0; mi < 4; mi++)
#pragma unroll
            for (int nj = 0; nj < 4; nj++) {
                asm volatile(
                    "mma.sync.aligned.m16n8k8.row.col.f32.tf32.tf32.f32 "
                    "{%0,%1,%2,%3},{%4,%5,%6,%7},{%8,%9},{%0,%1,%2,%3};\n"
                    : "+f"(acc[mi][nj][0]), "+f"(acc[mi][nj][1]),
                      "+f"(acc[mi][nj][2]), "+f"(acc[mi][nj][3])
                    : "r"(af[mi][0]), "r"(af[mi][1]), "r"(af[mi][2]), "r"(af[mi][3]),
                      "r"(bf[nj][0]), "r"(bf[nj][1]));
            }
    }

    float* Sb = S + (long)bz * ((long)NN * NN);
    float* Lb = L + bz * NN;
#pragma unroll
    for (int mi = 0; mi < 4; mi++) {
#pragma unroll
        for (int e2 = 0; e2 < 2; e2++) {
            int m = m0 + wm + 16 * mi + gid + 8 * e2;
            float rp = 0.0f;
#pragma unroll
            for (int nj = 0; nj < 4; nj++) {
                int n = n0 + wn + 8 * nj + 2 * tig;
                float e0 = rnatf(__expf(acc[mi][nj][2 * e2 + 0] - SM_SHIFT));
                float e1 = rnatf(__expf(acc[mi][nj][2 * e2 + 1] - SM_SHIFT));
                *(float2*)(Sb + (long)m * NN + n) = make_float2(e0, e1);
                rp += e0 + e1;
            }
            // reduce over tig (4 lanes cover this warp's 32 columns for row m)
            rp += __shfl_xor_sync(0xffffffffu, rp, 1);
            rp += __shfl_xor_sync(0xffffffffu, rp, 2);
            if (tig == 0) atomicAdd(&Lb[m], rp);
        }
    }
}

// ---------------- PV: pure dual-cp.async TF32 GEMM ------------------------------
// out[c,m] = relu( gamma * (sum_n v[c,n] * P[m,n]) / L[m] + xa[c,m] )
// A = v [c][n] k-contiguous; B = P [m][n] k-contiguous (pre-exp'd, pre-rounded).
__global__ __launch_bounds__(256) void gemm_pv(
    const float* __restrict__ V, const float* __restrict__ P,
    float* __restrict__ Cm,
    const float* __restrict__ Lrow,
    const float* __restrict__ res, const float* __restrict__ gammaPtr) {
    constexpr int BM = 128, BN = 128, BK = 16;
    constexpr int PAD = 20;
    __shared__ __align__(16) float As[2][BM][PAD];
    __shared__ __align__(16) float Bs[2][BN][PAD];

    int tid = threadIdx.x;
    int bz = blockIdx.z;
    const float* Ab = V + (long)bz * ((long)CC * NN);
    const float* Pb = P + (long)bz * ((long)NN * NN);
    int m0 = blockIdx.y * BM, n0 = blockIdx.x * BN;

    int a_row = tid >> 1, a_q = (tid & 1) * 2;

    uint32_t asBase = (uint32_t)__cvta_generic_to_shared(&As[0][0][0]);
    uint32_t bsBase = (uint32_t)__cvta_generic_to_shared(&Bs[0][0][0]);

    auto prefetch = [&](int buf, int k0) {
#pragma unroll
        for (int j = 0; j < 2; j++) {
            int q = a_q + j;
            cp16(asBase + (((buf * BM + a_row) * PAD) + q * 4) * 4,
                 Ab + (long)(m0 + a_row) * NN + k0 + q * 4);
        }
#pragma unroll
        for (int j = 0; j < 2; j++) {
            int q = a_q + j;
            cp16(bsBase + (((buf * BN + a_row) * PAD) + q * 4) * 4,
                 Pb + (long)(n0 + a_row) * NN + k0 + q * 4);
        }
        cp_commit();
    };

    int lane = tid & 31, warp = tid >> 5;
    int wm = (warp >> 2) * 64;
    int wn = (warp & 3) * 32;
    int gid = lane >> 2, tig = lane & 3;

    float acc[4][4][4];
#pragma unroll
    for (int i = 0; i < 4; i++)
#pragma unroll
        for (int j = 0; j < 4; j++)
#pragma unroll
            for (int e = 0; e < 4; e++) acc[i][j][e] = 0.0f;

    prefetch(0, 0);

    const int nk = NN / BK;   // 64
    for (int t = 0; t < nk; t++) {
        int cur = t & 1;
        if (t + 1 < nk) {
            prefetch(cur ^ 1, (t + 1) * BK);
            cp_wait<1>();     // tile t's group complete
        } else {
            cp_wait<0>();
        }
        __syncthreads();

#pragma unroll
        for (int ks = 0; ks < 2; ks++) {
            int kb = ks * 8;
            unsigned af[4][4], bf[4][2];
#pragma unroll
            for (int mi = 0; mi < 4; mi++) {
                const float* ap = &As[cur][wm + 16 * mi + gid][kb + tig];
                af[mi][0] = __float_as_uint(ap[0]);
                af[mi][1] = __float_as_uint(ap[8 * PAD]);
                af[mi][2] = __float_as_uint(ap[4]);
                af[mi][3] = __float_as_uint(ap[8 * PAD + 4]);
            }
#pragma unroll
            for (int nj = 0; nj < 4; nj++) {
                const float* bp = &Bs[cur][wn + 8 * nj + gid][kb + tig];
                bf[nj][0] = __float_as_uint(bp[0]);
                bf[nj][1] = __float_as_uint(bp[4]);
            }
#pragma unroll
            for (int mi = 0; mi < 4; mi++)
#pragma unroll
                for (int nj = 0; nj < 4; nj++) {
                    asm volatile(
                        "mma.sync.aligned.m16n8k8.row.col.f32.tf32.tf32.f32 "
                        "{%0,%1,%2,%3},{%4,%5,%6,%7},{%8,%9},{%0,%1,%2,%3};\n"
                        : "+f"(acc[mi][nj][0]), "+f"(acc[mi][nj][1]),
                          "+f"(acc[mi][nj][2]), "+f"(acc[mi][nj][3])
                        : "r"(af[mi][0]), "r"(af[mi][1]), "r"(af[mi][2]), "r"(af[mi][3]),
                          "r"(bf[nj][0]), "r"(bf[nj][1]));
                }
        }
        __syncthreads();
    }

    float gm = gammaPtr[0];
    const float* resb = res + (long)bz * ((long)CC * NN);
    const float* lb = Lrow + bz * NN;
    float* Cb = Cm + (long)bz * ((long)CC * NN);

#pragma unroll
    for (int mi = 0; mi < 4; mi++) {
#pragma unroll
        for (int e2 = 0; e2 < 2; e2++) {
            int m = m0 + wm + 16 * mi + gid + 8 * e2;
#pragma unroll
            for (int nj = 0; nj < 4; nj++) {
                int n = n0 + wn + 8 * nj + 2 * tig;
                float2 l2 = *(const float2*)(lb + n);
                float2 r2 = *(const float2*)(resb + (long)m * NN + n);
                float v0 = fmaxf(fmaf(gm / l2.x, acc[mi][nj][2 * e2 + 0], r2.x), 0.0f);
                float v1 = fmaxf(fmaf(gm / l2.y, acc[mi][nj][2 * e2 + 1], r2.y), 0.0f);
                *(float2*)(Cb + (long)m * NN + n) = make_float2(v0, v1);
            }
        }
    }
}

// ---------------- launch ---------------------------------------------------------
extern "C" void kernel_launch(void* const* d_in, const int* in_sizes, int n_in,
                              void* d_out, int out_size) {
    const float* x     = (const float*)d_in[0];
    const float* dw1   = (const float*)d_in[1];
    const float* pw1   = (const float*)d_in[2];
    const float* bn1_g = (const float*)d_in[3];
    const float* bn1_b = (const float*)d_in[4];
    const float* bn1_m = (const float*)d_in[5];
    const float* bn1_v = (const float*)d_in[6];
    const float* dw2   = (const float*)d_in[7];
    const float* pw2   = (const float*)d_in[8];
    const float* bn2_g = (const float*)d_in[9];
    const float* bn2_b = (const float*)d_in[10];
    const float* bn2_m = (const float*)d_in[11];
    const float* bn2_v = (const float*)d_in[12];
    const float* wq    = (const float*)d_in[13];
    const float* bq    = (const float*)d_in[14];
    const float* wk    = (const float*)d_in[15];
    const float* bk    = (const float*)d_in[16];
    const float* wv    = (const float*)d_in[17];
    const float* bv    = (const float*)d_in[18];
    const float* gamma = (const float*)d_in[19];
    float* out = (float*)d_out;

    float *t1, *t2, *t3, *xa, *q, *k, *v, *S, *L, *wr, *bn;
    cudaGetSymbolAddress((void**)&t1, g_t1);
    cudaGetSymbolAddress((void**)&t2, g_t2);
    cudaGetSymbolAddress((void**)&t3, g_t3);
    cudaGetSymbolAddress((void**)&xa, g_xa);
    cudaGetSymbolAddress((void**)&q,  g_q);
    cudaGetSymbolAddress((void**)&k,  g_k);
    cudaGetSymbolAddress((void**)&v,  g_v);
    cudaGetSymbolAddress((void**)&S,  g_S);
    cudaGetSymbolAddress((void**)&L,  g_L);
    cudaGetSymbolAddress((void**)&wr, g_wr);
    cudaGetSymbolAddress((void**)&bn, g_bn);
    const float* scale1 = bn;
    const float* shift1 = bn + CC;
    const float* scale2 = bn + 2 * CC;
    const float* shift2 = bn + 3 * CC;
    const float* pw1r = wr;
    const float* pw2r = wr + CC * CC;
    const float* wvr  = wr + 2 * CC * CC;

    const long sBCN = (long)CC * NN;   // 262144

    // 0) BN affine precompute + weight rounding + L zeroing
    bnprep_kernel<<<1, CC>>>(bn1_g, bn1_b, bn1_m, bn1_v, bn2_g, bn2_b, bn2_m, bn2_v, bn);
    roundw_kernel<<<3 * CC * CC / 256, 256>>>(pw1, pw2, wv, wr);
    zerol_kernel<<<BB * NN / 256, 256>>>(L);

    // 1) depthwise 1 (output tf32-rna rounded)
    dwconv_kernel<<<BB * CC, 256>>>(x, dw1, t1);

    // 2) pointwise 1 + BN + ReLU (TF32 TC)
    gemm_tf32<0><<<dim3(NN / 128, CC / 128, BB), 256>>>(
        pw1r, t1, t2, CC, CC, NN, NN, 0, sBCN, sBCN, scale1, shift1, nullptr, 0);

    // 3) depthwise 2 (output tf32-rna rounded)
    dwconv_kernel<<<BB * CC, 256>>>(t2, dw2, t3);

    // 4) pointwise 2 + BN + residual x (TF32 TC)
    gemm_tf32<1><<<dim3(NN / 128, CC / 128, BB), 256>>>(
        pw2r, t3, xa, CC, CC, NN, NN, 0, sBCN, sBCN, scale2, shift2, x, sBCN);

    // 5) fused q & k projections (fp32 math, rna-rounded outputs; reads xa once)
    qkproj_kernel<<<dim3(NN / 64, 1, BB), 256>>>(wq, bq, wk, bk, xa, q, k);

    // 6) v = wv @ xa + bv (TF32 TC, output rna-rounded for PV)
    gemm_tf32<2><<<dim3(NN / 128, CC / 128, BB), 256>>>(
        wvr, xa, v, CC, CC, NN, NN, 0, sBCN, sBCN, bv, nullptr, nullptr, 0);

    // 7) P = rna(exp(q^T k - SHIFT)) (TF32 TC) + rowsum -> L
    qk_tf32_kernel<<<dim3(NN / 128, NN / 128, BB), 256>>>(q, k, S, L);

    // 8) PV (pure dual-cp.async TF32 GEMM): out = relu(gamma * (v @ P) / L + xa)
    gemm_pv<<<dim3(NN / 128, CC / 128, BB), 256>>>(v, S, out, L, xa, gamma);

    (void)in_sizes; (void)n_in; (void)out_size;
}

// round 15
// speedup vs baseline: 3.2977x; 1.0170x over previous
#include <cuda_runtime.h>
#include <cuda_bf16.h>
#include <stdint.h>
#include <math.h>

// Problem dims (fixed)
#define BB   64
#define CC   256
#define C8   32
#define HH   32
#define WW   32
#define NN   1024            // H*W
#define BCN  16777216        // B*C*N
#define BQN  2097152         // B*C8*N
#define BNN  67108864        // B*N*N (element count; P stored as bf16 inside)
#define SM_SHIFT 32.0f       // global logit shift (cancels in softmax; overflow guard)

// ---------------- scratch (static device arrays; no runtime alloc) -------------
// __align__(256) is load-bearing: vector access on these.
__device__ __align__(256) float g_t1[BCN];
__device__ __align__(256) float g_t2[BCN];
__device__ __align__(256) float g_t3[BCN];
__device__ __align__(256) float g_xa[BCN];
__device__ __align__(256) float g_q[BQN];
__device__ __align__(256) float g_k[BQN];
__device__ __align__(256) float g_v[BCN];
__device__ __align__(256) __nv_bfloat16 g_P[BNN];      // rna->bf16(exp(S - SHIFT))
__device__ __align__(256) float g_L[BB * NN];          // row sums of the SAME bf16 values
__device__ __align__(256) float g_wr[3 * CC * CC];     // RNA-rounded pw1|pw2|wv
__device__ __align__(256) float g_bn[4 * CC];

// round-to-nearest tf32 (value stays in fp32 layout, low 13 mantissa bits zero)
__device__ __forceinline__ float rnatf(float x) {
    unsigned r;
    asm("cvt.rna.tf32.f32 %0, %1;" : "=r"(r) : "f"(x));
    return __uint_as_float(r);
}

// ---------------- BN affine precompute ----------------------------------------
__global__ void bnprep_kernel(const float* __restrict__ g1, const float* __restrict__ b1,
                              const float* __restrict__ m1, const float* __restrict__ v1,
                              const float* __restrict__ g2, const float* __restrict__ b2,
                              const float* __restrict__ m2, const float* __restrict__ v2,
                              float* __restrict__ bn) {
    int c = threadIdx.x;
    float s1 = g1[c] * rsqrtf(v1[c] + 1e-5f);
    float s2 = g2[c] * rsqrtf(v2[c] + 1e-5f);
    bn[c]          = s1;
    bn[CC + c]     = b1[c] - m1[c] * s1;
    bn[2 * CC + c] = s2;
    bn[3 * CC + c] = b2[c] - m2[c] * s2;
}

// ---------------- round weights to tf32-rna once --------------------------------
__global__ void roundw_kernel(const float* __restrict__ pw1, const float* __restrict__ pw2,
                              const float* __restrict__ wv, float* __restrict__ wr) {
    int i = blockIdx.x * 256 + threadIdx.x;   // 0 .. 3*CC*CC-1
    const int W = CC * CC;
    float v;
    if (i < W)          v = pw1[i];
    else if (i < 2 * W) v = pw2[i - W];
    else                v = wv[i - 2 * W];
    wr[i] = rnatf(v);
}

// ---------------- zero L ---------------------------------------------------------
__global__ void zerol_kernel(float* __restrict__ L) {
    L[blockIdx.x * 256 + threadIdx.x] = 0.0f;
}

// ---------------- depthwise 3x3 v3: padded tile, column mapping -----------------
#define DWST 40
__global__ __launch_bounds__(256) void dwconv_kernel(const float* __restrict__ in,
                                                     const float* __restrict__ w9,
                                                     float* __restrict__ out) {
    __shared__ __align__(16) float s[34 * DWST];
    int p = blockIdx.x;           // plane index = b*C + c
    int c = p & (CC - 1);
    const float* ip = in + (long)p * NN;
    int tid = threadIdx.x;
    float w[9];
#pragma unroll
    for (int j = 0; j < 9; j++) w[j] = w9[c * 9 + j];

#pragma unroll
    for (int i = tid; i < 34 * DWST / 4; i += 256)
        ((float4*)s)[i] = make_float4(0.f, 0.f, 0.f, 0.f);
    __syncthreads();
    {
        int y = tid >> 3;                 // 0..31
        int xq = (tid & 7) * 4;           // 0,4,...,28
        *(float4*)&s[(y + 1) * DWST + 4 + xq] = *(const float4*)(ip + y * WW + xq);
    }
    __syncthreads();

    int ox = tid & 31;                    // lane -> column
    int oy0 = (tid >> 5) * 4;             // warp -> 4 rows
    const float* col = s + (oy0 * DWST) + 4 + ox;
    float r[6][3];
#pragma unroll
    for (int rr = 0; rr < 6; rr++) {
        r[rr][0] = col[rr * DWST - 1];
        r[rr][1] = col[rr * DWST];
        r[rr][2] = col[rr * DWST + 1];
    }
    float* op = out + (long)p * NN + oy0 * WW + ox;
#pragma unroll
    for (int rr = 0; rr < 4; rr++) {
        float acc = 0.0f;
#pragma unroll
        for (int dy = 0; dy < 3; dy++)
#pragma unroll
            for (int dx = 0; dx < 3; dx++)
                acc = fmaf(r[rr + dy][dx], w[dy * 3 + dx], acc);
        op[rr * WW] = rnatf(acc);
    }
}

// ---------------- fused q/k projection (fp32 math, rna-rounded output) ----------
__global__ __launch_bounds__(256) void qkproj_kernel(
    const float* __restrict__ wq, const float* __restrict__ bq,
    const float* __restrict__ wk, const float* __restrict__ bk,
    const float* __restrict__ xa, float* __restrict__ q, float* __restrict__ k) {
    __shared__ __align__(16) float As[16][65];
    __shared__ __align__(16) float Bs[16][65];

    int bz = blockIdx.z;
    const float* xab = xa + (long)bz * ((long)CC * NN);
    int n0 = blockIdx.x * 64;
    int tid = threadIdx.x;
    int ty = tid >> 4, tx = tid & 15;

    float acc[4][4];
#pragma unroll
    for (int i = 0; i < 4; i++)
#pragma unroll
        for (int j = 0; j < 4; j++) acc[i][j] = 0.0f;

    int kk = tid & 15, mrow = tid >> 4;
    for (int k0 = 0; k0 < CC; k0 += 16) {
#pragma unroll
        for (int r = 0; r < 4; r++) {
            int m = mrow + r * 16;
            const float* wrow = (m < 32) ? (wq + m * CC) : (wk + (m - 32) * CC);
            As[kk][m] = wrow[k0 + kk];
        }
#pragma unroll
        for (int r = 0; r < 4; r++) {
            int idx = tid + r * 256;
            int kb2 = idx >> 6, nn = idx & 63;
            Bs[kb2][nn] = xab[(long)(k0 + kb2) * NN + n0 + nn];
        }
        __syncthreads();

#pragma unroll
        for (int kc = 0; kc < 16; kc++) {
            float a[4], b[4];
#pragma unroll
            for (int i = 0; i < 4; i++) a[i] = As[kc][ty + 16 * i];
#pragma unroll
            for (int j = 0; j < 4; j++) b[j] = Bs[kc][tx + 16 * j];
#pragma unroll
            for (int i = 0; i < 4; i++)
#pragma unroll
                for (int j = 0; j < 4; j++) acc[i][j] = fmaf(a[i], b[j], acc[i][j]);
        }
        __syncthreads();
    }

    float* qb = q + (long)bz * (C8 * NN);
    float* kb = k + (long)bz * (C8 * NN);
#pragma unroll
    for (int i = 0; i < 4; i++) {
        int m = ty + 16 * i;
        float bias = (m < 32) ? bq[m] : bk[m - 32];
        float* dst = (m < 32) ? (qb + (long)m * NN) : (kb + (long)(m - 32) * NN);
#pragma unroll
        for (int j = 0; j < 4; j++) {
            int n = n0 + tx + 16 * j;
            dst[n] = rnatf(acc[i][j] + bias);
        }
    }
}

// ---------------- cp.async helpers ----------------------------------------------
__device__ __forceinline__ void cp16(uint32_t dst, const float* src) {
    asm volatile("cp.async.ca.shared.global [%0], [%1], 16;" :: "r"(dst), "l"(src));
}
__device__ __forceinline__ void cp_commit() {
    asm volatile("cp.async.commit_group;" ::: "memory");
}
template <int N>
__device__ __forceinline__ void cp_wait() {
    asm volatile("cp.async.wait_group %0;" :: "n"(N) : "memory");
}

// ---------------- TF32 tensor-core GEMM, cp.async 2-stage pipeline --------------
// C[b][m][n] = sum_k A[b][m][k]*B[k][n]  (A [M,K] k-contiguous, B [K,N] n-contig)
// EPI: 0 relu(acc*scale[m]+shift[m]); 1 acc*scale[m]+shift[m]+res;
//      2 rnatf(acc+scale[m])   (v production — consumed only by PV tf32)
template <int EPI>
__global__ __launch_bounds__(256) void gemm_tf32(
    const float* __restrict__ A, const float* __restrict__ B, float* __restrict__ Cm,
    int K, int lda, int ldb, int ldc,
    long sA, long sB, long sC,
    const float* __restrict__ scale, const float* __restrict__ shift,
    const float* __restrict__ res, long sRes) {
    constexpr int BM = 128, BN = 128, BK = 16;
    constexpr int APAD = 20;
    __shared__ __align__(16) float As[2][BM][APAD];
    __shared__ __align__(16) float Bs[2][BK][BN + 8];

    int tid = threadIdx.x;
    int bz = blockIdx.z;
    const float* Ab = A + (long)bz * sA;
    const float* Bb = B + (long)bz * sB;
    int m0 = blockIdx.y * BM, n0 = blockIdx.x * BN;

    int a_row = tid >> 1, a_q = (tid & 1) * 2;
    int b_row = tid >> 4, b_q = (tid & 15) * 2;

    uint32_t asBase = (uint32_t)__cvta_generic_to_shared(&As[0][0][0]);
    uint32_t bsBase = (uint32_t)__cvta_generic_to_shared(&Bs[0][0][0]);

    auto prefetch = [&](int buf, int k0) {
#pragma unroll
        for (int j = 0; j < 2; j++) {
            int q = a_q + j;
            cp16(asBase + (((buf * BM + a_row) * APAD) + q * 4) * 4,
                 Ab + (long)(m0 + a_row) * lda + k0 + q * 4);
        }
#pragma unroll
        for (int j = 0; j < 2; j++) {
            int q = b_q + j;
            cp16(bsBase + (((buf * BK + b_row) * (BN + 8)) + q * 4) * 4,
                 Bb + (long)(k0 + b_row) * ldb + n0 + q * 4);
        }
        cp_commit();
    };

    int lane = tid & 31, warp = tid >> 5;
    int wm = (warp >> 2) * 64;
    int wn = (warp & 3) * 32;
    int gid = lane >> 2, tig = lane & 3;

    float acc[4][4][4];
#pragma unroll
    for (int i = 0; i < 4; i++)
#pragma unroll
        for (int j = 0; j < 4; j++)
#pragma unroll
            for (int e = 0; e < 4; e++) acc[i][j][e] = 0.0f;

    prefetch(0, 0);

    int nk = K / BK;
    for (int t = 0; t < nk; t++) {
        int cur = t & 1;
        if (t + 1 < nk) {
            prefetch(cur ^ 1, (t + 1) * BK);
            cp_wait<1>();     // guarantees group for tile t complete
        } else {
            cp_wait<0>();
        }
        __syncthreads();

#pragma unroll
        for (int ks = 0; ks < 2; ks++) {
            int kb = ks * 8;
            unsigned af[4][4], bf[4][2];
#pragma unroll
            for (int mi = 0; mi < 4; mi++) {
                const float* ap = &As[cur][wm + 16 * mi + gid][kb + tig];
                af[mi][0] = __float_as_uint(ap[0]);
                af[mi][1] = __float_as_uint(ap[8 * APAD]);
                af[mi][2] = __float_as_uint(ap[4]);
                af[mi][3] = __float_as_uint(ap[8 * APAD + 4]);
            }
#pragma unroll
            for (int nj = 0; nj < 4; nj++) {
                int n = wn + 8 * nj + gid;
                bf[nj][0] = __float_as_uint(Bs[cur][kb + tig][n]);
                bf[nj][1] = __float_as_uint(Bs[cur][kb + 4 + tig][n]);
            }
#pragma unroll
            for (int mi = 0; mi < 4; mi++)
#pragma unroll
                for (int nj = 0; nj < 4; nj++) {
                    asm volatile(
                        "mma.sync.aligned.m16n8k8.row.col.f32.tf32.tf32.f32 "
                        "{%0,%1,%2,%3},{%4,%5,%6,%7},{%8,%9},{%0,%1,%2,%3};\n"
                        : "+f"(acc[mi][nj][0]), "+f"(acc[mi][nj][1]),
                          "+f"(acc[mi][nj][2]), "+f"(acc[mi][nj][3])
                        : "r"(af[mi][0]), "r"(af[mi][1]), "r"(af[mi][2]), "r"(af[mi][3]),
                          "r"(bf[nj][0]), "r"(bf[nj][1]));
                }
        }
        __syncthreads();
    }

    const float* resb = res ? res + (long)bz * sRes : nullptr;
    float* Cb = Cm + (long)bz * sC;

#pragma unroll
    for (int mi = 0; mi < 4; mi++) {
#pragma unroll
        for (int e2 = 0; e2 < 2; e2++) {
            int m = m0 + wm + 16 * mi + gid + 8 * e2;
            float sc = 0.0f, sh = 0.0f;
            if (EPI == 0 || EPI == 1) { sc = scale[m]; sh = shift[m]; }
            else if (EPI == 2) { sc = scale[m]; }
#pragma unroll
            for (int nj = 0; nj < 4; nj++) {
                int n = n0 + wn + 8 * nj + 2 * tig;
                float v0 = acc[mi][nj][2 * e2 + 0];
                float v1 = acc[mi][nj][2 * e2 + 1];
                if (EPI == 0) {
                    v0 = fmaxf(fmaf(v0, sc, sh), 0.0f);
                    v1 = fmaxf(fmaf(v1, sc, sh), 0.0f);
                } else if (EPI == 1) {
                    float2 r2 = *(const float2*)(resb + (long)m * ldc + n);
                    v0 = fmaf(v0, sc, sh) + r2.x;
                    v1 = fmaf(v1, sc, sh) + r2.y;
                } else if (EPI == 2) {
                    v0 = rnatf(v0 + sc);
                    v1 = rnatf(v1 + sc);
                }
                *(float2*)(Cb + (long)m * ldc + n) = make_float2(v0, v1);
            }
        }
    }
}

// ---------------- TF32 QK: P = bf16(exp(q^T k - SHIFT)) + rowsum into L ---------
// Stores P as bf16 (halves traffic). L sums the SAME bf16-rounded values, so the
// softmax weights PV computes are exactly normalized w.r.t. the stored P.
__global__ __launch_bounds__(256) void qk_tf32_kernel(
    const float* __restrict__ q, const float* __restrict__ k,
    __nv_bfloat16* __restrict__ P, float* __restrict__ L) {
    __shared__ __align__(16) float Qs[128][33];   // [m][d]
    __shared__ __align__(16) float Ks[128][33];   // [n][d]
    int tid = threadIdx.x;
    int bz = blockIdx.z;
    const float* qb = q + (long)bz * (C8 * NN);
    const float* kb = k + (long)bz * (C8 * NN);
    int m0 = blockIdx.y * 128, n0 = blockIdx.x * 128;

#pragma unroll
    for (int r = 0; r < 16; r++) {
        int idx = tid + r * 256;      // 0..4095
        int d = idx >> 7, mm = idx & 127;
        Qs[mm][d] = qb[(long)d * NN + m0 + mm];
        Ks[mm][d] = kb[(long)d * NN + n0 + mm];
    }
    __syncthreads();

    int lane = tid & 31, warp = tid >> 5;
    int wm = (warp >> 2) * 64;
    int wn = (warp & 3) * 32;
    int gid = lane >> 2, tig = lane & 3;

    float acc[4][4][4];
#pragma unroll
    for (int i = 0; i < 4; i++)
#pragma unroll
        for (int j = 0; j < 4; j++)
#pragma unroll
            for (int e = 0; e < 4; e++) acc[i][j][e] = 0.0f;

#pragma unroll
    for (int ks = 0; ks < 4; ks++) {
        int kb2 = ks * 8;
        unsigned af[4][4], bf[4][2];
#pragma unroll
        for (int mi = 0; mi < 4; mi++) {
            const float* ap = &Qs[wm + 16 * mi + gid][kb2 + tig];
            af[mi][0] = __float_as_uint(ap[0]);
            af[mi][1] = __float_as_uint(ap[8 * 33]);
            af[mi][2] = __float_as_uint(ap[4]);
            af[mi][3] = __float_as_uint(ap[8 * 33 + 4]);
        }
#pragma unroll
        for (int nj = 0; nj < 4; nj++) {
            const float* bp = &Ks[wn + 8 * nj + gid][kb2 + tig];
            bf[nj][0] = __float_as_uint(bp[0]);
            bf[nj][1] = __float_as_uint(bp[4]);
        }
#pragma unroll
        for (int mi = 0; mi < 4; mi++)
#pragma unroll
            for (int nj = 0; nj < 4; nj++) {
                asm volatile(
                    "mma.sync.aligned.m16n8k8.row.col.f32.tf32.tf32.f32 "
                    "{%0,%1,%2,%3},{%4,%5,%6,%7},{%8,%9},{%0,%1,%2,%3};\n"
                    : "+f"(acc[mi][nj][0]), "+f"(acc[mi][nj][1]),
                      "+f"(acc[mi][nj][2]), "+f"(acc[mi][nj][3])
                    : "r"(af[mi][0]), "r"(af[mi][1]), "r"(af[mi][2]), "r"(af[mi][3]),
                      "r"(bf[nj][0]), "r"(bf[nj][1]));
            }
    }

    __nv_bfloat16* Pb = P + (long)bz * ((long)NN * NN);
    float* Lb = L + bz * NN;
#pragma unroll
    for (int mi = 0; mi < 4; mi++) {
#pragma unroll
        for (int e2 = 0; e2 < 2; e2++) {
            int m = m0 + wm + 16 * mi + gid + 8 * e2;
            float rp = 0.0f;
#pragma unroll
            for (int nj = 0; nj < 4; nj++) {
                int n = n0 + wn + 8 * nj + 2 * tig;
                __nv_bfloat16 b0 = __float2bfloat16(__expf(acc[mi][nj][2 * e2 + 0] - SM_SHIFT));
                __nv_bfloat16 b1 = __float2bfloat16(__expf(acc[mi][nj][2 * e2 + 1] - SM_SHIFT));
                __nv_bfloat162 pr;
                pr.x = b0; pr.y = b1;
                *(__nv_bfloat162*)(Pb + (long)m * NN + n) = pr;
                rp += __bfloat162float(b0) + __bfloat162float(b1);
            }
            rp += __shfl_xor_sync(0xffffffffu, rp, 1);
            rp += __shfl_xor_sync(0xffffffffu, rp, 2);
            if (tig == 0) atomicAdd(&Lb[m], rp);
        }
    }
}

// ---------------- PV: A via cp.async, B = bf16 P via LDG+expand -----------------
// out[c,m] = relu( gamma * (sum_n v[c,n] * P[m,n]) / L[m] + xa[c,m] )
// bf16 -> fp32 expansion is exact (bf16 subset of tf32), so mma stays tf32.
__global__ __launch_bounds__(256) void gemm_pv(
    const float* __restrict__ V, const __nv_bfloat16* __restrict__ P,
    float* __restrict__ Cm,
    const float* __restrict__ Lrow,
    const float* __restrict__ res, const float* __restrict__ gammaPtr) {
    constexpr int BM = 128, BN = 128, BK = 16;
    constexpr int PAD = 20;
    __shared__ __align__(16) float As[2][BM][PAD];
    __shared__ __align__(16) float Bs[2][BN][PAD];

    int tid = threadIdx.x;
    int bz = blockIdx.z;
    const float* Ab = V + (long)bz * ((long)CC * NN);
    const __nv_bfloat16* Pb = P + (long)bz * ((long)NN * NN);
    int m0 = blockIdx.y * BM, n0 = blockIdx.x * BN;

    int a_row = tid >> 1, a_q = (tid & 1) * 2;   // A: two 16B cp.async chunks
    int b_row = tid >> 1, b_q8 = (tid & 1) * 8;  // B: one 16B LDG = 8 bf16

    uint32_t asBase = (uint32_t)__cvta_generic_to_shared(&As[0][0][0]);

    auto prefetchA = [&](int buf, int k0) {
#pragma unroll
        for (int j = 0; j < 2; j++) {
            int q = a_q + j;
            cp16(asBase + (((buf * BM + a_row) * PAD) + q * 4) * 4,
                 Ab + (long)(m0 + a_row) * NN + k0 + q * 4);
        }
        cp_commit();
    };
    uint4 braw;
    auto ldgB = [&](int k0) {
        braw = *(const uint4*)(Pb + (long)(n0 + b_row) * NN + k0 + b_q8);
    };
    auto stsB = [&](int buf) {
        uint32_t u[4] = {braw.x, braw.y, braw.z, braw.w};
        float4 lo = make_float4(__uint_as_float(u[0] << 16),
                                __uint_as_float(u[0] & 0xffff0000u),
                                __uint_as_float(u[1] << 16),
                                __uint_as_float(u[1] & 0xffff0000u));
        float4 hi = make_float4(__uint_as_float(u[2] << 16),
                                __uint_as_float(u[2] & 0xffff0000u),
                                __uint_as_float(u[3] << 16),
                                __uint_as_float(u[3] & 0xffff0000u));
        *(float4*)&Bs[buf][b_row][b_q8]     = lo;
        *(float4*)&Bs[buf][b_row][b_q8 + 4] = hi;
    };

    int lane = tid & 31, warp = tid >> 5;
    int wm = (warp >> 2) * 64;
    int wn = (warp & 3) * 32;
    int gid = lane >> 2, tig = lane & 3;

    float acc[4][4][4];
#pragma unroll
    for (int i = 0; i < 4; i++)
#pragma unroll
        for (int j = 0; j < 4; j++)
#pragma unroll
            for (int e = 0; e < 4; e++) acc[i][j][e] = 0.0f;

    prefetchA(0, 0);
    ldgB(0);
    stsB(0);
    cp_wait<0>();
    __syncthreads();

    const int nk = NN / BK;   // 64
    for (int t = 0; t < nk; t++) {
        int cur = t & 1;
        bool more = (t + 1 < nk);
        if (more) {
            prefetchA(cur ^ 1, (t + 1) * BK);   // buf^1 readers finished at t-1 barrier
            ldgB((t + 1) * BK);
            cp_wait<1>();    // tile t's A group complete before mma reads it
        } else {
            cp_wait<0>();
        }

#pragma unroll
        for (int ks = 0; ks < 2; ks++) {
            int kb = ks * 8;
            unsigned af[4][4], bf[4][2];
#pragma unroll
            for (int mi = 0; mi < 4; mi++) {
                const float* ap = &As[cur][wm + 16 * mi + gid][kb + tig];
                af[mi][0] = __float_as_uint(ap[0]);
                af[mi][1] = __float_as_uint(ap[8 * PAD]);
                af[mi][2] = __float_as_uint(ap[4]);
                af[mi][3] = __float_as_uint(ap[8 * PAD + 4]);
            }
#pragma unroll
            for (int nj = 0; nj < 4; nj++) {
                const float* bp = &Bs[cur][wn + 8 * nj + gid][kb + tig];
                bf[nj][0] = __float_as_uint(bp[0]);
                bf[nj][1] = __float_as_uint(bp[4]);
            }
#pragma unroll
            for (int mi = 0; mi < 4; mi++)
#pragma unroll
                for (int nj = 0; nj < 4; nj++) {
                    asm volatile(
                        "mma.sync.aligned.m16n8k8.row.col.f32.tf32.tf32.f32 "
                        "{%0,%1,%2,%3},{%4,%5,%6,%7},{%8,%9},{%0,%1,%2,%3};\n"
                        : "+f"(acc[mi][nj][0]), "+f"(acc[mi][nj][1]),
                          "+f"(acc[mi][nj][2]), "+f"(acc[mi][nj][3])
                        : "r"(af[mi][0]), "r"(af[mi][1]), "r"(af[mi][2]), "r"(af[mi][3]),
                          "r"(bf[nj][0]), "r"(bf[nj][1]));
                }
        }
        if (more) stsB(cur ^ 1);   // buf^1 last read at iter t-1, fenced by t-1's barrier
        __syncthreads();           // stsB visible; readers of cur done before reuse
    }

    float gm = gammaPtr[0];
    const float* resb = res + (long)bz * ((long)CC * NN);
    const float* lb = Lrow + bz * NN;
    float* Cb = Cm + (long)bz * ((long)CC * NN);

#pragma unroll
    for (int mi = 0; mi < 4; mi++) {
#pragma unroll
        for (int e2 = 0; e2 < 2; e2++) {
            int m = m0 + wm + 16 * mi + gid + 8 * e2;
#pragma unroll
            for (int nj = 0; nj < 4; nj++) {
                int n = n0 + wn + 8 * nj + 2 * tig;
                float2 l2 = *(const float2*)(lb + n);
                float2 r2 = *(const float2*)(resb + (long)m * NN + n);
                float v0 = fmaxf(fmaf(gm / l2.x, acc[mi][nj][2 * e2 + 0], r2.x), 0.0f);
                float v1 = fmaxf(fmaf(gm / l2.y, acc[mi][nj][2 * e2 + 1], r2.y), 0.0f);
                *(float2*)(Cb + (long)m * NN + n) = make_float2(v0, v1);
            }
        }
    }
}

// ---------------- launch ---------------------------------------------------------
extern "C" void kernel_launch(void* const* d_in, const int* in_sizes, int n_in,
                              void* d_out, int out_size) {
    const float* x     = (const float*)d_in[0];
    const float* dw1   = (const float*)d_in[1];
    const float* pw1   = (const float*)d_in[2];
    const float* bn1_g = (const float*)d_in[3];
    const float* bn1_b = (const float*)d_in[4];
    const float* bn1_m = (const float*)d_in[5];
    const float* bn1_v = (const float*)d_in[6];
    const float* dw2   = (const float*)d_in[7];
    const float* pw2   = (const float*)d_in[8];
    const float* bn2_g = (const float*)d_in[9];
    const float* bn2_b = (const float*)d_in[10];
    const float* bn2_m = (const float*)d_in[11];
    const float* bn2_v = (const float*)d_in[12];
    const float* wq    = (const float*)d_in[13];
    const float* bq    = (const float*)d_in[14];
    const float* wk    = (const float*)d_in[15];
    const float* bk    = (const float*)d_in[16];
    const float* wv    = (const float*)d_in[17];
    const float* bv    = (const float*)d_in[18];
    const float* gamma = (const float*)d_in[19];
    float* out = (float*)d_out;

    float *t1, *t2, *t3, *xa, *q, *k, *v, *L, *wr, *bn;
    __nv_bfloat16* P;
    cudaGetSymbolAddress((void**)&t1, g_t1);
    cudaGetSymbolAddress((void**)&t2, g_t2);
    cudaGetSymbolAddress((void**)&t3, g_t3);
    cudaGetSymbolAddress((void**)&xa, g_xa);
    cudaGetSymbolAddress((void**)&q,  g_q);
    cudaGetSymbolAddress((void**)&k,  g_k);
    cudaGetSymbolAddress((void**)&v,  g_v);
    cudaGetSymbolAddress((void**)&P,  g_P);
    cudaGetSymbolAddress((void**)&L,  g_L);
    cudaGetSymbolAddress((void**)&wr, g_wr);
    cudaGetSymbolAddress((void**)&bn, g_bn);
    const float* scale1 = bn;
    const float* shift1 = bn + CC;
    const float* scale2 = bn + 2 * CC;
    const float* shift2 = bn + 3 * CC;
    const float* pw1r = wr;
    const float* pw2r = wr + CC * CC;
    const float* wvr  = wr + 2 * CC * CC;

    const long sBCN = (long)CC * NN;   // 262144

    // 0) BN affine precompute + weight rounding + L zeroing
    bnprep_kernel<<<1, CC>>>(bn1_g, bn1_b, bn1_m, bn1_v, bn2_g, bn2_b, bn2_m, bn2_v, bn);
    roundw_kernel<<<3 * CC * CC / 256, 256>>>(pw1, pw2, wv, wr);
    zerol_kernel<<<BB * NN / 256, 256>>>(L);

    // 1) depthwise 1 (output tf32-rna rounded)
    dwconv_kernel<<<BB * CC, 256>>>(x, dw1, t1);

    // 2) pointwise 1 + BN + ReLU (TF32 TC)
    gemm_tf32<0><<<dim3(NN / 128, CC / 128, BB), 256>>>(
        pw1r, t1, t2, CC, CC, NN, NN, 0, sBCN, sBCN, scale1, shift1, nullptr, 0);

    // 3) depthwise 2 (output tf32-rna rounded)
    dwconv_kernel<<<BB * CC, 256>>>(t2, dw2, t3);

    // 4) pointwise 2 + BN + residual x (TF32 TC)
    gemm_tf32<1><<<dim3(NN / 128, CC / 128, BB), 256>>>(
        pw2r, t3, xa, CC, CC, NN, NN, 0, sBCN, sBCN, scale2, shift2, x, sBCN);

    // 5) fused q & k projections (fp32 math, rna-rounded outputs; reads xa once)
    qkproj_kernel<<<dim3(NN / 64, 1, BB), 256>>>(wq, bq, wk, bk, xa, q, k);

    // 6) v = wv @ xa + bv (TF32 TC, output rna-rounded for PV)
    gemm_tf32<2><<<dim3(NN / 128, CC / 128, BB), 256>>>(
        wvr, xa, v, CC, CC, NN, NN, 0, sBCN, sBCN, bv, nullptr, nullptr, 0);

    // 7) P = bf16(exp(q^T k - SHIFT)) (TF32 TC) + rowsum -> L (consistent)
    qk_tf32_kernel<<<dim3(NN / 128, NN / 128, BB), 256>>>(q, k, P, L);

    // 8) PV: out = relu(gamma * (v @ P) / L + xa)
    gemm_pv<<<dim3(NN / 128, CC / 128, BB), 256>>>(v, P, out, L, xa, gamma);

    (void)in_sizes; (void)n_in; (void)out_size;
}